// round 3
// baseline (speedup 1.0000x reference)
#include <cuda_runtime.h>
#include <math.h>

#define S_LEN 4096
#define EMB   512
#define NH    8
#define DH    64
#define BATCH 4
#define M_ROWS (BATCH * S_LEN)          // 16384
#define N_QKV  (3 * EMB)                // 1536

// Scratch (allocation-free: __device__ globals)
__device__ __align__(16) float g_qkv[(size_t)M_ROWS * N_QKV];       // [B*S, 3E]
__device__ __align__(16) float g_Q[(size_t)BATCH * NH * S_LEN * DH]; // [B,H,S,Dh]
__device__ __align__(16) float g_K[(size_t)BATCH * NH * S_LEN * DH];
__device__ __align__(16) float g_V[(size_t)BATCH * NH * S_LEN * DH];
__device__ __align__(16) float g_att[(size_t)M_ROWS * EMB];          // [B,S,E]

// ---------------------------------------------------------------------------
// Textbook 32x32 tiled SGEMM: C[M,N] = A[M,K] @ B[K,N] + bias[N]
// blockDim (32,32), grid (N/32, M/32). M,N,K all multiples of 32 here.
// ---------------------------------------------------------------------------
__global__ __launch_bounds__(1024) void gemm32_kernel(
    const float* __restrict__ A, const float* __restrict__ B,
    const float* __restrict__ bias, float* __restrict__ C,
    int M, int N, int K)
{
    __shared__ float As[32][33];
    __shared__ float Bs[32][33];
    const int tx = threadIdx.x;
    const int ty = threadIdx.y;
    const int row = blockIdx.y * 32 + ty;
    const int col = blockIdx.x * 32 + tx;

    float acc = 0.f;
    for (int k0 = 0; k0 < K; k0 += 32) {
        As[ty][tx] = A[(size_t)row * K + (k0 + tx)];
        Bs[ty][tx] = B[(size_t)(k0 + ty) * N + col];
        __syncthreads();
#pragma unroll
        for (int kk = 0; kk < 32; kk++)
            acc += As[ty][kk] * Bs[kk][tx];
        __syncthreads();
    }
    C[(size_t)row * N + col] = acc + bias[col];
}

// ---------------------------------------------------------------------------
// Scatter: g_qkv [B*S, 3E] -> g_Q/g_K/g_V each [B,H,S,Dh]
// ---------------------------------------------------------------------------
__global__ __launch_bounds__(256) void scatter_qkv_kernel()
{
    const size_t total = (size_t)M_ROWS * N_QKV;
    size_t idx = (size_t)blockIdx.x * 256 + threadIdx.x;
    if (idx >= total) return;

    const int row = (int)(idx / N_QKV);          // 0..16383  (b*4096+s)
    const int col = (int)(idx - (size_t)row * N_QKV);  // 0..1535
    const int b = row >> 12;
    const int s = row & 4095;
    const int which = col / EMB;                 // 0=Q 1=K 2=V
    const int e = col - which * EMB;             // 0..511
    const int h = e >> 6;
    const int d = e & 63;

    const float v = g_qkv[idx];
    const size_t dst = (((size_t)(b * NH + h) * S_LEN) + s) * DH + d;
    if (which == 0)      g_Q[dst] = v;
    else if (which == 1) g_K[dst] = v;
    else                 g_V[dst] = v;
}

// ---------------------------------------------------------------------------
// Flash attention (fp32, causal). 1 thread = 1 query row, 128 rows/block.
// K/V tiles (64 rows) staged into smem with plain scalar copies.
// ---------------------------------------------------------------------------
__global__ __launch_bounds__(128) void attn_kernel(float* __restrict__ Out)
{
    __shared__ float Ks[64 * DH];
    __shared__ float Vs[64 * DH];

    const int tid = threadIdx.x;
    const int qt  = blockIdx.x;              // 0..31
    const int bh  = blockIdx.y;              // 0..31  (= b*NH + h)
    const int row = qt * 128 + tid;          // query index within (b,h)

    const float* qp = g_Q + ((size_t)bh * S_LEN + row) * DH;
    float q[DH], o[DH];
#pragma unroll
    for (int d = 0; d < DH; d++) { q[d] = qp[d]; o[d] = 0.f; }
    float m = -1e30f;
    float l = 0.f;

    const float* Kb = g_K + (size_t)bh * S_LEN * DH;
    const float* Vb = g_V + (size_t)bh * S_LEN * DH;
    const int nT = qt * 2 + 2;               // 64-key tiles needed causally

    for (int jt = 0; jt < nT; jt++) {
        const float* Kg = Kb + (size_t)jt * 64 * DH;
        const float* Vg = Vb + (size_t)jt * 64 * DH;
        for (int i = tid; i < 64 * DH; i += 128) {
            Ks[i] = Kg[i];
            Vs[i] = Vg[i];
        }
        __syncthreads();

        int kmax = row - jt * 64 + 1;        // causal: key <= row
        if (kmax > 64) kmax = 64;
        for (int t = 0; t < kmax; t++) {
            float s = 0.f;
#pragma unroll
            for (int d = 0; d < DH; d++) s += q[d] * Ks[t * DH + d];
            s *= 0.125f;                     // 1/sqrt(64)
            float p;
            if (s > m) {
                const float corr = __expf(m - s);
                m = s;
                l *= corr;
#pragma unroll
                for (int d = 0; d < DH; d++) o[d] *= corr;
                p = 1.f;
            } else {
                p = __expf(s - m);
            }
            l += p;
#pragma unroll
            for (int d = 0; d < DH; d++) o[d] += p * Vs[t * DH + d];
        }
        __syncthreads();
    }

    const float inv = 1.f / l;
    const int b = bh >> 3;
    const int h = bh & 7;
    float* op = Out + ((size_t)b * S_LEN + row) * EMB + h * DH;
#pragma unroll
    for (int d = 0; d < DH; d++) op[d] = o[d] * inv;
}

// ---------------------------------------------------------------------------
extern "C" void kernel_launch(void* const* d_in, const int* in_sizes, int n_in,
                              void* d_out, int out_size)
{
    // Resolve inputs by element count (all five pairwise distinct):
    //   x: 8388608, Wqkv: 786432, bqkv: 1536, Wo: 262144, bo: 512
    const float* x    = (const float*)d_in[0];
    const float* Wqkv = (const float*)d_in[1];
    const float* bqkv = (const float*)d_in[2];
    const float* Wo   = (const float*)d_in[3];
    const float* bo   = (const float*)d_in[4];
    for (int i = 0; i < n_in; i++) {
        switch (in_sizes[i]) {
            case 8388608: x    = (const float*)d_in[i]; break;
            case 786432:  Wqkv = (const float*)d_in[i]; break;
            case 1536:    bqkv = (const float*)d_in[i]; break;
            case 262144:  Wo   = (const float*)d_in[i]; break;
            case 512:     bo   = (const float*)d_in[i]; break;
        }
    }
    float* out = (float*)d_out;

    // Resolve device-global scratch addresses (host-side symbols are not
    // device pointers; kernels reference the globals directly, so only the
    // gemm32 A/C arguments need real device addresses).
    // We get them via cudaGetSymbolAddress-free route: pass through kernels
    // that reference the globals directly. gemm32 needs pointers, so use
    // cudaGetSymbolAddress (allowed: not an allocation).
    static float* p_qkv = nullptr;
    static float* p_att = nullptr;
    if (!p_qkv) {
        void* tmp;
        cudaGetSymbolAddress(&tmp, g_qkv); p_qkv = (float*)tmp;
        cudaGetSymbolAddress(&tmp, g_att); p_att = (float*)tmp;
    }

    dim3 blk(32, 32);

    // 1) QKV projection: g_qkv = x @ Wqkv + bqkv
    gemm32_kernel<<<dim3(N_QKV / 32, M_ROWS / 32), blk>>>(
        x, Wqkv, bqkv, p_qkv, M_ROWS, N_QKV, EMB);

    // 2) Scatter into [B,H,S,Dh]
    {
        const size_t total = (size_t)M_ROWS * N_QKV;
        const int nblk = (int)((total + 255) / 256);
        scatter_qkv_kernel<<<nblk, 256>>>();
    }

    // 3) Causal flash attention -> g_att [B,S,E]
    attn_kernel<<<dim3(S_LEN / 128, BATCH * NH), 128>>>(p_att);

    // 4) Output projection: out = g_att @ Wo + bo
    gemm32_kernel<<<dim3(EMB / 32, M_ROWS / 32), blk>>>(
        p_att, Wo, bo, out, M_ROWS, EMB, EMB);
}

// round 4
// speedup vs baseline: 1.7577x; 1.7577x over previous
#include <cuda_runtime.h>
#include <math.h>

#define S_LEN 4096
#define EMB   512
#define NH    8
#define DH    64
#define BATCH 4
#define M_ROWS (BATCH * S_LEN)          // 16384
#define N_QKV  (3 * EMB)                // 1536

// Scratch (allocation-free: __device__ globals)
__device__ __align__(16) float g_qkv[(size_t)M_ROWS * N_QKV];        // [B*S, 3E]
__device__ __align__(16) float g_Q[(size_t)BATCH * NH * S_LEN * DH]; // [B,H,S,Dh]
__device__ __align__(16) float g_K[(size_t)BATCH * NH * S_LEN * DH];
__device__ __align__(16) float g_V[(size_t)BATCH * NH * S_LEN * DH];
__device__ __align__(16) float g_att[(size_t)M_ROWS * EMB];          // [B,S,E]

// ---------------------------------------------------------------------------
// Register-blocked SGEMM: C[M,N] = A[M,K] @ B[K,N] + bias[N]
// 128x128 tile, BK=8, 256 threads, 8x8 outputs per thread.
// Requires: M%128==0, N%128==0, K%8==0 (true for all uses here).
// ---------------------------------------------------------------------------
__global__ __launch_bounds__(256) void gemm128_kernel(
    const float* __restrict__ A, const float* __restrict__ B,
    const float* __restrict__ bias, float* __restrict__ C,
    int M, int N, int K)
{
    __shared__ float As[8][128];
    __shared__ float Bs[8][128];

    const int tid = threadIdx.x;
    const int bx = blockIdx.x;          // N tile
    const int by = blockIdx.y;          // M tile
    const int tx = tid & 15;            // 0..15
    const int ty = tid >> 4;            // 0..15

    const int aRow = tid >> 1;          // 0..127
    const int aCol = (tid & 1) * 4;     // 0 or 4
    const int bRow = tid >> 5;          // 0..7
    const int bCol = (tid & 31) * 4;    // 0..124

    const float* Ag = A + ((size_t)by * 128 + aRow) * K + aCol;
    const float* Bg = B + (size_t)bRow * N + bx * 128 + bCol;

    float acc[8][8];
#pragma unroll
    for (int i = 0; i < 8; i++)
#pragma unroll
        for (int j = 0; j < 8; j++) acc[i][j] = 0.f;

    for (int k0 = 0; k0 < K; k0 += 8) {
        const float4 a = *(const float4*)(Ag + k0);
        As[aCol + 0][aRow] = a.x;
        As[aCol + 1][aRow] = a.y;
        As[aCol + 2][aRow] = a.z;
        As[aCol + 3][aRow] = a.w;
        *(float4*)&Bs[bRow][bCol] = *(const float4*)(Bg + (size_t)k0 * N);
        __syncthreads();
#pragma unroll
        for (int k = 0; k < 8; k++) {
            float ra[8], rb[8];
#pragma unroll
            for (int i = 0; i < 8; i++) ra[i] = As[k][ty * 8 + i];
#pragma unroll
            for (int j = 0; j < 8; j++) rb[j] = Bs[k][tx * 8 + j];
#pragma unroll
            for (int i = 0; i < 8; i++)
#pragma unroll
                for (int j = 0; j < 8; j++) acc[i][j] += ra[i] * rb[j];
        }
        __syncthreads();
    }

#pragma unroll
    for (int i = 0; i < 8; i++) {
        const int row = by * 128 + ty * 8 + i;
#pragma unroll
        for (int j = 0; j < 8; j += 4) {
            const int col = bx * 128 + tx * 8 + j;
            float4 v;
            v.x = acc[i][j + 0] + bias[col + 0];
            v.y = acc[i][j + 1] + bias[col + 1];
            v.z = acc[i][j + 2] + bias[col + 2];
            v.w = acc[i][j + 3] + bias[col + 3];
            *(float4*)(C + (size_t)row * N + col) = v;
        }
    }
}

// ---------------------------------------------------------------------------
// Scatter: g_qkv [B*S, 3E] -> g_Q/g_K/g_V each [B,H,S,Dh]   (unchanged, proven)
// ---------------------------------------------------------------------------
__global__ __launch_bounds__(256) void scatter_qkv_kernel()
{
    const size_t total = (size_t)M_ROWS * N_QKV;
    size_t idx = (size_t)blockIdx.x * 256 + threadIdx.x;
    if (idx >= total) return;

    const int row = (int)(idx / N_QKV);
    const int col = (int)(idx - (size_t)row * N_QKV);
    const int b = row >> 12;
    const int s = row & 4095;
    const int which = col / EMB;
    const int e = col - which * EMB;
    const int h = e >> 6;
    const int d = e & 63;

    const float v = g_qkv[idx];
    const size_t dst = (((size_t)(b * NH + h) * S_LEN) + s) * DH + d;
    if (which == 0)      g_Q[dst] = v;
    else if (which == 1) g_K[dst] = v;
    else                 g_V[dst] = v;
}

// ---------------------------------------------------------------------------
// Flash attention (fp32, causal). 1 thread = 1 query row, 128 rows/block.
// Unchanged from the passing R3 version.
// ---------------------------------------------------------------------------
__global__ __launch_bounds__(128) void attn_kernel(float* __restrict__ Out)
{
    __shared__ float Ks[64 * DH];
    __shared__ float Vs[64 * DH];

    const int tid = threadIdx.x;
    const int qt  = blockIdx.x;              // 0..31
    const int bh  = blockIdx.y;              // 0..31  (= b*NH + h)
    const int row = qt * 128 + tid;

    const float* qp = g_Q + ((size_t)bh * S_LEN + row) * DH;
    float q[DH], o[DH];
#pragma unroll
    for (int d = 0; d < DH; d++) { q[d] = qp[d]; o[d] = 0.f; }
    float m = -1e30f;
    float l = 0.f;

    const float* Kb = g_K + (size_t)bh * S_LEN * DH;
    const float* Vb = g_V + (size_t)bh * S_LEN * DH;
    const int nT = qt * 2 + 2;

    for (int jt = 0; jt < nT; jt++) {
        const float* Kg = Kb + (size_t)jt * 64 * DH;
        const float* Vg = Vb + (size_t)jt * 64 * DH;
        for (int i = tid; i < 64 * DH; i += 128) {
            Ks[i] = Kg[i];
            Vs[i] = Vg[i];
        }
        __syncthreads();

        int kmax = row - jt * 64 + 1;
        if (kmax > 64) kmax = 64;
        for (int t = 0; t < kmax; t++) {
            float s = 0.f;
#pragma unroll
            for (int d = 0; d < DH; d++) s += q[d] * Ks[t * DH + d];
            s *= 0.125f;
            float p;
            if (s > m) {
                const float corr = __expf(m - s);
                m = s;
                l *= corr;
#pragma unroll
                for (int d = 0; d < DH; d++) o[d] *= corr;
                p = 1.f;
            } else {
                p = __expf(s - m);
            }
            l += p;
#pragma unroll
            for (int d = 0; d < DH; d++) o[d] += p * Vs[t * DH + d];
        }
        __syncthreads();
    }

    const float inv = 1.f / l;
    const int b = bh >> 3;
    const int h = bh & 7;
    float* op = Out + ((size_t)b * S_LEN + row) * EMB + h * DH;
#pragma unroll
    for (int d = 0; d < DH; d++) op[d] = o[d] * inv;
}

// ---------------------------------------------------------------------------
extern "C" void kernel_launch(void* const* d_in, const int* in_sizes, int n_in,
                              void* d_out, int out_size)
{
    // Resolve inputs by element count (all five pairwise distinct).
    const float* x    = (const float*)d_in[0];
    const float* Wqkv = (const float*)d_in[1];
    const float* bqkv = (const float*)d_in[2];
    const float* Wo   = (const float*)d_in[3];
    const float* bo   = (const float*)d_in[4];
    for (int i = 0; i < n_in; i++) {
        switch (in_sizes[i]) {
            case 8388608: x    = (const float*)d_in[i]; break;
            case 786432:  Wqkv = (const float*)d_in[i]; break;
            case 1536:    bqkv = (const float*)d_in[i]; break;
            case 262144:  Wo   = (const float*)d_in[i]; break;
            case 512:     bo   = (const float*)d_in[i]; break;
        }
    }
    float* out = (float*)d_out;

    static float* p_qkv = nullptr;
    static float* p_att = nullptr;
    if (!p_qkv) {
        void* tmp;
        cudaGetSymbolAddress(&tmp, g_qkv); p_qkv = (float*)tmp;
        cudaGetSymbolAddress(&tmp, g_att); p_att = (float*)tmp;
    }

    // 1) QKV projection: g_qkv = x @ Wqkv + bqkv
    gemm128_kernel<<<dim3(N_QKV / 128, M_ROWS / 128), 256>>>(
        x, Wqkv, bqkv, p_qkv, M_ROWS, N_QKV, EMB);

    // 2) Scatter into [B,H,S,Dh]
    {
        const size_t total = (size_t)M_ROWS * N_QKV;
        const int nblk = (int)((total + 255) / 256);
        scatter_qkv_kernel<<<nblk, 256>>>();
    }

    // 3) Causal flash attention -> g_att [B,S,E]
    attn_kernel<<<dim3(S_LEN / 128, BATCH * NH), 128>>>(p_att);

    // 4) Output projection: out = g_att @ Wo + bo
    gemm128_kernel<<<dim3(EMB / 128, M_ROWS / 128), 256>>>(
        p_att, Wo, bo, out, M_ROWS, EMB, EMB);
}

// round 5
// speedup vs baseline: 4.2176x; 2.3996x over previous
#include <cuda_runtime.h>
#include <cuda_bf16.h>
#include <math.h>
#include <stdint.h>

#define S_LEN 4096
#define EMB   512
#define NH    8
#define DH    64
#define BATCH 4
#define M_ROWS (BATCH * S_LEN)          // 16384
#define N_QKV  (3 * EMB)                // 1536
#define KSTR   72                        // smem half-stride (64 + 8 pad)

// Scratch (allocation-free: __device__ globals)
__device__ __align__(16) float g_qkv[(size_t)M_ROWS * N_QKV];        // [B*S, 3E]
__device__ __align__(16) float g_Q[(size_t)BATCH * NH * S_LEN * DH]; // [B,H,S,Dh]
__device__ __align__(16) float g_K[(size_t)BATCH * NH * S_LEN * DH];
__device__ __align__(16) float g_V[(size_t)BATCH * NH * S_LEN * DH];
__device__ __align__(16) float g_att[(size_t)M_ROWS * EMB];          // [B,S,E]

// ---------------------------------------------------------------------------
// Register-blocked SGEMM (unchanged from passing R4).
// ---------------------------------------------------------------------------
__global__ __launch_bounds__(256) void gemm128_kernel(
    const float* __restrict__ A, const float* __restrict__ B,
    const float* __restrict__ bias, float* __restrict__ C,
    int M, int N, int K)
{
    __shared__ float As[8][128];
    __shared__ float Bs[8][128];

    const int tid = threadIdx.x;
    const int bx = blockIdx.x;
    const int by = blockIdx.y;
    const int tx = tid & 15;
    const int ty = tid >> 4;

    const int aRow = tid >> 1;
    const int aCol = (tid & 1) * 4;
    const int bRow = tid >> 5;
    const int bCol = (tid & 31) * 4;

    const float* Ag = A + ((size_t)by * 128 + aRow) * K + aCol;
    const float* Bg = B + (size_t)bRow * N + bx * 128 + bCol;

    float acc[8][8];
#pragma unroll
    for (int i = 0; i < 8; i++)
#pragma unroll
        for (int j = 0; j < 8; j++) acc[i][j] = 0.f;

    for (int k0 = 0; k0 < K; k0 += 8) {
        const float4 a = *(const float4*)(Ag + k0);
        As[aCol + 0][aRow] = a.x;
        As[aCol + 1][aRow] = a.y;
        As[aCol + 2][aRow] = a.z;
        As[aCol + 3][aRow] = a.w;
        *(float4*)&Bs[bRow][bCol] = *(const float4*)(Bg + (size_t)k0 * N);
        __syncthreads();
#pragma unroll
        for (int k = 0; k < 8; k++) {
            float ra[8], rb[8];
#pragma unroll
            for (int i = 0; i < 8; i++) ra[i] = As[k][ty * 8 + i];
#pragma unroll
            for (int j = 0; j < 8; j++) rb[j] = Bs[k][tx * 8 + j];
#pragma unroll
            for (int i = 0; i < 8; i++)
#pragma unroll
                for (int j = 0; j < 8; j++) acc[i][j] += ra[i] * rb[j];
        }
        __syncthreads();
    }

#pragma unroll
    for (int i = 0; i < 8; i++) {
        const int row = by * 128 + ty * 8 + i;
#pragma unroll
        for (int j = 0; j < 8; j += 4) {
            const int col = bx * 128 + tx * 8 + j;
            float4 v;
            v.x = acc[i][j + 0] + bias[col + 0];
            v.y = acc[i][j + 1] + bias[col + 1];
            v.z = acc[i][j + 2] + bias[col + 2];
            v.w = acc[i][j + 3] + bias[col + 3];
            *(float4*)(C + (size_t)row * N + col) = v;
        }
    }
}

// ---------------------------------------------------------------------------
// Scatter (unchanged, proven)
// ---------------------------------------------------------------------------
__global__ __launch_bounds__(256) void scatter_qkv_kernel()
{
    const size_t total = (size_t)M_ROWS * N_QKV;
    size_t idx = (size_t)blockIdx.x * 256 + threadIdx.x;
    if (idx >= total) return;

    const int row = (int)(idx / N_QKV);
    const int col = (int)(idx - (size_t)row * N_QKV);
    const int b = row >> 12;
    const int s = row & 4095;
    const int which = col / EMB;
    const int e = col - which * EMB;
    const int h = e >> 6;
    const int d = e & 63;

    const float v = g_qkv[idx];
    const size_t dst = (((size_t)(b * NH + h) * S_LEN) + s) * DH + d;
    if (which == 0)      g_Q[dst] = v;
    else if (which == 1) g_K[dst] = v;
    else                 g_V[dst] = v;
}

// ---------------------------------------------------------------------------
// Tensor-core flash attention: bf16-split mma.sync, fp32 accumulate.
// ---------------------------------------------------------------------------
__device__ __forceinline__ void mma16816(float c[4], const uint32_t a[4],
                                         const uint32_t* b)
{
    asm volatile(
        "mma.sync.aligned.m16n8k16.row.col.f32.bf16.bf16.f32 "
        "{%0,%1,%2,%3}, {%4,%5,%6,%7}, {%8,%9}, {%0,%1,%2,%3};\n"
        : "+f"(c[0]), "+f"(c[1]), "+f"(c[2]), "+f"(c[3])
        : "r"(a[0]), "r"(a[1]), "r"(a[2]), "r"(a[3]), "r"(b[0]), "r"(b[1]));
}

__device__ __forceinline__ void ldsm4(uint32_t r[4], uint32_t addr)
{
    asm volatile("ldmatrix.sync.aligned.m8n8.x4.shared.b16 {%0,%1,%2,%3}, [%4];\n"
                 : "=r"(r[0]), "=r"(r[1]), "=r"(r[2]), "=r"(r[3]) : "r"(addr));
}

__device__ __forceinline__ void ldsm4t(uint32_t r[4], uint32_t addr)
{
    asm volatile("ldmatrix.sync.aligned.m8n8.x4.trans.shared.b16 {%0,%1,%2,%3}, [%4];\n"
                 : "=r"(r[0]), "=r"(r[1]), "=r"(r[2]), "=r"(r[3]) : "r"(addr));
}

__device__ __forceinline__ void split2(float x, float y, uint32_t& h, uint32_t& l)
{
    __nv_bfloat16 hx = __float2bfloat16(x);
    __nv_bfloat16 hy = __float2bfloat16(y);
    __nv_bfloat162 hh; hh.x = hx; hh.y = hy;
    __nv_bfloat162 ll;
    ll.x = __float2bfloat16(x - __bfloat162float(hx));
    ll.y = __float2bfloat16(y - __bfloat162float(hy));
    h = *(uint32_t*)&hh;
    l = *(uint32_t*)&ll;
}

__global__ __launch_bounds__(256) void attn_mma_kernel(float* __restrict__ Out)
{
    __shared__ __nv_bfloat16 Kh[64 * KSTR], Kl[64 * KSTR];
    __shared__ __nv_bfloat16 Vh[64 * KSTR], Vl[64 * KSTR];

    const int tid  = threadIdx.x;
    const int warp = tid >> 5;
    const int lane = tid & 31;
    const int qt = blockIdx.x;               // 0..31
    const int bh = blockIdx.y;               // 0..31 (= b*NH + h)
    const int rowbase = qt * 128;
    const int qr = lane >> 2;                // 0..7
    const int qc = lane & 3;                 // 0..3
    const int g  = lane >> 3;                // 0..3 (ldmatrix tile group)
    const int rr = lane & 7;                 // row within tile group

    // Load Q a-fragments (hi/lo) once: 4 k-steps x 4 regs each
    uint32_t Qah[4][4], Qal[4][4];
    {
        const float* Qbase = g_Q + ((size_t)bh * S_LEN + rowbase + warp * 16) * DH;
#pragma unroll
        for (int s = 0; s < 4; s++)
#pragma unroll
            for (int e = 0; e < 4; e++) {
                const int r = qr + 8 * (e & 1);
                const int c = 16 * s + 2 * qc + 8 * (e >> 1);
                const float2 v = *(const float2*)(Qbase + (size_t)r * DH + c);
                split2(v.x, v.y, Qah[s][e], Qal[s][e]);
            }
    }

    float O[8][4];
#pragma unroll
    for (int j = 0; j < 8; j++)
#pragma unroll
        for (int e = 0; e < 4; e++) O[j][e] = 0.f;
    float m0 = -1e30f, m1 = -1e30f, l0 = 0.f, l1 = 0.f;

    const float* Kb = g_K + (size_t)bh * S_LEN * DH;
    const float* Vb = g_V + (size_t)bh * S_LEN * DH;
    const int nT = qt * 2 + 2;

    for (int kt = 0; kt < nT; kt++) {
        __syncthreads();   // protect previous iteration's smem reads
        // Fill smem with bf16 hi/lo of K,V tiles (64 keys x 64 dh)
        {
            const float4* Kg = (const float4*)(Kb + (size_t)kt * 64 * DH);
            const float4* Vg = (const float4*)(Vb + (size_t)kt * 64 * DH);
#pragma unroll
            for (int i = 0; i < 4; i++) {
                const int idx4 = i * 256 + tid;          // 0..1023
                const int key = idx4 >> 4;
                const int d4  = (idx4 & 15) * 4;
                const float4 kv = Kg[idx4];
                const float4 vv = Vg[idx4];
                const int base = key * KSTR + d4;
                uint32_t h0, l0r, h1, l1r;
                split2(kv.x, kv.y, h0, l0r);
                split2(kv.z, kv.w, h1, l1r);
                *(uint32_t*)&Kh[base + 0] = h0; *(uint32_t*)&Kh[base + 2] = h1;
                *(uint32_t*)&Kl[base + 0] = l0r; *(uint32_t*)&Kl[base + 2] = l1r;
                split2(vv.x, vv.y, h0, l0r);
                split2(vv.z, vv.w, h1, l1r);
                *(uint32_t*)&Vh[base + 0] = h0; *(uint32_t*)&Vh[base + 2] = h1;
                *(uint32_t*)&Vl[base + 0] = l0r; *(uint32_t*)&Vl[base + 2] = l1r;
            }
        }
        __syncthreads();

        // S = Q K^T  (bf16x3 compensation)
        float S[8][4];
#pragma unroll
        for (int j = 0; j < 8; j++)
#pragma unroll
            for (int e = 0; e < 4; e++) S[j][e] = 0.f;

#pragma unroll
        for (int s = 0; s < 4; s++) {
#pragma unroll
            for (int jp = 0; jp < 4; jp++) {
                const int off = (16 * jp + 8 * (g >> 1) + rr) * KSTR
                              + 16 * s + 8 * (g & 1);
                uint32_t bhv[4], blv[4];
                ldsm4(bhv, (uint32_t)__cvta_generic_to_shared(&Kh[off]));
                ldsm4(blv, (uint32_t)__cvta_generic_to_shared(&Kl[off]));
                mma16816(S[2 * jp],     Qah[s], &bhv[0]);
                mma16816(S[2 * jp],     Qah[s], &blv[0]);
                mma16816(S[2 * jp],     Qal[s], &bhv[0]);
                mma16816(S[2 * jp + 1], Qah[s], &bhv[2]);
                mma16816(S[2 * jp + 1], Qah[s], &blv[2]);
                mma16816(S[2 * jp + 1], Qal[s], &bhv[2]);
            }
        }

        // scale + causal mask (mask only needed on diagonal tiles)
        const int grow0 = rowbase + warp * 16 + qr;
        if (kt * 64 + 63 > rowbase + warp * 16) {
#pragma unroll
            for (int j = 0; j < 8; j++)
#pragma unroll
                for (int e = 0; e < 4; e++) {
                    const int col = kt * 64 + 8 * j + 2 * qc + (e & 1);
                    const int row = grow0 + 8 * (e >> 1);
                    S[j][e] = (col <= row) ? S[j][e] * 0.125f : -1e30f;
                }
        } else {
#pragma unroll
            for (int j = 0; j < 8; j++)
#pragma unroll
                for (int e = 0; e < 4; e++) S[j][e] *= 0.125f;
        }

        // online softmax (rows r0 = e<2, r1 = e>=2)
        float mx0 = -1e30f, mx1 = -1e30f;
#pragma unroll
        for (int j = 0; j < 8; j++) {
            mx0 = fmaxf(mx0, fmaxf(S[j][0], S[j][1]));
            mx1 = fmaxf(mx1, fmaxf(S[j][2], S[j][3]));
        }
        mx0 = fmaxf(mx0, __shfl_xor_sync(0xffffffffu, mx0, 1));
        mx0 = fmaxf(mx0, __shfl_xor_sync(0xffffffffu, mx0, 2));
        mx1 = fmaxf(mx1, __shfl_xor_sync(0xffffffffu, mx1, 1));
        mx1 = fmaxf(mx1, __shfl_xor_sync(0xffffffffu, mx1, 2));

        const float nm0 = fmaxf(m0, mx0);
        const float nm1 = fmaxf(m1, mx1);
        const float c0 = __expf(m0 - nm0);
        const float c1 = __expf(m1 - nm1);
        m0 = nm0; m1 = nm1;

        float s0 = 0.f, s1 = 0.f;
#pragma unroll
        for (int j = 0; j < 8; j++) {
            S[j][0] = __expf(S[j][0] - m0); s0 += S[j][0];
            S[j][1] = __expf(S[j][1] - m0); s0 += S[j][1];
            S[j][2] = __expf(S[j][2] - m1); s1 += S[j][2];
            S[j][3] = __expf(S[j][3] - m1); s1 += S[j][3];
        }
        s0 += __shfl_xor_sync(0xffffffffu, s0, 1);
        s0 += __shfl_xor_sync(0xffffffffu, s0, 2);
        s1 += __shfl_xor_sync(0xffffffffu, s1, 1);
        s1 += __shfl_xor_sync(0xffffffffu, s1, 2);
        l0 = l0 * c0 + s0;
        l1 = l1 * c1 + s1;
#pragma unroll
        for (int j = 0; j < 8; j++) {
            O[j][0] *= c0; O[j][1] *= c0;
            O[j][2] *= c1; O[j][3] *= c1;
        }

        // O += P V  (bf16x3 compensation; P from S regs)
#pragma unroll
        for (int s = 0; s < 4; s++) {
            uint32_t Pah[4], Pal[4];
            split2(S[2 * s][0],     S[2 * s][1],     Pah[0], Pal[0]);
            split2(S[2 * s][2],     S[2 * s][3],     Pah[1], Pal[1]);
            split2(S[2 * s + 1][0], S[2 * s + 1][1], Pah[2], Pal[2]);
            split2(S[2 * s + 1][2], S[2 * s + 1][3], Pah[3], Pal[3]);
#pragma unroll
            for (int jp = 0; jp < 4; jp++) {
                const int off = (16 * s + 8 * (g & 1) + rr) * KSTR
                              + 16 * jp + 8 * (g >> 1);
                uint32_t bhv[4], blv[4];
                ldsm4t(bhv, (uint32_t)__cvta_generic_to_shared(&Vh[off]));
                ldsm4t(blv, (uint32_t)__cvta_generic_to_shared(&Vl[off]));
                mma16816(O[2 * jp],     Pah, &bhv[0]);
                mma16816(O[2 * jp],     Pah, &blv[0]);
                mma16816(O[2 * jp],     Pal, &bhv[0]);
                mma16816(O[2 * jp + 1], Pah, &bhv[2]);
                mma16816(O[2 * jp + 1], Pah, &blv[2]);
                mma16816(O[2 * jp + 1], Pal, &bhv[2]);
            }
        }
    }

    // epilogue: normalize and write [B,S,E]
    const float inv0 = 1.f / l0;
    const float inv1 = 1.f / l1;
    const int b = bh >> 3;
    const int h = bh & 7;
    const int row0 = rowbase + warp * 16 + qr;
    const int row1 = row0 + 8;
#pragma unroll
    for (int j = 0; j < 8; j++) {
        const int col = h * DH + 8 * j + 2 * qc;
        float2 v0 = make_float2(O[j][0] * inv0, O[j][1] * inv0);
        float2 v1 = make_float2(O[j][2] * inv1, O[j][3] * inv1);
        *(float2*)(Out + ((size_t)b * S_LEN + row0) * EMB + col) = v0;
        *(float2*)(Out + ((size_t)b * S_LEN + row1) * EMB + col) = v1;
    }
}

// ---------------------------------------------------------------------------
extern "C" void kernel_launch(void* const* d_in, const int* in_sizes, int n_in,
                              void* d_out, int out_size)
{
    const float* x    = (const float*)d_in[0];
    const float* Wqkv = (const float*)d_in[1];
    const float* bqkv = (const float*)d_in[2];
    const float* Wo   = (const float*)d_in[3];
    const float* bo   = (const float*)d_in[4];
    for (int i = 0; i < n_in; i++) {
        switch (in_sizes[i]) {
            case 8388608: x    = (const float*)d_in[i]; break;
            case 786432:  Wqkv = (const float*)d_in[i]; break;
            case 1536:    bqkv = (const float*)d_in[i]; break;
            case 262144:  Wo   = (const float*)d_in[i]; break;
            case 512:     bo   = (const float*)d_in[i]; break;
        }
    }
    float* out = (float*)d_out;

    static float* p_qkv = nullptr;
    static float* p_att = nullptr;
    if (!p_qkv) {
        void* tmp;
        cudaGetSymbolAddress(&tmp, g_qkv); p_qkv = (float*)tmp;
        cudaGetSymbolAddress(&tmp, g_att); p_att = (float*)tmp;
    }

    // 1) QKV projection
    gemm128_kernel<<<dim3(N_QKV / 128, M_ROWS / 128), 256>>>(
        x, Wqkv, bqkv, p_qkv, M_ROWS, N_QKV, EMB);

    // 2) Scatter into [B,H,S,Dh]
    {
        const size_t total = (size_t)M_ROWS * N_QKV;
        const int nblk = (int)((total + 255) / 256);
        scatter_qkv_kernel<<<nblk, 256>>>();
    }

    // 3) Tensor-core causal flash attention -> g_att [B,S,E]
    attn_mma_kernel<<<dim3(S_LEN / 128, BATCH * NH), 256>>>(p_att);

    // 4) Output projection
    gemm128_kernel<<<dim3(EMB / 128, M_ROWS / 128), 256>>>(
        p_att, Wo, bo, out, M_ROWS, EMB, EMB);
}

// round 6
// speedup vs baseline: 4.6124x; 1.0936x over previous
#include <cuda_runtime.h>
#include <cuda_bf16.h>
#include <math.h>
#include <stdint.h>

#define S_LEN 4096
#define EMB   512
#define NH    8
#define DH    64
#define BATCH 4
#define M_ROWS (BATCH * S_LEN)          // 16384
#define N_QKV  (3 * EMB)                // 1536
#define KSTR   72                        // smem half-stride (64 + 8 pad)
#define TILE_E (64 * KSTR)               // elements per smem tile

// Scratch (allocation-free: __device__ globals)
__device__ __align__(16) float g_att[(size_t)M_ROWS * EMB];           // [B,S,E]
// Pre-split bf16 hi/lo of Q (pre-scaled by 0.125), K, V — all [B,H,S,Dh]
__device__ __align__(16) __nv_bfloat16 g_Qh[(size_t)BATCH * NH * S_LEN * DH];
__device__ __align__(16) __nv_bfloat16 g_Ql[(size_t)BATCH * NH * S_LEN * DH];
__device__ __align__(16) __nv_bfloat16 g_Kh[(size_t)BATCH * NH * S_LEN * DH];
__device__ __align__(16) __nv_bfloat16 g_Kl[(size_t)BATCH * NH * S_LEN * DH];
__device__ __align__(16) __nv_bfloat16 g_Vh[(size_t)BATCH * NH * S_LEN * DH];
__device__ __align__(16) __nv_bfloat16 g_Vl[(size_t)BATCH * NH * S_LEN * DH];

__device__ __forceinline__ void split2(float x, float y, uint32_t& h, uint32_t& l)
{
    __nv_bfloat16 hx = __float2bfloat16(x);
    __nv_bfloat16 hy = __float2bfloat16(y);
    __nv_bfloat162 hh; hh.x = hx; hh.y = hy;
    __nv_bfloat162 ll;
    ll.x = __float2bfloat16(x - __bfloat162float(hx));
    ll.y = __float2bfloat16(y - __bfloat162float(hy));
    h = *(uint32_t*)&hh;
    l = *(uint32_t*)&ll;
}

// ---------------------------------------------------------------------------
// QKV GEMM with fused split/scatter epilogue:
//   qkv = x @ Wqkv + bqkv ; Q scaled by 0.125 ; all split to bf16 hi/lo
//   and scattered into [B,H,S,Dh].
// ---------------------------------------------------------------------------
__global__ __launch_bounds__(256) void gemm_qkv_split_kernel(
    const float* __restrict__ A,      // x  [16384, 512]
    const float* __restrict__ B,      // Wqkv [512, 1536]
    const float* __restrict__ bias)   // bqkv [1536]
{
    const int K = EMB, N = N_QKV;
    __shared__ float As[8][128];
    __shared__ float Bs[8][128];

    const int tid = threadIdx.x;
    const int bx = blockIdx.x;
    const int by = blockIdx.y;
    const int tx = tid & 15;
    const int ty = tid >> 4;

    const int aRow = tid >> 1;
    const int aCol = (tid & 1) * 4;
    const int bRow = tid >> 5;
    const int bCol = (tid & 31) * 4;

    const float* Ag = A + ((size_t)by * 128 + aRow) * K + aCol;
    const float* Bg = B + (size_t)bRow * N + bx * 128 + bCol;

    float acc[8][8];
#pragma unroll
    for (int i = 0; i < 8; i++)
#pragma unroll
        for (int j = 0; j < 8; j++) acc[i][j] = 0.f;

    for (int k0 = 0; k0 < K; k0 += 8) {
        const float4 a = *(const float4*)(Ag + k0);
        As[aCol + 0][aRow] = a.x;
        As[aCol + 1][aRow] = a.y;
        As[aCol + 2][aRow] = a.z;
        As[aCol + 3][aRow] = a.w;
        *(float4*)&Bs[bRow][bCol] = *(const float4*)(Bg + (size_t)k0 * N);
        __syncthreads();
#pragma unroll
        for (int k = 0; k < 8; k++) {
            float ra[8], rb[8];
#pragma unroll
            for (int i = 0; i < 8; i++) ra[i] = As[k][ty * 8 + i];
#pragma unroll
            for (int j = 0; j < 8; j++) rb[j] = Bs[k][tx * 8 + j];
#pragma unroll
            for (int i = 0; i < 8; i++)
#pragma unroll
                for (int j = 0; j < 8; j++) acc[i][j] += ra[i] * rb[j];
        }
        __syncthreads();
    }

    // Fused epilogue: bias + (Q scale) + split + scatter to [B,H,S,Dh]
#pragma unroll
    for (int i = 0; i < 8; i++) {
        const int row = by * 128 + ty * 8 + i;
        const int b = row >> 12;
        const int s = row & 4095;
#pragma unroll
        for (int j = 0; j < 8; j += 2) {
            const int col = bx * 128 + tx * 8 + j;   // even
            float v0 = acc[i][j + 0] + bias[col + 0];
            float v1 = acc[i][j + 1] + bias[col + 1];
            const int which = col >> 9;
            const int e = col & 511;
            const int h = e >> 6;
            const int d = e & 63;                    // even; d,d+1 same head
            if (which == 0) { v0 *= 0.125f; v1 *= 0.125f; }
            uint32_t hh, ll;
            split2(v0, v1, hh, ll);
            const size_t dst = (((size_t)(b * NH + h) * S_LEN) + s) * DH + d;
            __nv_bfloat16* ph = (which == 0) ? g_Qh : (which == 1) ? g_Kh : g_Vh;
            __nv_bfloat16* pl = (which == 0) ? g_Ql : (which == 1) ? g_Kl : g_Vl;
            *(uint32_t*)&ph[dst] = hh;
            *(uint32_t*)&pl[dst] = ll;
        }
    }
}

// ---------------------------------------------------------------------------
// Generic register-blocked SGEMM (unchanged, used for out-projection)
// ---------------------------------------------------------------------------
__global__ __launch_bounds__(256) void gemm128_kernel(
    const float* __restrict__ A, const float* __restrict__ B,
    const float* __restrict__ bias, float* __restrict__ C,
    int M, int N, int K)
{
    __shared__ float As[8][128];
    __shared__ float Bs[8][128];

    const int tid = threadIdx.x;
    const int bx = blockIdx.x;
    const int by = blockIdx.y;
    const int tx = tid & 15;
    const int ty = tid >> 4;

    const int aRow = tid >> 1;
    const int aCol = (tid & 1) * 4;
    const int bRow = tid >> 5;
    const int bCol = (tid & 31) * 4;

    const float* Ag = A + ((size_t)by * 128 + aRow) * K + aCol;
    const float* Bg = B + (size_t)bRow * N + bx * 128 + bCol;

    float acc[8][8];
#pragma unroll
    for (int i = 0; i < 8; i++)
#pragma unroll
        for (int j = 0; j < 8; j++) acc[i][j] = 0.f;

    for (int k0 = 0; k0 < K; k0 += 8) {
        const float4 a = *(const float4*)(Ag + k0);
        As[aCol + 0][aRow] = a.x;
        As[aCol + 1][aRow] = a.y;
        As[aCol + 2][aRow] = a.z;
        As[aCol + 3][aRow] = a.w;
        *(float4*)&Bs[bRow][bCol] = *(const float4*)(Bg + (size_t)k0 * N);
        __syncthreads();
#pragma unroll
        for (int k = 0; k < 8; k++) {
            float ra[8], rb[8];
#pragma unroll
            for (int i = 0; i < 8; i++) ra[i] = As[k][ty * 8 + i];
#pragma unroll
            for (int j = 0; j < 8; j++) rb[j] = Bs[k][tx * 8 + j];
#pragma unroll
            for (int i = 0; i < 8; i++)
#pragma unroll
                for (int j = 0; j < 8; j++) acc[i][j] += ra[i] * rb[j];
        }
        __syncthreads();
    }

#pragma unroll
    for (int i = 0; i < 8; i++) {
        const int row = by * 128 + ty * 8 + i;
#pragma unroll
        for (int j = 0; j < 8; j += 4) {
            const int col = bx * 128 + tx * 8 + j;
            float4 v;
            v.x = acc[i][j + 0] + bias[col + 0];
            v.y = acc[i][j + 1] + bias[col + 1];
            v.z = acc[i][j + 2] + bias[col + 2];
            v.w = acc[i][j + 3] + bias[col + 3];
            *(float4*)(C + (size_t)row * N + col) = v;
        }
    }
}

// ---------------------------------------------------------------------------
// Tensor-core flash attention: pre-split bf16 inputs, cp.async double buffer.
// ---------------------------------------------------------------------------
__device__ __forceinline__ void mma16816(float c[4], const uint32_t a[4],
                                         const uint32_t* b)
{
    asm volatile(
        "mma.sync.aligned.m16n8k16.row.col.f32.bf16.bf16.f32 "
        "{%0,%1,%2,%3}, {%4,%5,%6,%7}, {%8,%9}, {%0,%1,%2,%3};\n"
        : "+f"(c[0]), "+f"(c[1]), "+f"(c[2]), "+f"(c[3])
        : "r"(a[0]), "r"(a[1]), "r"(a[2]), "r"(a[3]), "r"(b[0]), "r"(b[1]));
}

__device__ __forceinline__ void ldsm4(uint32_t r[4], uint32_t addr)
{
    asm volatile("ldmatrix.sync.aligned.m8n8.x4.shared.b16 {%0,%1,%2,%3}, [%4];\n"
                 : "=r"(r[0]), "=r"(r[1]), "=r"(r[2]), "=r"(r[3]) : "r"(addr));
}

__device__ __forceinline__ void ldsm4t(uint32_t r[4], uint32_t addr)
{
    asm volatile("ldmatrix.sync.aligned.m8n8.x4.trans.shared.b16 {%0,%1,%2,%3}, [%4];\n"
                 : "=r"(r[0]), "=r"(r[1]), "=r"(r[2]), "=r"(r[3]) : "r"(addr));
}

__device__ __forceinline__ void cpasync16(uint32_t s, const void* g)
{
    asm volatile("cp.async.cg.shared.global [%0], [%1], 16;\n"
                 :: "r"(s), "l"(g));
}

__global__ __launch_bounds__(256) void attn_mma_kernel(float* __restrict__ Out)
{
    extern __shared__ __align__(16) __nv_bfloat16 sm[];
    // layout: [arr 0..3 = Kh,Kl,Vh,Vl][buf 0..1][64*KSTR]

    const int tid  = threadIdx.x;
    const int warp = tid >> 5;
    const int lane = tid & 31;
    const int qt = blockIdx.x;
    const int bh = blockIdx.y;
    const int rowbase = qt * 128;
    const int qr = lane >> 2;
    const int qc = lane & 3;
    const int g  = lane >> 3;
    const int rr = lane & 7;

    const uint32_t smem_base = (uint32_t)__cvta_generic_to_shared(sm);

    const __nv_bfloat16* srcs[4] = {
        g_Kh + (size_t)bh * S_LEN * DH,
        g_Kl + (size_t)bh * S_LEN * DH,
        g_Vh + (size_t)bh * S_LEN * DH,
        g_Vl + (size_t)bh * S_LEN * DH };

    // Q a-fragments from pre-split gmem
    uint32_t Qah[4][4], Qal[4][4];
    {
        const size_t qoff = ((size_t)bh * S_LEN + rowbase + warp * 16) * DH;
#pragma unroll
        for (int s = 0; s < 4; s++)
#pragma unroll
            for (int e = 0; e < 4; e++) {
                const int r = qr + 8 * (e & 1);
                const int c = 16 * s + 2 * qc + 8 * (e >> 1);
                Qah[s][e] = *(const uint32_t*)(g_Qh + qoff + (size_t)r * DH + c);
                Qal[s][e] = *(const uint32_t*)(g_Ql + qoff + (size_t)r * DH + c);
            }
    }

    float O[8][4];
#pragma unroll
    for (int j = 0; j < 8; j++)
#pragma unroll
        for (int e = 0; e < 4; e++) O[j][e] = 0.f;
    float m0 = -1e30f, m1 = -1e30f, l0 = 0.f, l1 = 0.f;

    const int nT = qt * 2 + 2;

    // async fill of tile kt into buffer buf
    auto fill = [&](int kt, int buf) {
#pragma unroll
        for (int i = 0; i < 8; i++) {
            const int arr = i >> 1;
            const int e = ((i & 1) << 8) + tid;      // 0..511
            const int row = e >> 3;
            const int grp = e & 7;
            const __nv_bfloat16* src = srcs[arr] + (size_t)kt * 64 * DH
                                     + (size_t)row * DH + grp * 8;
            const uint32_t dst = smem_base +
                ((arr * 2 + buf) * TILE_E + row * KSTR + grp * 8) * 2;
            cpasync16(dst, src);
        }
        asm volatile("cp.async.commit_group;\n");
    };

    fill(0, 0);

    for (int kt = 0; kt < nT; kt++) {
        const int buf = kt & 1;
        asm volatile("cp.async.wait_group 0;\n");
        __syncthreads();
        if (kt + 1 < nT) fill(kt + 1, buf ^ 1);

        const uint32_t Kh_t = smem_base + ((0 * 2 + buf) * TILE_E) * 2;
        const uint32_t Kl_t = smem_base + ((1 * 2 + buf) * TILE_E) * 2;
        const uint32_t Vh_t = smem_base + ((2 * 2 + buf) * TILE_E) * 2;
        const uint32_t Vl_t = smem_base + ((3 * 2 + buf) * TILE_E) * 2;

        // S = Q K^T  (bf16x3 compensation; scale pre-folded into Q)
        float S[8][4];
#pragma unroll
        for (int j = 0; j < 8; j++)
#pragma unroll
            for (int e = 0; e < 4; e++) S[j][e] = 0.f;

#pragma unroll
        for (int s = 0; s < 4; s++) {
#pragma unroll
            for (int jp = 0; jp < 4; jp++) {
                const uint32_t off = ((16 * jp + 8 * (g >> 1) + rr) * KSTR
                                    + 16 * s + 8 * (g & 1)) * 2;
                uint32_t bhv[4], blv[4];
                ldsm4(bhv, Kh_t + off);
                ldsm4(blv, Kl_t + off);
                mma16816(S[2 * jp],     Qah[s], &bhv[0]);
                mma16816(S[2 * jp],     Qah[s], &blv[0]);
                mma16816(S[2 * jp],     Qal[s], &bhv[0]);
                mma16816(S[2 * jp + 1], Qah[s], &bhv[2]);
                mma16816(S[2 * jp + 1], Qah[s], &blv[2]);
                mma16816(S[2 * jp + 1], Qal[s], &bhv[2]);
            }
        }

        // causal mask (diagonal tiles only)
        const int grow0 = rowbase + warp * 16 + qr;
        if (kt * 64 + 63 > rowbase + warp * 16) {
#pragma unroll
            for (int j = 0; j < 8; j++)
#pragma unroll
                for (int e = 0; e < 4; e++) {
                    const int col = kt * 64 + 8 * j + 2 * qc + (e & 1);
                    const int row = grow0 + 8 * (e >> 1);
                    if (col > row) S[j][e] = -1e30f;
                }
        }

        // online softmax
        float mx0 = -1e30f, mx1 = -1e30f;
#pragma unroll
        for (int j = 0; j < 8; j++) {
            mx0 = fmaxf(mx0, fmaxf(S[j][0], S[j][1]));
            mx1 = fmaxf(mx1, fmaxf(S[j][2], S[j][3]));
        }
        mx0 = fmaxf(mx0, __shfl_xor_sync(0xffffffffu, mx0, 1));
        mx0 = fmaxf(mx0, __shfl_xor_sync(0xffffffffu, mx0, 2));
        mx1 = fmaxf(mx1, __shfl_xor_sync(0xffffffffu, mx1, 1));
        mx1 = fmaxf(mx1, __shfl_xor_sync(0xffffffffu, mx1, 2));

        const float nm0 = fmaxf(m0, mx0);
        const float nm1 = fmaxf(m1, mx1);
        const float c0 = __expf(m0 - nm0);
        const float c1 = __expf(m1 - nm1);
        m0 = nm0; m1 = nm1;

        float s0 = 0.f, s1 = 0.f;
#pragma unroll
        for (int j = 0; j < 8; j++) {
            S[j][0] = __expf(S[j][0] - m0); s0 += S[j][0];
            S[j][1] = __expf(S[j][1] - m0); s0 += S[j][1];
            S[j][2] = __expf(S[j][2] - m1); s1 += S[j][2];
            S[j][3] = __expf(S[j][3] - m1); s1 += S[j][3];
        }
        s0 += __shfl_xor_sync(0xffffffffu, s0, 1);
        s0 += __shfl_xor_sync(0xffffffffu, s0, 2);
        s1 += __shfl_xor_sync(0xffffffffu, s1, 1);
        s1 += __shfl_xor_sync(0xffffffffu, s1, 2);
        l0 = l0 * c0 + s0;
        l1 = l1 * c1 + s1;
#pragma unroll
        for (int j = 0; j < 8; j++) {
            O[j][0] *= c0; O[j][1] *= c0;
            O[j][2] *= c1; O[j][3] *= c1;
        }

        // O += P V  (bf16x3 compensation)
#pragma unroll
        for (int s = 0; s < 4; s++) {
            uint32_t Pah[4], Pal[4];
            split2(S[2 * s][0],     S[2 * s][1],     Pah[0], Pal[0]);
            split2(S[2 * s][2],     S[2 * s][3],     Pah[1], Pal[1]);
            split2(S[2 * s + 1][0], S[2 * s + 1][1], Pah[2], Pal[2]);
            split2(S[2 * s + 1][2], S[2 * s + 1][3], Pah[3], Pal[3]);
#pragma unroll
            for (int jp = 0; jp < 4; jp++) {
                const uint32_t off = ((16 * s + 8 * (g & 1) + rr) * KSTR
                                    + 16 * jp + 8 * (g >> 1)) * 2;
                uint32_t bhv[4], blv[4];
                ldsm4t(bhv, Vh_t + off);
                ldsm4t(blv, Vl_t + off);
                mma16816(O[2 * jp],     Pah, &bhv[0]);
                mma16816(O[2 * jp],     Pah, &blv[0]);
                mma16816(O[2 * jp],     Pal, &bhv[0]);
                mma16816(O[2 * jp + 1], Pah, &bhv[2]);
                mma16816(O[2 * jp + 1], Pah, &blv[2]);
                mma16816(O[2 * jp + 1], Pal, &bhv[2]);
            }
        }
        __syncthreads();
    }

    // epilogue: normalize and write [B,S,E]
    const float inv0 = 1.f / l0;
    const float inv1 = 1.f / l1;
    const int b = bh >> 3;
    const int h = bh & 7;
    const int row0 = rowbase + warp * 16 + qr;
    const int row1 = row0 + 8;
#pragma unroll
    for (int j = 0; j < 8; j++) {
        const int col = h * DH + 8 * j + 2 * qc;
        float2 v0 = make_float2(O[j][0] * inv0, O[j][1] * inv0);
        float2 v1 = make_float2(O[j][2] * inv1, O[j][3] * inv1);
        *(float2*)(Out + ((size_t)b * S_LEN + row0) * EMB + col) = v0;
        *(float2*)(Out + ((size_t)b * S_LEN + row1) * EMB + col) = v1;
    }
}

// ---------------------------------------------------------------------------
extern "C" void kernel_launch(void* const* d_in, const int* in_sizes, int n_in,
                              void* d_out, int out_size)
{
    const float* x    = (const float*)d_in[0];
    const float* Wqkv = (const float*)d_in[1];
    const float* bqkv = (const float*)d_in[2];
    const float* Wo   = (const float*)d_in[3];
    const float* bo   = (const float*)d_in[4];
    for (int i = 0; i < n_in; i++) {
        switch (in_sizes[i]) {
            case 8388608: x    = (const float*)d_in[i]; break;
            case 786432:  Wqkv = (const float*)d_in[i]; break;
            case 1536:    bqkv = (const float*)d_in[i]; break;
            case 262144:  Wo   = (const float*)d_in[i]; break;
            case 512:     bo   = (const float*)d_in[i]; break;
        }
    }
    float* out = (float*)d_out;

    const int ATTN_SMEM = 2 * 4 * TILE_E * 2;   // 73728 bytes

    static float* p_att = nullptr;
    if (!p_att) {
        void* tmp;
        cudaGetSymbolAddress(&tmp, g_att); p_att = (float*)tmp;
        cudaFuncSetAttribute(attn_mma_kernel,
                             cudaFuncAttributeMaxDynamicSharedMemorySize,
                             ATTN_SMEM);
    }

    // 1) QKV projection + fused split/scatter
    gemm_qkv_split_kernel<<<dim3(N_QKV / 128, M_ROWS / 128), 256>>>(
        x, Wqkv, bqkv);

    // 2) Tensor-core causal flash attention -> g_att [B,S,E]
    attn_mma_kernel<<<dim3(S_LEN / 128, BATCH * NH), 256, ATTN_SMEM>>>(p_att);

    // 3) Output projection
    gemm128_kernel<<<dim3(EMB / 128, M_ROWS / 128), 256>>>(
        p_att, Wo, bo, out, M_ROWS, EMB, EMB);
}

// round 7
// speedup vs baseline: 7.3038x; 1.5835x over previous
#include <cuda_runtime.h>
#include <cuda_bf16.h>
#include <math.h>
#include <stdint.h>

#define S_LEN 4096
#define EMB   512
#define NH    8
#define DH    64
#define BATCH 4
#define M_ROWS (BATCH * S_LEN)          // 16384
#define N_QKV  (3 * EMB)                // 1536
#define KSTR   72                        // attn smem stride (64 + 8 pad)
#define TILE_E (64 * KSTR)

// GEMM smem strides (halves)
#define ASTR 40                          // 32 + 8
#define BSTR 136                         // 128 + 8
#define GBUF 18944                       // halves per gemm buffer
#define GSMEM (2 * GBUF * 2)             // bytes (75776)
#define ATTN_SMEM (2 * 4 * TILE_E * 2)   // 73728

// Scratch (allocation-free: __device__ globals)
__device__ __align__(16) __nv_bfloat16 g_xh[(size_t)M_ROWS * EMB];
__device__ __align__(16) __nv_bfloat16 g_xl[(size_t)M_ROWS * EMB];
__device__ __align__(16) __nv_bfloat16 g_Wqkvh[(size_t)EMB * N_QKV];
__device__ __align__(16) __nv_bfloat16 g_Wqkvl[(size_t)EMB * N_QKV];
__device__ __align__(16) __nv_bfloat16 g_Woh[(size_t)EMB * EMB];
__device__ __align__(16) __nv_bfloat16 g_Wol[(size_t)EMB * EMB];
// Q pre-scaled by 0.125; all [B,H,S,Dh]
__device__ __align__(16) __nv_bfloat16 g_Qh[(size_t)BATCH * NH * S_LEN * DH];
__device__ __align__(16) __nv_bfloat16 g_Ql[(size_t)BATCH * NH * S_LEN * DH];
__device__ __align__(16) __nv_bfloat16 g_Kh[(size_t)BATCH * NH * S_LEN * DH];
__device__ __align__(16) __nv_bfloat16 g_Kl[(size_t)BATCH * NH * S_LEN * DH];
__device__ __align__(16) __nv_bfloat16 g_Vh[(size_t)BATCH * NH * S_LEN * DH];
__device__ __align__(16) __nv_bfloat16 g_Vl[(size_t)BATCH * NH * S_LEN * DH];
// attention output split [B,S,E]
__device__ __align__(16) __nv_bfloat16 g_atth[(size_t)M_ROWS * EMB];
__device__ __align__(16) __nv_bfloat16 g_attl[(size_t)M_ROWS * EMB];

__device__ __forceinline__ void split2(float x, float y, uint32_t& h, uint32_t& l)
{
    __nv_bfloat16 hx = __float2bfloat16(x);
    __nv_bfloat16 hy = __float2bfloat16(y);
    __nv_bfloat162 hh; hh.x = hx; hh.y = hy;
    __nv_bfloat162 ll;
    ll.x = __float2bfloat16(x - __bfloat162float(hx));
    ll.y = __float2bfloat16(y - __bfloat162float(hy));
    h = *(uint32_t*)&hh;
    l = *(uint32_t*)&ll;
}

__device__ __forceinline__ void mma16816(float c[4], const uint32_t a[4],
                                         const uint32_t* b)
{
    asm volatile(
        "mma.sync.aligned.m16n8k16.row.col.f32.bf16.bf16.f32 "
        "{%0,%1,%2,%3}, {%4,%5,%6,%7}, {%8,%9}, {%0,%1,%2,%3};\n"
        : "+f"(c[0]), "+f"(c[1]), "+f"(c[2]), "+f"(c[3])
        : "r"(a[0]), "r"(a[1]), "r"(a[2]), "r"(a[3]), "r"(b[0]), "r"(b[1]));
}

__device__ __forceinline__ void ldsm4(uint32_t r[4], uint32_t addr)
{
    asm volatile("ldmatrix.sync.aligned.m8n8.x4.shared.b16 {%0,%1,%2,%3}, [%4];\n"
                 : "=r"(r[0]), "=r"(r[1]), "=r"(r[2]), "=r"(r[3]) : "r"(addr));
}

__device__ __forceinline__ void ldsm4t(uint32_t r[4], uint32_t addr)
{
    asm volatile("ldmatrix.sync.aligned.m8n8.x4.trans.shared.b16 {%0,%1,%2,%3}, [%4];\n"
                 : "=r"(r[0]), "=r"(r[1]), "=r"(r[2]), "=r"(r[3]) : "r"(addr));
}

__device__ __forceinline__ void cpasync16(uint32_t s, const void* g)
{
    asm volatile("cp.async.cg.shared.global [%0], [%1], 16;\n" :: "r"(s), "l"(g));
}

// ---------------------------------------------------------------------------
// Split fp32 array -> bf16 hi/lo (2 elements per thread)
// ---------------------------------------------------------------------------
__global__ __launch_bounds__(256) void split_kernel(
    const float* __restrict__ src, __nv_bfloat16* __restrict__ h,
    __nv_bfloat16* __restrict__ l, int n2)
{
    const int idx = blockIdx.x * 256 + threadIdx.x;
    if (idx >= n2) return;
    const float2 v = ((const float2*)src)[idx];
    uint32_t hh, ll;
    split2(v.x, v.y, hh, ll);
    ((uint32_t*)h)[idx] = hh;
    ((uint32_t*)l)[idx] = ll;
}

// ---------------------------------------------------------------------------
// bf16x3 tensor-core GEMM: C = A @ B + bias
// A [M,K] hi/lo, B [K,N] hi/lo. 128x128 tile, k-chunk 32, cp.async dbuf.
// mode 0: fp32 C out (out-projection). mode 1: QKV split/scatter epilogue.
// ---------------------------------------------------------------------------
__global__ __launch_bounds__(256) void gemm_bf3_kernel(
    const __nv_bfloat16* __restrict__ Ah, const __nv_bfloat16* __restrict__ Al,
    const __nv_bfloat16* __restrict__ Bh, const __nv_bfloat16* __restrict__ Bl,
    const float* __restrict__ bias, float* __restrict__ C,
    int N, int K, int mode)
{
    extern __shared__ __align__(16) __nv_bfloat16 sg[];
    const int tid  = threadIdx.x;
    const int bx = blockIdx.x, by = blockIdx.y;
    const int lane = tid & 31, warp = tid >> 5;
    const int wm = warp & 3, wn = warp >> 2;       // warp tile m32 x n64
    const int qr = lane >> 2, qc = lane & 3;
    const int g = lane >> 3, rr = lane & 7;
    const uint32_t sb = (uint32_t)__cvta_generic_to_shared(sg);

    float acc[2][8][4];
#pragma unroll
    for (int i = 0; i < 2; i++)
#pragma unroll
        for (int j = 0; j < 8; j++)
#pragma unroll
            for (int e = 0; e < 4; e++) acc[i][j][e] = 0.f;

    auto fill = [&](int kc, int buf) {
        const int k0 = kc * 32;
        const uint32_t base = sb + buf * GBUF * 2;
        // A: 128 rows x 4 chunks x 2 arrays = 1024 chunks
#pragma unroll
        for (int t = 0; t < 4; t++) {
            const int idx = t * 256 + tid;
            const int arr = idx >> 9;
            const int rem = idx & 511;
            const int row = rem >> 2, c = rem & 3;
            const __nv_bfloat16* src =
                (arr ? Al : Ah) + (size_t)(by * 128 + row) * K + k0 + c * 8;
            cpasync16(base + (arr * 5120 + row * ASTR + c * 8) * 2, src);
        }
        // B: 32 rows x 16 chunks x 2 arrays = 1024 chunks
#pragma unroll
        for (int t = 0; t < 4; t++) {
            const int idx = t * 256 + tid;
            const int arr = idx >> 9;
            const int rem = idx & 511;
            const int row = rem >> 4, c = rem & 15;
            const __nv_bfloat16* src =
                (arr ? Bl : Bh) + (size_t)(k0 + row) * N + bx * 128 + c * 8;
            cpasync16(base + (10240 + arr * 4352 + row * BSTR + c * 8) * 2, src);
        }
        asm volatile("cp.async.commit_group;\n");
    };

    fill(0, 0);
    const int nkc = K / 32;

    for (int kc = 0; kc < nkc; kc++) {
        const int buf = kc & 1;
        asm volatile("cp.async.wait_group 0;\n");
        __syncthreads();
        if (kc + 1 < nkc) fill(kc + 1, buf ^ 1);

        const uint32_t base = sb + buf * GBUF * 2;
        const uint32_t Ah_s = base;
        const uint32_t Al_s = base + 5120 * 2;
        const uint32_t Bh_s = base + 10240 * 2;
        const uint32_t Bl_s = base + 14592 * 2;

#pragma unroll
        for (int s = 0; s < 2; s++) {
            uint32_t afh[2][4], afl[2][4];
#pragma unroll
            for (int i = 0; i < 2; i++) {
                const uint32_t off =
                    ((wm * 32 + i * 16 + (lane & 15)) * ASTR
                     + s * 16 + 8 * (lane >> 4)) * 2;
                ldsm4(afh[i], Ah_s + off);
                ldsm4(afl[i], Al_s + off);
            }
#pragma unroll
            for (int jp = 0; jp < 4; jp++) {
                const uint32_t off =
                    ((s * 16 + 8 * (g & 1) + rr) * BSTR
                     + wn * 64 + jp * 16 + 8 * (g >> 1)) * 2;
                uint32_t bh4[4], bl4[4];
                ldsm4t(bh4, Bh_s + off);
                ldsm4t(bl4, Bl_s + off);
#pragma unroll
                for (int i = 0; i < 2; i++) {
                    mma16816(acc[i][2 * jp],     afh[i], &bh4[0]);
                    mma16816(acc[i][2 * jp],     afh[i], &bl4[0]);
                    mma16816(acc[i][2 * jp],     afl[i], &bh4[0]);
                    mma16816(acc[i][2 * jp + 1], afh[i], &bh4[2]);
                    mma16816(acc[i][2 * jp + 1], afh[i], &bl4[2]);
                    mma16816(acc[i][2 * jp + 1], afl[i], &bh4[2]);
                }
            }
        }
        __syncthreads();
    }

    if (mode == 0) {
        // out-projection epilogue: fp32 store
#pragma unroll
        for (int i = 0; i < 2; i++) {
            const int row0 = by * 128 + wm * 32 + i * 16 + qr;
#pragma unroll
            for (int j = 0; j < 8; j++) {
                const int col = bx * 128 + wn * 64 + j * 8 + 2 * qc;
                float2 v0 = make_float2(acc[i][j][0] + bias[col],
                                        acc[i][j][1] + bias[col + 1]);
                float2 v1 = make_float2(acc[i][j][2] + bias[col],
                                        acc[i][j][3] + bias[col + 1]);
                *(float2*)(C + (size_t)row0 * N + col) = v0;
                *(float2*)(C + (size_t)(row0 + 8) * N + col) = v1;
            }
        }
    } else {
        // QKV epilogue: bias + (Q scale) + split + scatter to [B,H,S,Dh]
#pragma unroll
        for (int i = 0; i < 2; i++) {
            const int row0 = by * 128 + wm * 32 + i * 16 + qr;
            const int b = row0 >> 12;
            const int s0 = row0 & 4095;
#pragma unroll
            for (int j = 0; j < 8; j++) {
                const int col = bx * 128 + wn * 64 + j * 8 + 2 * qc;
                float v0 = acc[i][j][0] + bias[col];
                float v1 = acc[i][j][1] + bias[col + 1];
                float v2 = acc[i][j][2] + bias[col];
                float v3 = acc[i][j][3] + bias[col + 1];
                const int which = col >> 9;
                const int e = col & 511;
                const int h = e >> 6;
                const int d = e & 63;
                if (which == 0) { v0 *= 0.125f; v1 *= 0.125f;
                                  v2 *= 0.125f; v3 *= 0.125f; }
                __nv_bfloat16* ph = (which == 0) ? g_Qh : (which == 1) ? g_Kh : g_Vh;
                __nv_bfloat16* pl = (which == 0) ? g_Ql : (which == 1) ? g_Kl : g_Vl;
                uint32_t hh, ll;
                const size_t dst0 = (((size_t)(b * NH + h) * S_LEN) + s0) * DH + d;
                split2(v0, v1, hh, ll);
                *(uint32_t*)&ph[dst0] = hh;
                *(uint32_t*)&pl[dst0] = ll;
                const size_t dst1 = dst0 + (size_t)8 * DH;
                split2(v2, v3, hh, ll);
                *(uint32_t*)&ph[dst1] = hh;
                *(uint32_t*)&pl[dst1] = ll;
            }
        }
    }
}

// ---------------------------------------------------------------------------
// Tensor-core flash attention (unchanged core; epilogue writes bf16 split)
// ---------------------------------------------------------------------------
__global__ __launch_bounds__(256) void attn_mma_kernel()
{
    extern __shared__ __align__(16) __nv_bfloat16 sm[];

    const int tid  = threadIdx.x;
    const int warp = tid >> 5;
    const int lane = tid & 31;
    const int qt = blockIdx.x;
    const int bh = blockIdx.y;
    const int rowbase = qt * 128;
    const int qr = lane >> 2;
    const int qc = lane & 3;
    const int g  = lane >> 3;
    const int rr = lane & 7;

    const uint32_t smem_base = (uint32_t)__cvta_generic_to_shared(sm);

    const __nv_bfloat16* srcs[4] = {
        g_Kh + (size_t)bh * S_LEN * DH,
        g_Kl + (size_t)bh * S_LEN * DH,
        g_Vh + (size_t)bh * S_LEN * DH,
        g_Vl + (size_t)bh * S_LEN * DH };

    uint32_t Qah[4][4], Qal[4][4];
    {
        const size_t qoff = ((size_t)bh * S_LEN + rowbase + warp * 16) * DH;
#pragma unroll
        for (int s = 0; s < 4; s++)
#pragma unroll
            for (int e = 0; e < 4; e++) {
                const int r = qr + 8 * (e & 1);
                const int c = 16 * s + 2 * qc + 8 * (e >> 1);
                Qah[s][e] = *(const uint32_t*)(g_Qh + qoff + (size_t)r * DH + c);
                Qal[s][e] = *(const uint32_t*)(g_Ql + qoff + (size_t)r * DH + c);
            }
    }

    float O[8][4];
#pragma unroll
    for (int j = 0; j < 8; j++)
#pragma unroll
        for (int e = 0; e < 4; e++) O[j][e] = 0.f;
    float m0 = -1e30f, m1 = -1e30f, l0 = 0.f, l1 = 0.f;

    const int nT = qt * 2 + 2;

    auto fill = [&](int kt, int buf) {
#pragma unroll
        for (int i = 0; i < 8; i++) {
            const int arr = i >> 1;
            const int e = ((i & 1) << 8) + tid;
            const int row = e >> 3;
            const int grp = e & 7;
            const __nv_bfloat16* src = srcs[arr] + (size_t)kt * 64 * DH
                                     + (size_t)row * DH + grp * 8;
            const uint32_t dst = smem_base +
                ((arr * 2 + buf) * TILE_E + row * KSTR + grp * 8) * 2;
            cpasync16(dst, src);
        }
        asm volatile("cp.async.commit_group;\n");
    };

    fill(0, 0);

    for (int kt = 0; kt < nT; kt++) {
        const int buf = kt & 1;
        asm volatile("cp.async.wait_group 0;\n");
        __syncthreads();
        if (kt + 1 < nT) fill(kt + 1, buf ^ 1);

        const uint32_t Kh_t = smem_base + ((0 * 2 + buf) * TILE_E) * 2;
        const uint32_t Kl_t = smem_base + ((1 * 2 + buf) * TILE_E) * 2;
        const uint32_t Vh_t = smem_base + ((2 * 2 + buf) * TILE_E) * 2;
        const uint32_t Vl_t = smem_base + ((3 * 2 + buf) * TILE_E) * 2;

        float S[8][4];
#pragma unroll
        for (int j = 0; j < 8; j++)
#pragma unroll
            for (int e = 0; e < 4; e++) S[j][e] = 0.f;

#pragma unroll
        for (int s = 0; s < 4; s++) {
#pragma unroll
            for (int jp = 0; jp < 4; jp++) {
                const uint32_t off = ((16 * jp + 8 * (g >> 1) + rr) * KSTR
                                    + 16 * s + 8 * (g & 1)) * 2;
                uint32_t bhv[4], blv[4];
                ldsm4(bhv, Kh_t + off);
                ldsm4(blv, Kl_t + off);
                mma16816(S[2 * jp],     Qah[s], &bhv[0]);
                mma16816(S[2 * jp],     Qah[s], &blv[0]);
                mma16816(S[2 * jp],     Qal[s], &bhv[0]);
                mma16816(S[2 * jp + 1], Qah[s], &bhv[2]);
                mma16816(S[2 * jp + 1], Qah[s], &blv[2]);
                mma16816(S[2 * jp + 1], Qal[s], &bhv[2]);
            }
        }

        const int grow0 = rowbase + warp * 16 + qr;
        if (kt * 64 + 63 > rowbase + warp * 16) {
#pragma unroll
            for (int j = 0; j < 8; j++)
#pragma unroll
                for (int e = 0; e < 4; e++) {
                    const int col = kt * 64 + 8 * j + 2 * qc + (e & 1);
                    const int row = grow0 + 8 * (e >> 1);
                    if (col > row) S[j][e] = -1e30f;
                }
        }

        float mx0 = -1e30f, mx1 = -1e30f;
#pragma unroll
        for (int j = 0; j < 8; j++) {
            mx0 = fmaxf(mx0, fmaxf(S[j][0], S[j][1]));
            mx1 = fmaxf(mx1, fmaxf(S[j][2], S[j][3]));
        }
        mx0 = fmaxf(mx0, __shfl_xor_sync(0xffffffffu, mx0, 1));
        mx0 = fmaxf(mx0, __shfl_xor_sync(0xffffffffu, mx0, 2));
        mx1 = fmaxf(mx1, __shfl_xor_sync(0xffffffffu, mx1, 1));
        mx1 = fmaxf(mx1, __shfl_xor_sync(0xffffffffu, mx1, 2));

        const float nm0 = fmaxf(m0, mx0);
        const float nm1 = fmaxf(m1, mx1);
        const float c0 = __expf(m0 - nm0);
        const float c1 = __expf(m1 - nm1);
        m0 = nm0; m1 = nm1;

        float s0 = 0.f, s1 = 0.f;
#pragma unroll
        for (int j = 0; j < 8; j++) {
            S[j][0] = __expf(S[j][0] - m0); s0 += S[j][0];
            S[j][1] = __expf(S[j][1] - m0); s0 += S[j][1];
            S[j][2] = __expf(S[j][2] - m1); s1 += S[j][2];
            S[j][3] = __expf(S[j][3] - m1); s1 += S[j][3];
        }
        s0 += __shfl_xor_sync(0xffffffffu, s0, 1);
        s0 += __shfl_xor_sync(0xffffffffu, s0, 2);
        s1 += __shfl_xor_sync(0xffffffffu, s1, 1);
        s1 += __shfl_xor_sync(0xffffffffu, s1, 2);
        l0 = l0 * c0 + s0;
        l1 = l1 * c1 + s1;
#pragma unroll
        for (int j = 0; j < 8; j++) {
            O[j][0] *= c0; O[j][1] *= c0;
            O[j][2] *= c1; O[j][3] *= c1;
        }

#pragma unroll
        for (int s = 0; s < 4; s++) {
            uint32_t Pah[4], Pal[4];
            split2(S[2 * s][0],     S[2 * s][1],     Pah[0], Pal[0]);
            split2(S[2 * s][2],     S[2 * s][3],     Pah[1], Pal[1]);
            split2(S[2 * s + 1][0], S[2 * s + 1][1], Pah[2], Pal[2]);
            split2(S[2 * s + 1][2], S[2 * s + 1][3], Pah[3], Pal[3]);
#pragma unroll
            for (int jp = 0; jp < 4; jp++) {
                const uint32_t off = ((16 * s + 8 * (g & 1) + rr) * KSTR
                                    + 16 * jp + 8 * (g >> 1)) * 2;
                uint32_t bhv[4], blv[4];
                ldsm4t(bhv, Vh_t + off);
                ldsm4t(blv, Vl_t + off);
                mma16816(O[2 * jp],     Pah, &bhv[0]);
                mma16816(O[2 * jp],     Pah, &blv[0]);
                mma16816(O[2 * jp],     Pal, &bhv[0]);
                mma16816(O[2 * jp + 1], Pah, &bhv[2]);
                mma16816(O[2 * jp + 1], Pah, &blv[2]);
                mma16816(O[2 * jp + 1], Pal, &bhv[2]);
            }
        }
        __syncthreads();
    }

    // epilogue: normalize, split to bf16 hi/lo, write [B,S,E]
    const float inv0 = 1.f / l0;
    const float inv1 = 1.f / l1;
    const int b = bh >> 3;
    const int h = bh & 7;
    const int row0 = rowbase + warp * 16 + qr;
    const int row1 = row0 + 8;
#pragma unroll
    for (int j = 0; j < 8; j++) {
        const int col = h * DH + 8 * j + 2 * qc;
        uint32_t hh, ll;
        const size_t o0 = ((size_t)b * S_LEN + row0) * EMB + col;
        split2(O[j][0] * inv0, O[j][1] * inv0, hh, ll);
        *(uint32_t*)&g_atth[o0] = hh;
        *(uint32_t*)&g_attl[o0] = ll;
        const size_t o1 = ((size_t)b * S_LEN + row1) * EMB + col;
        split2(O[j][2] * inv1, O[j][3] * inv1, hh, ll);
        *(uint32_t*)&g_atth[o1] = hh;
        *(uint32_t*)&g_attl[o1] = ll;
    }
}

// ---------------------------------------------------------------------------
extern "C" void kernel_launch(void* const* d_in, const int* in_sizes, int n_in,
                              void* d_out, int out_size)
{
    const float* x    = (const float*)d_in[0];
    const float* Wqkv = (const float*)d_in[1];
    const float* bqkv = (const float*)d_in[2];
    const float* Wo   = (const float*)d_in[3];
    const float* bo   = (const float*)d_in[4];
    for (int i = 0; i < n_in; i++) {
        switch (in_sizes[i]) {
            case 8388608: x    = (const float*)d_in[i]; break;
            case 786432:  Wqkv = (const float*)d_in[i]; break;
            case 1536:    bqkv = (const float*)d_in[i]; break;
            case 262144:  Wo   = (const float*)d_in[i]; break;
            case 512:     bo   = (const float*)d_in[i]; break;
        }
    }
    float* out = (float*)d_out;

    static bool init = false;
    static __nv_bfloat16 *p_xh, *p_xl, *p_Wqh, *p_Wql, *p_Woh, *p_Wol,
                         *p_ath, *p_atl;
    if (!init) {
        void* t;
        cudaGetSymbolAddress(&t, g_xh);    p_xh  = (__nv_bfloat16*)t;
        cudaGetSymbolAddress(&t, g_xl);    p_xl  = (__nv_bfloat16*)t;
        cudaGetSymbolAddress(&t, g_Wqkvh); p_Wqh = (__nv_bfloat16*)t;
        cudaGetSymbolAddress(&t, g_Wqkvl); p_Wql = (__nv_bfloat16*)t;
        cudaGetSymbolAddress(&t, g_Woh);   p_Woh = (__nv_bfloat16*)t;
        cudaGetSymbolAddress(&t, g_Wol);   p_Wol = (__nv_bfloat16*)t;
        cudaGetSymbolAddress(&t, g_atth);  p_ath = (__nv_bfloat16*)t;
        cudaGetSymbolAddress(&t, g_attl);  p_atl = (__nv_bfloat16*)t;
        cudaFuncSetAttribute(attn_mma_kernel,
                             cudaFuncAttributeMaxDynamicSharedMemorySize,
                             ATTN_SMEM);
        cudaFuncSetAttribute(gemm_bf3_kernel,
                             cudaFuncAttributeMaxDynamicSharedMemorySize,
                             GSMEM);
        init = true;
    }

    // 0) split inputs to bf16 hi/lo
    split_kernel<<<(M_ROWS * EMB / 2 + 255) / 256, 256>>>(x, p_xh, p_xl,
                                                          M_ROWS * EMB / 2);
    split_kernel<<<(EMB * N_QKV / 2 + 255) / 256, 256>>>(Wqkv, p_Wqh, p_Wql,
                                                         EMB * N_QKV / 2);
    split_kernel<<<(EMB * EMB / 2 + 255) / 256, 256>>>(Wo, p_Woh, p_Wol,
                                                       EMB * EMB / 2);

    // 1) QKV projection (tensor core) + fused split/scatter
    gemm_bf3_kernel<<<dim3(N_QKV / 128, M_ROWS / 128), 256, GSMEM>>>(
        p_xh, p_xl, p_Wqh, p_Wql, bqkv, nullptr, N_QKV, EMB, 1);

    // 2) Tensor-core causal flash attention -> g_atth/g_attl
    attn_mma_kernel<<<dim3(S_LEN / 128, BATCH * NH), 256, ATTN_SMEM>>>();

    // 3) Output projection (tensor core)
    gemm_bf3_kernel<<<dim3(EMB / 128, M_ROWS / 128), 256, GSMEM>>>(
        p_ath, p_atl, p_Woh, p_Wol, bo, out, EMB, EMB, 0);
}

// round 9
// speedup vs baseline: 7.3583x; 1.0075x over previous
#include <cuda_runtime.h>
#include <cuda_bf16.h>
#include <math.h>
#include <stdint.h>

#define S_LEN 4096
#define EMB   512
#define NH    8
#define DH    64
#define BATCH 4
#define M_ROWS (BATCH * S_LEN)          // 16384
#define N_QKV  (3 * EMB)                // 1536
#define KSTR   72                        // attn smem stride (64 + 8 pad)
#define TILE_E (64 * KSTR)
#define ATTN_SMEM (2 * 4 * TILE_E * 2)   // 73728

// out-proj (R7) GEMM smem
#define ASTR 40
#define BSTR 136
#define GBUF 18944
#define GSMEM (2 * GBUF * 2)             // 75776

// QKV blocked GEMM smem: mbars @0, tiles @1024, 2 stages x 32KB
#define QK_SMEM (1024 + 2 * 32768)       // 66560

// Scratch (allocation-free: __device__ globals)
// x and Wqkv pre-split into BLOCK-MAJOR swizzled 8KB tiles
__device__ __align__(16) __nv_bfloat16 g_xhB[(size_t)M_ROWS * EMB];
__device__ __align__(16) __nv_bfloat16 g_xlB[(size_t)M_ROWS * EMB];
__device__ __align__(16) __nv_bfloat16 g_WqhB[(size_t)EMB * N_QKV];
__device__ __align__(16) __nv_bfloat16 g_WqlB[(size_t)EMB * N_QKV];
// Wo flat hi/lo (out-proj keeps R7 path)
__device__ __align__(16) __nv_bfloat16 g_Woh[(size_t)EMB * EMB];
__device__ __align__(16) __nv_bfloat16 g_Wol[(size_t)EMB * EMB];
// Q pre-scaled by 0.125; all [B,H,S,Dh]
__device__ __align__(16) __nv_bfloat16 g_Qh[(size_t)BATCH * NH * S_LEN * DH];
__device__ __align__(16) __nv_bfloat16 g_Ql[(size_t)BATCH * NH * S_LEN * DH];
__device__ __align__(16) __nv_bfloat16 g_Kh[(size_t)BATCH * NH * S_LEN * DH];
__device__ __align__(16) __nv_bfloat16 g_Kl[(size_t)BATCH * NH * S_LEN * DH];
__device__ __align__(16) __nv_bfloat16 g_Vh[(size_t)BATCH * NH * S_LEN * DH];
__device__ __align__(16) __nv_bfloat16 g_Vl[(size_t)BATCH * NH * S_LEN * DH];
// attention output split [B,S,E]
__device__ __align__(16) __nv_bfloat16 g_atth[(size_t)M_ROWS * EMB];
__device__ __align__(16) __nv_bfloat16 g_attl[(size_t)M_ROWS * EMB];

__device__ __forceinline__ void split2(float x, float y, uint32_t& h, uint32_t& l)
{
    __nv_bfloat16 hx = __float2bfloat16(x);
    __nv_bfloat16 hy = __float2bfloat16(y);
    __nv_bfloat162 hh; hh.x = hx; hh.y = hy;
    __nv_bfloat162 ll;
    ll.x = __float2bfloat16(x - __bfloat162float(hx));
    ll.y = __float2bfloat16(y - __bfloat162float(hy));
    h = *(uint32_t*)&hh;
    l = *(uint32_t*)&ll;
}

__device__ __forceinline__ void mma16816(float c[4], const uint32_t a[4],
                                         const uint32_t* b)
{
    asm volatile(
        "mma.sync.aligned.m16n8k16.row.col.f32.bf16.bf16.f32 "
        "{%0,%1,%2,%3}, {%4,%5,%6,%7}, {%8,%9}, {%0,%1,%2,%3};\n"
        : "+f"(c[0]), "+f"(c[1]), "+f"(c[2]), "+f"(c[3])
        : "r"(a[0]), "r"(a[1]), "r"(a[2]), "r"(a[3]), "r"(b[0]), "r"(b[1]));
}

__device__ __forceinline__ void ldsm4(uint32_t r[4], uint32_t addr)
{
    asm volatile("ldmatrix.sync.aligned.m8n8.x4.shared.b16 {%0,%1,%2,%3}, [%4];\n"
                 : "=r"(r[0]), "=r"(r[1]), "=r"(r[2]), "=r"(r[3]) : "r"(addr));
}

__device__ __forceinline__ void ldsm4t(uint32_t r[4], uint32_t addr)
{
    asm volatile("ldmatrix.sync.aligned.m8n8.x4.trans.shared.b16 {%0,%1,%2,%3}, [%4];\n"
                 : "=r"(r[0]), "=r"(r[1]), "=r"(r[2]), "=r"(r[3]) : "r"(addr));
}

__device__ __forceinline__ void cpasync16(uint32_t s, const void* g)
{
    asm volatile("cp.async.cg.shared.global [%0], [%1], 16;\n" :: "r"(s), "l"(g));
}

// ---- bulk copy + mbarrier helpers (sm_90 PTX, no 'a' features) ----
__device__ __forceinline__ void bulk_g2s(uint32_t dst, const void* src,
                                         uint32_t bytes, uint32_t mbar)
{
    asm volatile(
        "cp.async.bulk.shared::cta.global.mbarrier::complete_tx::bytes "
        "[%0], [%1], %2, [%3];\n"
        :: "r"(dst), "l"(src), "r"(bytes), "r"(mbar) : "memory");
}

__device__ __forceinline__ void mbar_init(uint32_t mbar, uint32_t cnt)
{
    asm volatile("mbarrier.init.shared.b64 [%0], %1;" :: "r"(mbar), "r"(cnt) : "memory");
}

__device__ __forceinline__ void mbar_expect_tx(uint32_t mbar, uint32_t bytes)
{
    asm volatile("mbarrier.arrive.expect_tx.shared.b64 _, [%0], %1;"
                 :: "r"(mbar), "r"(bytes) : "memory");
}

__device__ __forceinline__ void mbar_wait(uint32_t mbar, uint32_t parity)
{
    uint32_t done;
    asm volatile(
        "{\n\t.reg .pred p;\n\t"
        "mbarrier.try_wait.parity.acquire.cta.shared::cta.b64 p, [%1], %2;\n\t"
        "selp.b32 %0, 1, 0, p;\n\t}"
        : "=r"(done) : "r"(mbar), "r"(parity) : "memory");
    if (!done) {
        asm volatile(
            "{\n\t.reg .pred P1;\n\t"
            "WL_%=:\n\t"
            "mbarrier.try_wait.parity.acquire.cta.shared::cta.b64 P1, [%0], %1, 0x989680;\n\t"
            "@P1 bra.uni WD_%=;\n\t"
            "bra.uni WL_%=;\n\t"
            "WD_%=:\n\t}"
            :: "r"(mbar), "r"(parity) : "memory");
    }
}

__device__ __forceinline__ uint32_t smem_u32(const void* p)
{
    uint32_t a;
    asm("{ .reg .u64 t; cvta.to.shared.u64 t, %1; cvt.u32.u64 %0, t; }"
        : "=r"(a) : "l"(p));
    return a;
}

// ---------------------------------------------------------------------------
// Flat split (used for Wo)
// ---------------------------------------------------------------------------
__global__ __launch_bounds__(256) void split_kernel(
    const float* __restrict__ src, __nv_bfloat16* __restrict__ h,
    __nv_bfloat16* __restrict__ l, int n2)
{
    const int idx = blockIdx.x * 256 + threadIdx.x;
    if (idx >= n2) return;
    const float2 v = ((const float2*)src)[idx];
    uint32_t hh, ll;
    split2(v.x, v.y, hh, ll);
    ((uint32_t*)h)[idx] = hh;
    ((uint32_t*)l)[idx] = ll;
}

// ---------------------------------------------------------------------------
// Blocked splits: one thread per 16B output unit (8 elements)
// A (x): block(by,kc) 8KB: elem (r 0..127, c 0..31). unit u=c>>3 (0..3)
//   swizzled u' = (u + (r>>1)) & 3 ; offset halves = r*32 + u'*8
// ---------------------------------------------------------------------------
__global__ __launch_bounds__(256) void splitA_blk_kernel(const float* __restrict__ x)
{
    const int idx = blockIdx.x * 256 + threadIdx.x;      // 0 .. 1048575
    const int row = idx >> 6;                             // 0..16383
    const int cu = idx & 63;                              // unit in row (8 elems)
    const int kc = cu >> 2;
    const int u = cu & 3;
    const int by = row >> 7;
    const int r = row & 127;
    const int up = (u + (r >> 1)) & 3;
    const size_t off = (size_t)(by * 16 + kc) * 4096 + r * 32 + up * 8; // halves

    const float4 a0 = *(const float4*)(x + (size_t)row * 512 + cu * 8);
    const float4 a1 = *(const float4*)(x + (size_t)row * 512 + cu * 8 + 4);
    uint4 H, L;
    split2(a0.x, a0.y, H.x, L.x);
    split2(a0.z, a0.w, H.y, L.y);
    split2(a1.x, a1.y, H.z, L.z);
    split2(a1.z, a1.w, H.w, L.w);
    *(uint4*)(g_xhB + off) = H;
    *(uint4*)(g_xlB + off) = L;
}

// B (Wqkv): block(bx,kc) 8KB: elem (r 0..31 k, c 0..127 n). unit u=c>>3 (0..15)
//   swizzled u' = (u&8) | ((u&7)^(r&7)) ; offset halves = r*128 + u'*8
__global__ __launch_bounds__(256) void splitB_blk_kernel(const float* __restrict__ W)
{
    const int idx = blockIdx.x * 256 + threadIdx.x;      // 0 .. 98303
    const int k = idx / 192;                              // 0..511
    const int cu = idx - k * 192;                         // 0..191
    const int bx = cu >> 4;
    const int u = cu & 15;
    const int kc = k >> 5;
    const int r = k & 31;
    const int up = (u & 8) | ((u & 7) ^ (r & 7));
    const size_t off = (size_t)(bx * 16 + kc) * 4096 + r * 128 + up * 8;

    const float4 a0 = *(const float4*)(W + (size_t)k * N_QKV + cu * 8);
    const float4 a1 = *(const float4*)(W + (size_t)k * N_QKV + cu * 8 + 4);
    uint4 H, L;
    split2(a0.x, a0.y, H.x, L.x);
    split2(a0.z, a0.w, H.y, L.y);
    split2(a1.x, a1.y, H.z, L.z);
    split2(a1.z, a1.w, H.w, L.w);
    *(uint4*)(g_WqhB + off) = H;
    *(uint4*)(g_WqlB + off) = L;
}

// ---------------------------------------------------------------------------
// QKV GEMM with cp.async.bulk fill: C = x @ Wqkv + bqkv, split/scatter epi.
// 128x128 tile, k-chunk 32, 2-stage bulk pipeline, 256 threads.
// ---------------------------------------------------------------------------
__global__ __launch_bounds__(256) void gemm_qkv_blk_kernel(
    const float* __restrict__ bias)
{
    extern __shared__ __align__(1024) char sq[];
    const uint32_t sb = smem_u32(sq);
    const int tid = threadIdx.x;
    const int bx = blockIdx.x, by = blockIdx.y;
    const int lane = tid & 31, warp = tid >> 5;
    const int wm = warp & 3, wn = warp >> 2;    // warp tile m32 x n64
    const int qr = lane >> 2, qc = lane & 3;
    const int g = lane >> 3, rr = lane & 7;

    float acc[2][8][4];
#pragma unroll
    for (int i = 0; i < 2; i++)
#pragma unroll
        for (int j = 0; j < 8; j++)
#pragma unroll
            for (int e = 0; e < 4; e++) acc[i][j][e] = 0.f;

    if (tid == 0) { mbar_init(sb, 1); mbar_init(sb + 16, 1); }
    __syncthreads();

    auto fill = [&](int kc) {
        const int buf = kc & 1;
        const uint32_t mb = sb + buf * 16;
        const uint32_t dst = sb + 1024 + buf * 32768;
        mbar_expect_tx(mb, 32768);
        bulk_g2s(dst,         g_xhB + (size_t)(by * 16 + kc) * 4096, 8192, mb);
        bulk_g2s(dst + 8192,  g_xlB + (size_t)(by * 16 + kc) * 4096, 8192, mb);
        bulk_g2s(dst + 16384, g_WqhB + (size_t)(bx * 16 + kc) * 4096, 8192, mb);
        bulk_g2s(dst + 24576, g_WqlB + (size_t)(bx * 16 + kc) * 4096, 8192, mb);
    };

    if (tid == 0) fill(0);

    for (int kc = 0; kc < 16; kc++) {
        if (kc + 1 < 16 && tid == 0) fill(kc + 1);
        mbar_wait(sb + (kc & 1) * 16, (kc >> 1) & 1);

        const uint32_t base = sb + 1024 + (kc & 1) * 32768;
        const uint32_t Ah_s = base;
        const uint32_t Al_s = base + 8192;
        const uint32_t Bh_s = base + 16384;
        const uint32_t Bl_s = base + 24576;

#pragma unroll
        for (int s = 0; s < 2; s++) {
            uint32_t afh[2][4], afl[2][4];
#pragma unroll
            for (int i = 0; i < 2; i++) {
                const int ar = wm * 32 + i * 16 + (lane & 15);
                const int au = s * 2 + (lane >> 4);
                const int aup = (au + (ar >> 1)) & 3;
                const uint32_t off = ar * 64 + aup * 16;
                ldsm4(afh[i], Ah_s + off);
                ldsm4(afl[i], Al_s + off);
            }
#pragma unroll
            for (int jp = 0; jp < 4; jp++) {
                const int br = s * 16 + 8 * (g & 1) + rr;
                const int bu = wn * 8 + jp * 2 + (g >> 1);
                const int bup = (bu & 8) | ((bu & 7) ^ (br & 7));
                const uint32_t off = br * 256 + bup * 16;
                uint32_t bh4[4], bl4[4];
                ldsm4t(bh4, Bh_s + off);
                ldsm4t(bl4, Bl_s + off);
#pragma unroll
                for (int i = 0; i < 2; i++) {
                    mma16816(acc[i][2 * jp],     afh[i], &bh4[0]);
                    mma16816(acc[i][2 * jp],     afh[i], &bl4[0]);
                    mma16816(acc[i][2 * jp],     afl[i], &bh4[0]);
                    mma16816(acc[i][2 * jp + 1], afh[i], &bh4[2]);
                    mma16816(acc[i][2 * jp + 1], afh[i], &bl4[2]);
                    mma16816(acc[i][2 * jp + 1], afl[i], &bh4[2]);
                }
            }
        }
        __syncthreads();
    }

    // QKV epilogue: bias + (Q scale) + split + scatter to [B,H,S,Dh]
#pragma unroll
    for (int i = 0; i < 2; i++) {
        const int row0 = by * 128 + wm * 32 + i * 16 + qr;
        const int b = row0 >> 12;
        const int s0 = row0 & 4095;
#pragma unroll
        for (int j = 0; j < 8; j++) {
            const int col = bx * 128 + wn * 64 + j * 8 + 2 * qc;
            float v0 = acc[i][j][0] + bias[col];
            float v1 = acc[i][j][1] + bias[col + 1];
            float v2 = acc[i][j][2] + bias[col];
            float v3 = acc[i][j][3] + bias[col + 1];
            const int which = col >> 9;
            const int e = col & 511;
            const int h = e >> 6;
            const int d = e & 63;
            if (which == 0) { v0 *= 0.125f; v1 *= 0.125f;
                              v2 *= 0.125f; v3 *= 0.125f; }
            __nv_bfloat16* ph = (which == 0) ? g_Qh : (which == 1) ? g_Kh : g_Vh;
            __nv_bfloat16* pl = (which == 0) ? g_Ql : (which == 1) ? g_Kl : g_Vl;
            uint32_t hh, ll;
            const size_t dst0 = (((size_t)(b * NH + h) * S_LEN) + s0) * DH + d;
            split2(v0, v1, hh, ll);
            *(uint32_t*)&ph[dst0] = hh;
            *(uint32_t*)&pl[dst0] = ll;
            const size_t dst1 = dst0 + (size_t)8 * DH;
            split2(v2, v3, hh, ll);
            *(uint32_t*)&ph[dst1] = hh;
            *(uint32_t*)&pl[dst1] = ll;
        }
    }
}

// ---------------------------------------------------------------------------
// Out-projection GEMM (unchanged from passing R7, mode-0 only)
// ---------------------------------------------------------------------------
__global__ __launch_bounds__(256) void gemm_bf3_kernel(
    const __nv_bfloat16* __restrict__ Ah, const __nv_bfloat16* __restrict__ Al,
    const __nv_bfloat16* __restrict__ Bh, const __nv_bfloat16* __restrict__ Bl,
    const float* __restrict__ bias, float* __restrict__ C,
    int N, int K)
{
    extern __shared__ __align__(16) __nv_bfloat16 sg[];
    const int tid  = threadIdx.x;
    const int bx = blockIdx.x, by = blockIdx.y;
    const int lane = tid & 31, warp = tid >> 5;
    const int wm = warp & 3, wn = warp >> 2;
    const int qr = lane >> 2, qc = lane & 3;
    const int g = lane >> 3, rr = lane & 7;
    const uint32_t sb = (uint32_t)__cvta_generic_to_shared(sg);

    float acc[2][8][4];
#pragma unroll
    for (int i = 0; i < 2; i++)
#pragma unroll
        for (int j = 0; j < 8; j++)
#pragma unroll
            for (int e = 0; e < 4; e++) acc[i][j][e] = 0.f;

    auto fill = [&](int kc, int buf) {
        const int k0 = kc * 32;
        const uint32_t base = sb + buf * GBUF * 2;
#pragma unroll
        for (int t = 0; t < 4; t++) {
            const int idx = t * 256 + tid;
            const int arr = idx >> 9;
            const int rem = idx & 511;
            const int row = rem >> 2, c = rem & 3;
            const __nv_bfloat16* src =
                (arr ? Al : Ah) + (size_t)(by * 128 + row) * K + k0 + c * 8;
            cpasync16(base + (arr * 5120 + row * ASTR + c * 8) * 2, src);
        }
#pragma unroll
        for (int t = 0; t < 4; t++) {
            const int idx = t * 256 + tid;
            const int arr = idx >> 9;
            const int rem = idx & 511;
            const int row = rem >> 4, c = rem & 15;
            const __nv_bfloat16* src =
                (arr ? Bl : Bh) + (size_t)(k0 + row) * N + bx * 128 + c * 8;
            cpasync16(base + (10240 + arr * 4352 + row * BSTR + c * 8) * 2, src);
        }
        asm volatile("cp.async.commit_group;\n");
    };

    fill(0, 0);
    const int nkc = K / 32;

    for (int kc = 0; kc < nkc; kc++) {
        const int buf = kc & 1;
        asm volatile("cp.async.wait_group 0;\n");
        __syncthreads();
        if (kc + 1 < nkc) fill(kc + 1, buf ^ 1);

        const uint32_t base = sb + buf * GBUF * 2;
        const uint32_t Ah_s = base;
        const uint32_t Al_s = base + 5120 * 2;
        const uint32_t Bh_s = base + 10240 * 2;
        const uint32_t Bl_s = base + 14592 * 2;

#pragma unroll
        for (int s = 0; s < 2; s++) {
            uint32_t afh[2][4], afl[2][4];
#pragma unroll
            for (int i = 0; i < 2; i++) {
                const uint32_t off =
                    ((wm * 32 + i * 16 + (lane & 15)) * ASTR
                     + s * 16 + 8 * (lane >> 4)) * 2;
                ldsm4(afh[i], Ah_s + off);
                ldsm4(afl[i], Al_s + off);
            }
#pragma unroll
            for (int jp = 0; jp < 4; jp++) {
                const uint32_t off =
                    ((s * 16 + 8 * (g & 1) + rr) * BSTR
                     + wn * 64 + jp * 16 + 8 * (g >> 1)) * 2;
                uint32_t bh4[4], bl4[4];
                ldsm4t(bh4, Bh_s + off);
                ldsm4t(bl4, Bl_s + off);
#pragma unroll
                for (int i = 0; i < 2; i++) {
                    mma16816(acc[i][2 * jp],     afh[i], &bh4[0]);
                    mma16816(acc[i][2 * jp],     afh[i], &bl4[0]);
                    mma16816(acc[i][2 * jp],     afl[i], &bh4[0]);
                    mma16816(acc[i][2 * jp + 1], afh[i], &bh4[2]);
                    mma16816(acc[i][2 * jp + 1], afh[i], &bl4[2]);
                    mma16816(acc[i][2 * jp + 1], afl[i], &bh4[2]);
                }
            }
        }
        __syncthreads();
    }

#pragma unroll
    for (int i = 0; i < 2; i++) {
        const int row0 = by * 128 + wm * 32 + i * 16 + qr;
#pragma unroll
        for (int j = 0; j < 8; j++) {
            const int col = bx * 128 + wn * 64 + j * 8 + 2 * qc;
            float2 v0 = make_float2(acc[i][j][0] + bias[col],
                                    acc[i][j][1] + bias[col + 1]);
            float2 v1 = make_float2(acc[i][j][2] + bias[col],
                                    acc[i][j][3] + bias[col + 1]);
            *(float2*)(C + (size_t)row0 * N + col) = v0;
            *(float2*)(C + (size_t)(row0 + 8) * N + col) = v1;
        }
    }
}

// ---------------------------------------------------------------------------
// Tensor-core flash attention (unchanged from passing R7)
// ---------------------------------------------------------------------------
__global__ __launch_bounds__(256) void attn_mma_kernel()
{
    extern __shared__ __align__(16) __nv_bfloat16 sm[];

    const int tid  = threadIdx.x;
    const int warp = tid >> 5;
    const int lane = tid & 31;
    const int qt = blockIdx.x;
    const int bh = blockIdx.y;
    const int rowbase = qt * 128;
    const int qr = lane >> 2;
    const int qc = lane & 3;
    const int g  = lane >> 3;
    const int rr = lane & 7;

    const uint32_t smem_base = (uint32_t)__cvta_generic_to_shared(sm);

    const __nv_bfloat16* srcs[4] = {
        g_Kh + (size_t)bh * S_LEN * DH,
        g_Kl + (size_t)bh * S_LEN * DH,
        g_Vh + (size_t)bh * S_LEN * DH,
        g_Vl + (size_t)bh * S_LEN * DH };

    uint32_t Qah[4][4], Qal[4][4];
    {
        const size_t qoff = ((size_t)bh * S_LEN + rowbase + warp * 16) * DH;
#pragma unroll
        for (int s = 0; s < 4; s++)
#pragma unroll
            for (int e = 0; e < 4; e++) {
                const int r = qr + 8 * (e & 1);
                const int c = 16 * s + 2 * qc + 8 * (e >> 1);
                Qah[s][e] = *(const uint32_t*)(g_Qh + qoff + (size_t)r * DH + c);
                Qal[s][e] = *(const uint32_t*)(g_Ql + qoff + (size_t)r * DH + c);
            }
    }

    float O[8][4];
#pragma unroll
    for (int j = 0; j < 8; j++)
#pragma unroll
        for (int e = 0; e < 4; e++) O[j][e] = 0.f;
    float m0 = -1e30f, m1 = -1e30f, l0 = 0.f, l1 = 0.f;

    const int nT = qt * 2 + 2;

    auto fill = [&](int kt, int buf) {
#pragma unroll
        for (int i = 0; i < 8; i++) {
            const int arr = i >> 1;
            const int e = ((i & 1) << 8) + tid;
            const int row = e >> 3;
            const int grp = e & 7;
            const __nv_bfloat16* src = srcs[arr] + (size_t)kt * 64 * DH
                                     + (size_t)row * DH + grp * 8;
            const uint32_t dst = smem_base +
                ((arr * 2 + buf) * TILE_E + row * KSTR + grp * 8) * 2;
            cpasync16(dst, src);
        }
        asm volatile("cp.async.commit_group;\n");
    };

    fill(0, 0);

    for (int kt = 0; kt < nT; kt++) {
        const int buf = kt & 1;
        asm volatile("cp.async.wait_group 0;\n");
        __syncthreads();
        if (kt + 1 < nT) fill(kt + 1, buf ^ 1);

        const uint32_t Kh_t = smem_base + ((0 * 2 + buf) * TILE_E) * 2;
        const uint32_t Kl_t = smem_base + ((1 * 2 + buf) * TILE_E) * 2;
        const uint32_t Vh_t = smem_base + ((2 * 2 + buf) * TILE_E) * 2;
        const uint32_t Vl_t = smem_base + ((3 * 2 + buf) * TILE_E) * 2;

        float S[8][4];
#pragma unroll
        for (int j = 0; j < 8; j++)
#pragma unroll
            for (int e = 0; e < 4; e++) S[j][e] = 0.f;

#pragma unroll
        for (int s = 0; s < 4; s++) {
#pragma unroll
            for (int jp = 0; jp < 4; jp++) {
                const uint32_t off = ((16 * jp + 8 * (g >> 1) + rr) * KSTR
                                    + 16 * s + 8 * (g & 1)) * 2;
                uint32_t bhv[4], blv[4];
                ldsm4(bhv, Kh_t + off);
                ldsm4(blv, Kl_t + off);
                mma16816(S[2 * jp],     Qah[s], &bhv[0]);
                mma16816(S[2 * jp],     Qah[s], &blv[0]);
                mma16816(S[2 * jp],     Qal[s], &bhv[0]);
                mma16816(S[2 * jp + 1], Qah[s], &bhv[2]);
                mma16816(S[2 * jp + 1], Qah[s], &blv[2]);
                mma16816(S[2 * jp + 1], Qal[s], &bhv[2]);
            }
        }

        const int grow0 = rowbase + warp * 16 + qr;
        if (kt * 64 + 63 > rowbase + warp * 16) {
#pragma unroll
            for (int j = 0; j < 8; j++)
#pragma unroll
                for (int e = 0; e < 4; e++) {
                    const int col = kt * 64 + 8 * j + 2 * qc + (e & 1);
                    const int row = grow0 + 8 * (e >> 1);
                    if (col > row) S[j][e] = -1e30f;
                }
        }

        float mx0 = -1e30f, mx1 = -1e30f;
#pragma unroll
        for (int j = 0; j < 8; j++) {
            mx0 = fmaxf(mx0, fmaxf(S[j][0], S[j][1]));
            mx1 = fmaxf(mx1, fmaxf(S[j][2], S[j][3]));
        }
        mx0 = fmaxf(mx0, __shfl_xor_sync(0xffffffffu, mx0, 1));
        mx0 = fmaxf(mx0, __shfl_xor_sync(0xffffffffu, mx0, 2));
        mx1 = fmaxf(mx1, __shfl_xor_sync(0xffffffffu, mx1, 1));
        mx1 = fmaxf(mx1, __shfl_xor_sync(0xffffffffu, mx1, 2));

        const float nm0 = fmaxf(m0, mx0);
        const float nm1 = fmaxf(m1, mx1);
        const float c0 = __expf(m0 - nm0);
        const float c1 = __expf(m1 - nm1);
        m0 = nm0; m1 = nm1;

        float s0 = 0.f, s1 = 0.f;
#pragma unroll
        for (int j = 0; j < 8; j++) {
            S[j][0] = __expf(S[j][0] - m0); s0 += S[j][0];
            S[j][1] = __expf(S[j][1] - m0); s0 += S[j][1];
            S[j][2] = __expf(S[j][2] - m1); s1 += S[j][2];
            S[j][3] = __expf(S[j][3] - m1); s1 += S[j][3];
        }
        s0 += __shfl_xor_sync(0xffffffffu, s0, 1);
        s0 += __shfl_xor_sync(0xffffffffu, s0, 2);
        s1 += __shfl_xor_sync(0xffffffffu, s1, 1);
        s1 += __shfl_xor_sync(0xffffffffu, s1, 2);
        l0 = l0 * c0 + s0;
        l1 = l1 * c1 + s1;
#pragma unroll
        for (int j = 0; j < 8; j++) {
            O[j][0] *= c0; O[j][1] *= c0;
            O[j][2] *= c1; O[j][3] *= c1;
        }

#pragma unroll
        for (int s = 0; s < 4; s++) {
            uint32_t Pah[4], Pal[4];
            split2(S[2 * s][0],     S[2 * s][1],     Pah[0], Pal[0]);
            split2(S[2 * s][2],     S[2 * s][3],     Pah[1], Pal[1]);
            split2(S[2 * s + 1][0], S[2 * s + 1][1], Pah[2], Pal[2]);
            split2(S[2 * s + 1][2], S[2 * s + 1][3], Pah[3], Pal[3]);
#pragma unroll
            for (int jp = 0; jp < 4; jp++) {
                const uint32_t off = ((16 * s + 8 * (g & 1) + rr) * KSTR
                                    + 16 * jp + 8 * (g >> 1)) * 2;
                uint32_t bhv[4], blv[4];
                ldsm4t(bhv, Vh_t + off);
                ldsm4t(blv, Vl_t + off);
                mma16816(O[2 * jp],     Pah, &bhv[0]);
                mma16816(O[2 * jp],     Pah, &blv[0]);
                mma16816(O[2 * jp],     Pal, &bhv[0]);
                mma16816(O[2 * jp + 1], Pah, &bhv[2]);
                mma16816(O[2 * jp + 1], Pah, &blv[2]);
                mma16816(O[2 * jp + 1], Pal, &bhv[2]);
            }
        }
        __syncthreads();
    }

    const float inv0 = 1.f / l0;
    const float inv1 = 1.f / l1;
    const int b = bh >> 3;
    const int h = bh & 7;
    const int row0 = rowbase + warp * 16 + qr;
    const int row1 = row0 + 8;
#pragma unroll
    for (int j = 0; j < 8; j++) {
        const int col = h * DH + 8 * j + 2 * qc;
        uint32_t hh, ll;
        const size_t o0 = ((size_t)b * S_LEN + row0) * EMB + col;
        split2(O[j][0] * inv0, O[j][1] * inv0, hh, ll);
        *(uint32_t*)&g_atth[o0] = hh;
        *(uint32_t*)&g_attl[o0] = ll;
        const size_t o1 = ((size_t)b * S_LEN + row1) * EMB + col;
        split2(O[j][2] * inv1, O[j][3] * inv1, hh, ll);
        *(uint32_t*)&g_atth[o1] = hh;
        *(uint32_t*)&g_attl[o1] = ll;
    }
}

// ---------------------------------------------------------------------------
extern "C" void kernel_launch(void* const* d_in, const int* in_sizes, int n_in,
                              void* d_out, int out_size)
{
    const float* x    = (const float*)d_in[0];
    const float* Wqkv = (const float*)d_in[1];
    const float* bqkv = (const float*)d_in[2];
    const float* Wo   = (const float*)d_in[3];
    const float* bo   = (const float*)d_in[4];
    for (int i = 0; i < n_in; i++) {
        switch (in_sizes[i]) {
            case 8388608: x    = (const float*)d_in[i]; break;
            case 786432:  Wqkv = (const float*)d_in[i]; break;
            case 1536:    bqkv = (const float*)d_in[i]; break;
            case 262144:  Wo   = (const float*)d_in[i]; break;
            case 512:     bo   = (const float*)d_in[i]; break;
        }
    }
    float* out = (float*)d_out;

    static bool init = false;
    static __nv_bfloat16 *p_Woh, *p_Wol, *p_ath, *p_atl;
    if (!init) {
        void* t;
        cudaGetSymbolAddress(&t, g_Woh);   p_Woh = (__nv_bfloat16*)t;
        cudaGetSymbolAddress(&t, g_Wol);   p_Wol = (__nv_bfloat16*)t;
        cudaGetSymbolAddress(&t, g_atth);  p_ath = (__nv_bfloat16*)t;
        cudaGetSymbolAddress(&t, g_attl);  p_atl = (__nv_bfloat16*)t;
        cudaFuncSetAttribute(attn_mma_kernel,
                             cudaFuncAttributeMaxDynamicSharedMemorySize,
                             ATTN_SMEM);
        cudaFuncSetAttribute(gemm_bf3_kernel,
                             cudaFuncAttributeMaxDynamicSharedMemorySize,
                             GSMEM);
        cudaFuncSetAttribute(gemm_qkv_blk_kernel,
                             cudaFuncAttributeMaxDynamicSharedMemorySize,
                             QK_SMEM);
        init = true;
    }

    // 0) splits: x, Wqkv -> blocked swizzled; Wo -> flat
    splitA_blk_kernel<<<M_ROWS * EMB / 8 / 256, 256>>>(x);
    splitB_blk_kernel<<<EMB * N_QKV / 8 / 256, 256>>>(Wqkv);
    split_kernel<<<(EMB * EMB / 2 + 255) / 256, 256>>>(Wo, p_Woh, p_Wol,
                                                       EMB * EMB / 2);

    // 1) QKV projection (bulk-fill mma.sync) + fused split/scatter
    gemm_qkv_blk_kernel<<<dim3(N_QKV / 128, M_ROWS / 128), 256, QK_SMEM>>>(bqkv);

    // 2) Tensor-core causal flash attention -> g_atth/g_attl
    attn_mma_kernel<<<dim3(S_LEN / 128, BATCH * NH), 256, ATTN_SMEM>>>();

    // 3) Output projection
    gemm_bf3_kernel<<<dim3(EMB / 128, M_ROWS / 128), 256, GSMEM>>>(
        p_ath, p_atl, p_Woh, p_Wol, bo, out, EMB, EMB);
}

// round 10
// speedup vs baseline: 7.3870x; 1.0039x over previous
#include <cuda_runtime.h>
#include <cuda_bf16.h>
#include <math.h>
#include <stdint.h>

#define S_LEN 4096
#define EMB   512
#define NH    8
#define DH    64
#define BATCH 4
#define M_ROWS (BATCH * S_LEN)          // 16384
#define N_QKV  (3 * EMB)                // 1536
#define KSTR   72                        // attn smem stride (64 + 8 pad)
#define TILE_E (64 * KSTR)
#define ATTN_SMEM (2 * 4 * TILE_E * 2)   // 73728

// out-proj GEMM smem
#define ASTR 40
#define BSTR 136
#define GBUF 18944
#define GSMEM (2 * GBUF * 2)             // 75776

// QKV blocked GEMM smem: mbars @0, tiles @1024, 2 stages x 32KB
#define QK_SMEM (1024 + 2 * 32768)       // 66560

// Scratch (allocation-free: __device__ globals)
__device__ __align__(16) __nv_bfloat16 g_xhB[(size_t)M_ROWS * EMB];
__device__ __align__(16) __nv_bfloat16 g_xlB[(size_t)M_ROWS * EMB];
__device__ __align__(16) __nv_bfloat16 g_WqhB[(size_t)EMB * N_QKV];
__device__ __align__(16) __nv_bfloat16 g_WqlB[(size_t)EMB * N_QKV];
__device__ __align__(16) __nv_bfloat16 g_Woh[(size_t)EMB * EMB];
__device__ __align__(16) __nv_bfloat16 g_Wol[(size_t)EMB * EMB];
__device__ __align__(16) __nv_bfloat16 g_Qh[(size_t)BATCH * NH * S_LEN * DH];
__device__ __align__(16) __nv_bfloat16 g_Ql[(size_t)BATCH * NH * S_LEN * DH];
__device__ __align__(16) __nv_bfloat16 g_Kh[(size_t)BATCH * NH * S_LEN * DH];
__device__ __align__(16) __nv_bfloat16 g_Kl[(size_t)BATCH * NH * S_LEN * DH];
__device__ __align__(16) __nv_bfloat16 g_Vh[(size_t)BATCH * NH * S_LEN * DH];
__device__ __align__(16) __nv_bfloat16 g_Vl[(size_t)BATCH * NH * S_LEN * DH];
__device__ __align__(16) __nv_bfloat16 g_atth[(size_t)M_ROWS * EMB];
__device__ __align__(16) __nv_bfloat16 g_attl[(size_t)M_ROWS * EMB];

__device__ __forceinline__ void split2(float x, float y, uint32_t& h, uint32_t& l)
{
    __nv_bfloat16 hx = __float2bfloat16(x);
    __nv_bfloat16 hy = __float2bfloat16(y);
    __nv_bfloat162 hh; hh.x = hx; hh.y = hy;
    __nv_bfloat162 ll;
    ll.x = __float2bfloat16(x - __bfloat162float(hx));
    ll.y = __float2bfloat16(y - __bfloat162float(hy));
    h = *(uint32_t*)&hh;
    l = *(uint32_t*)&ll;
}

__device__ __forceinline__ void mma16816(float c[4], const uint32_t a[4],
                                         const uint32_t* b)
{
    asm volatile(
        "mma.sync.aligned.m16n8k16.row.col.f32.bf16.bf16.f32 "
        "{%0,%1,%2,%3}, {%4,%5,%6,%7}, {%8,%9}, {%0,%1,%2,%3};\n"
        : "+f"(c[0]), "+f"(c[1]), "+f"(c[2]), "+f"(c[3])
        : "r"(a[0]), "r"(a[1]), "r"(a[2]), "r"(a[3]), "r"(b[0]), "r"(b[1]));
}

__device__ __forceinline__ void ldsm4(uint32_t r[4], uint32_t addr)
{
    asm volatile("ldmatrix.sync.aligned.m8n8.x4.shared.b16 {%0,%1,%2,%3}, [%4];\n"
                 : "=r"(r[0]), "=r"(r[1]), "=r"(r[2]), "=r"(r[3]) : "r"(addr));
}

__device__ __forceinline__ void ldsm4t(uint32_t r[4], uint32_t addr)
{
    asm volatile("ldmatrix.sync.aligned.m8n8.x4.trans.shared.b16 {%0,%1,%2,%3}, [%4];\n"
                 : "=r"(r[0]), "=r"(r[1]), "=r"(r[2]), "=r"(r[3]) : "r"(addr));
}

__device__ __forceinline__ void cpasync16(uint32_t s, const void* g)
{
    asm volatile("cp.async.cg.shared.global [%0], [%1], 16;\n" :: "r"(s), "l"(g));
}

// ---- bulk copy + mbarrier helpers ----
__device__ __forceinline__ void bulk_g2s(uint32_t dst, const void* src,
                                         uint32_t bytes, uint32_t mbar)
{
    asm volatile(
        "cp.async.bulk.shared::cta.global.mbarrier::complete_tx::bytes "
        "[%0], [%1], %2, [%3];\n"
        :: "r"(dst), "l"(src), "r"(bytes), "r"(mbar) : "memory");
}

__device__ __forceinline__ void mbar_init(uint32_t mbar, uint32_t cnt)
{
    asm volatile("mbarrier.init.shared.b64 [%0], %1;" :: "r"(mbar), "r"(cnt) : "memory");
}

__device__ __forceinline__ void mbar_expect_tx(uint32_t mbar, uint32_t bytes)
{
    asm volatile("mbarrier.arrive.expect_tx.shared.b64 _, [%0], %1;"
                 :: "r"(mbar), "r"(bytes) : "memory");
}

__device__ __forceinline__ void mbar_wait(uint32_t mbar, uint32_t parity)
{
    uint32_t done;
    asm volatile(
        "{\n\t.reg .pred p;\n\t"
        "mbarrier.try_wait.parity.acquire.cta.shared::cta.b64 p, [%1], %2;\n\t"
        "selp.b32 %0, 1, 0, p;\n\t}"
        : "=r"(done) : "r"(mbar), "r"(parity) : "memory");
    if (!done) {
        asm volatile(
            "{\n\t.reg .pred P1;\n\t"
            "WL_%=:\n\t"
            "mbarrier.try_wait.parity.acquire.cta.shared::cta.b64 P1, [%0], %1, 0x989680;\n\t"
            "@P1 bra.uni WD_%=;\n\t"
            "bra.uni WL_%=;\n\t"
            "WD_%=:\n\t}"
            :: "r"(mbar), "r"(parity) : "memory");
    }
}

__device__ __forceinline__ uint32_t smem_u32(const void* p)
{
    uint32_t a;
    asm("{ .reg .u64 t; cvta.to.shared.u64 t, %1; cvt.u32.u64 %0, t; }"
        : "=r"(a) : "l"(p));
    return a;
}

// ---------------------------------------------------------------------------
// Splits
// ---------------------------------------------------------------------------
__global__ __launch_bounds__(256) void split_kernel(
    const float* __restrict__ src, __nv_bfloat16* __restrict__ h,
    __nv_bfloat16* __restrict__ l, int n2)
{
    const int idx = blockIdx.x * 256 + threadIdx.x;
    if (idx >= n2) return;
    const float2 v = ((const float2*)src)[idx];
    uint32_t hh, ll;
    split2(v.x, v.y, hh, ll);
    ((uint32_t*)h)[idx] = hh;
    ((uint32_t*)l)[idx] = ll;
}

__global__ __launch_bounds__(256) void splitA_blk_kernel(const float* __restrict__ x)
{
    const int idx = blockIdx.x * 256 + threadIdx.x;
    const int row = idx >> 6;
    const int cu = idx & 63;
    const int kc = cu >> 2;
    const int u = cu & 3;
    const int by = row >> 7;
    const int r = row & 127;
    const int up = (u + (r >> 1)) & 3;
    const size_t off = (size_t)(by * 16 + kc) * 4096 + r * 32 + up * 8;

    const float4 a0 = *(const float4*)(x + (size_t)row * 512 + cu * 8);
    const float4 a1 = *(const float4*)(x + (size_t)row * 512 + cu * 8 + 4);
    uint4 H, L;
    split2(a0.x, a0.y, H.x, L.x);
    split2(a0.z, a0.w, H.y, L.y);
    split2(a1.x, a1.y, H.z, L.z);
    split2(a1.z, a1.w, H.w, L.w);
    *(uint4*)(g_xhB + off) = H;
    *(uint4*)(g_xlB + off) = L;
}

__global__ __launch_bounds__(256) void splitB_blk_kernel(const float* __restrict__ W)
{
    const int idx = blockIdx.x * 256 + threadIdx.x;
    const int k = idx / 192;
    const int cu = idx - k * 192;
    const int bx = cu >> 4;
    const int u = cu & 15;
    const int kc = k >> 5;
    const int r = k & 31;
    const int up = (u & 8) | ((u & 7) ^ (r & 7));
    const size_t off = (size_t)(bx * 16 + kc) * 4096 + r * 128 + up * 8;

    const float4 a0 = *(const float4*)(W + (size_t)k * N_QKV + cu * 8);
    const float4 a1 = *(const float4*)(W + (size_t)k * N_QKV + cu * 8 + 4);
    uint4 H, L;
    split2(a0.x, a0.y, H.x, L.x);
    split2(a0.z, a0.w, H.y, L.y);
    split2(a1.x, a1.y, H.z, L.z);
    split2(a1.z, a1.w, H.w, L.w);
    *(uint4*)(g_WqhB + off) = H;
    *(uint4*)(g_WqlB + off) = L;
}

// ---------------------------------------------------------------------------
// QKV GEMM with cp.async.bulk fill (now 2 CTAs/SM)
// ---------------------------------------------------------------------------
__global__ __launch_bounds__(256, 2) void gemm_qkv_blk_kernel(
    const float* __restrict__ bias)
{
    extern __shared__ __align__(1024) char sq[];
    const uint32_t sb = smem_u32(sq);
    const int tid = threadIdx.x;
    const int bx = blockIdx.x, by = blockIdx.y;
    const int lane = tid & 31, warp = tid >> 5;
    const int wm = warp & 3, wn = warp >> 2;
    const int qr = lane >> 2, qc = lane & 3;
    const int g = lane >> 3, rr = lane & 7;

    float acc[2][8][4];
#pragma unroll
    for (int i = 0; i < 2; i++)
#pragma unroll
        for (int j = 0; j < 8; j++)
#pragma unroll
            for (int e = 0; e < 4; e++) acc[i][j][e] = 0.f;

    if (tid == 0) { mbar_init(sb, 1); mbar_init(sb + 16, 1); }
    __syncthreads();

    auto fill = [&](int kc) {
        const int buf = kc & 1;
        const uint32_t mb = sb + buf * 16;
        const uint32_t dst = sb + 1024 + buf * 32768;
        mbar_expect_tx(mb, 32768);
        bulk_g2s(dst,         g_xhB + (size_t)(by * 16 + kc) * 4096, 8192, mb);
        bulk_g2s(dst + 8192,  g_xlB + (size_t)(by * 16 + kc) * 4096, 8192, mb);
        bulk_g2s(dst + 16384, g_WqhB + (size_t)(bx * 16 + kc) * 4096, 8192, mb);
        bulk_g2s(dst + 24576, g_WqlB + (size_t)(bx * 16 + kc) * 4096, 8192, mb);
    };

    if (tid == 0) fill(0);

    for (int kc = 0; kc < 16; kc++) {
        if (kc + 1 < 16 && tid == 0) fill(kc + 1);
        mbar_wait(sb + (kc & 1) * 16, (kc >> 1) & 1);

        const uint32_t base = sb + 1024 + (kc & 1) * 32768;
        const uint32_t Ah_s = base;
        const uint32_t Al_s = base + 8192;
        const uint32_t Bh_s = base + 16384;
        const uint32_t Bl_s = base + 24576;

#pragma unroll
        for (int s = 0; s < 2; s++) {
            uint32_t afh[2][4], afl[2][4];
#pragma unroll
            for (int i = 0; i < 2; i++) {
                const int ar = wm * 32 + i * 16 + (lane & 15);
                const int au = s * 2 + (lane >> 4);
                const int aup = (au + (ar >> 1)) & 3;
                const uint32_t off = ar * 64 + aup * 16;
                ldsm4(afh[i], Ah_s + off);
                ldsm4(afl[i], Al_s + off);
            }
#pragma unroll
            for (int jp = 0; jp < 4; jp++) {
                const int br = s * 16 + 8 * (g & 1) + rr;
                const int bu = wn * 8 + jp * 2 + (g >> 1);
                const int bup = (bu & 8) | ((bu & 7) ^ (br & 7));
                const uint32_t off = br * 256 + bup * 16;
                uint32_t bh4[4], bl4[4];
                ldsm4t(bh4, Bh_s + off);
                ldsm4t(bl4, Bl_s + off);
#pragma unroll
                for (int i = 0; i < 2; i++) {
                    mma16816(acc[i][2 * jp],     afh[i], &bh4[0]);
                    mma16816(acc[i][2 * jp],     afh[i], &bl4[0]);
                    mma16816(acc[i][2 * jp],     afl[i], &bh4[0]);
                    mma16816(acc[i][2 * jp + 1], afh[i], &bh4[2]);
                    mma16816(acc[i][2 * jp + 1], afh[i], &bl4[2]);
                    mma16816(acc[i][2 * jp + 1], afl[i], &bh4[2]);
                }
            }
        }
        __syncthreads();
    }

#pragma unroll
    for (int i = 0; i < 2; i++) {
        const int row0 = by * 128 + wm * 32 + i * 16 + qr;
        const int b = row0 >> 12;
        const int s0 = row0 & 4095;
#pragma unroll
        for (int j = 0; j < 8; j++) {
            const int col = bx * 128 + wn * 64 + j * 8 + 2 * qc;
            float v0 = acc[i][j][0] + bias[col];
            float v1 = acc[i][j][1] + bias[col + 1];
            float v2 = acc[i][j][2] + bias[col];
            float v3 = acc[i][j][3] + bias[col + 1];
            const int which = col >> 9;
            const int e = col & 511;
            const int h = e >> 6;
            const int d = e & 63;
            if (which == 0) { v0 *= 0.125f; v1 *= 0.125f;
                              v2 *= 0.125f; v3 *= 0.125f; }
            __nv_bfloat16* ph = (which == 0) ? g_Qh : (which == 1) ? g_Kh : g_Vh;
            __nv_bfloat16* pl = (which == 0) ? g_Ql : (which == 1) ? g_Kl : g_Vl;
            uint32_t hh, ll;
            const size_t dst0 = (((size_t)(b * NH + h) * S_LEN) + s0) * DH + d;
            split2(v0, v1, hh, ll);
            *(uint32_t*)&ph[dst0] = hh;
            *(uint32_t*)&pl[dst0] = ll;
            const size_t dst1 = dst0 + (size_t)8 * DH;
            split2(v2, v3, hh, ll);
            *(uint32_t*)&ph[dst1] = hh;
            *(uint32_t*)&pl[dst1] = ll;
        }
    }
}

// ---------------------------------------------------------------------------
// Out-projection GEMM (now 2 CTAs/SM)
// ---------------------------------------------------------------------------
__global__ __launch_bounds__(256, 2) void gemm_bf3_kernel(
    const __nv_bfloat16* __restrict__ Ah, const __nv_bfloat16* __restrict__ Al,
    const __nv_bfloat16* __restrict__ Bh, const __nv_bfloat16* __restrict__ Bl,
    const float* __restrict__ bias, float* __restrict__ C,
    int N, int K)
{
    extern __shared__ __align__(16) __nv_bfloat16 sg[];
    const int tid  = threadIdx.x;
    const int bx = blockIdx.x, by = blockIdx.y;
    const int lane = tid & 31, warp = tid >> 5;
    const int wm = warp & 3, wn = warp >> 2;
    const int qr = lane >> 2, qc = lane & 3;
    const int g = lane >> 3, rr = lane & 7;
    const uint32_t sb = (uint32_t)__cvta_generic_to_shared(sg);

    float acc[2][8][4];
#pragma unroll
    for (int i = 0; i < 2; i++)
#pragma unroll
        for (int j = 0; j < 8; j++)
#pragma unroll
            for (int e = 0; e < 4; e++) acc[i][j][e] = 0.f;

    auto fill = [&](int kc, int buf) {
        const int k0 = kc * 32;
        const uint32_t base = sb + buf * GBUF * 2;
#pragma unroll
        for (int t = 0; t < 4; t++) {
            const int idx = t * 256 + tid;
            const int arr = idx >> 9;
            const int rem = idx & 511;
            const int row = rem >> 2, c = rem & 3;
            const __nv_bfloat16* src =
                (arr ? Al : Ah) + (size_t)(by * 128 + row) * K + k0 + c * 8;
            cpasync16(base + (arr * 5120 + row * ASTR + c * 8) * 2, src);
        }
#pragma unroll
        for (int t = 0; t < 4; t++) {
            const int idx = t * 256 + tid;
            const int arr = idx >> 9;
            const int rem = idx & 511;
            const int row = rem >> 4, c = rem & 15;
            const __nv_bfloat16* src =
                (arr ? Bl : Bh) + (size_t)(k0 + row) * N + bx * 128 + c * 8;
            cpasync16(base + (10240 + arr * 4352 + row * BSTR + c * 8) * 2, src);
        }
        asm volatile("cp.async.commit_group;\n");
    };

    fill(0, 0);
    const int nkc = K / 32;

    for (int kc = 0; kc < nkc; kc++) {
        const int buf = kc & 1;
        asm volatile("cp.async.wait_group 0;\n");
        __syncthreads();
        if (kc + 1 < nkc) fill(kc + 1, buf ^ 1);

        const uint32_t base = sb + buf * GBUF * 2;
        const uint32_t Ah_s = base;
        const uint32_t Al_s = base + 5120 * 2;
        const uint32_t Bh_s = base + 10240 * 2;
        const uint32_t Bl_s = base + 14592 * 2;

#pragma unroll
        for (int s = 0; s < 2; s++) {
            uint32_t afh[2][4], afl[2][4];
#pragma unroll
            for (int i = 0; i < 2; i++) {
                const uint32_t off =
                    ((wm * 32 + i * 16 + (lane & 15)) * ASTR
                     + s * 16 + 8 * (lane >> 4)) * 2;
                ldsm4(afh[i], Ah_s + off);
                ldsm4(afl[i], Al_s + off);
            }
#pragma unroll
            for (int jp = 0; jp < 4; jp++) {
                const uint32_t off =
                    ((s * 16 + 8 * (g & 1) + rr) * BSTR
                     + wn * 64 + jp * 16 + 8 * (g >> 1)) * 2;
                uint32_t bh4[4], bl4[4];
                ldsm4t(bh4, Bh_s + off);
                ldsm4t(bl4, Bl_s + off);
#pragma unroll
                for (int i = 0; i < 2; i++) {
                    mma16816(acc[i][2 * jp],     afh[i], &bh4[0]);
                    mma16816(acc[i][2 * jp],     afh[i], &bl4[0]);
                    mma16816(acc[i][2 * jp],     afl[i], &bh4[0]);
                    mma16816(acc[i][2 * jp + 1], afh[i], &bh4[2]);
                    mma16816(acc[i][2 * jp + 1], afh[i], &bl4[2]);
                    mma16816(acc[i][2 * jp + 1], afl[i], &bh4[2]);
                }
            }
        }
        __syncthreads();
    }

#pragma unroll
    for (int i = 0; i < 2; i++) {
        const int row0 = by * 128 + wm * 32 + i * 16 + qr;
#pragma unroll
        for (int j = 0; j < 8; j++) {
            const int col = bx * 128 + wn * 64 + j * 8 + 2 * qc;
            float2 v0 = make_float2(acc[i][j][0] + bias[col],
                                    acc[i][j][1] + bias[col + 1]);
            float2 v1 = make_float2(acc[i][j][2] + bias[col],
                                    acc[i][j][3] + bias[col + 1]);
            *(float2*)(C + (size_t)row0 * N + col) = v0;
            *(float2*)(C + (size_t)(row0 + 8) * N + col) = v1;
        }
    }
}

// ---------------------------------------------------------------------------
// Tensor-core flash attention (now 2 CTAs/SM)
// ---------------------------------------------------------------------------
__global__ __launch_bounds__(256, 2) void attn_mma_kernel()
{
    extern __shared__ __align__(16) __nv_bfloat16 sm[];

    const int tid  = threadIdx.x;
    const int warp = tid >> 5;
    const int lane = tid & 31;
    const int qt = blockIdx.x;
    const int bh = blockIdx.y;
    const int rowbase = qt * 128;
    const int qr = lane >> 2;
    const int qc = lane & 3;
    const int g  = lane >> 3;
    const int rr = lane & 7;

    const uint32_t smem_base = (uint32_t)__cvta_generic_to_shared(sm);

    const __nv_bfloat16* srcs[4] = {
        g_Kh + (size_t)bh * S_LEN * DH,
        g_Kl + (size_t)bh * S_LEN * DH,
        g_Vh + (size_t)bh * S_LEN * DH,
        g_Vl + (size_t)bh * S_LEN * DH };

    uint32_t Qah[4][4], Qal[4][4];
    {
        const size_t qoff = ((size_t)bh * S_LEN + rowbase + warp * 16) * DH;
#pragma unroll
        for (int s = 0; s < 4; s++)
#pragma unroll
            for (int e = 0; e < 4; e++) {
                const int r = qr + 8 * (e & 1);
                const int c = 16 * s + 2 * qc + 8 * (e >> 1);
                Qah[s][e] = *(const uint32_t*)(g_Qh + qoff + (size_t)r * DH + c);
                Qal[s][e] = *(const uint32_t*)(g_Ql + qoff + (size_t)r * DH + c);
            }
    }

    float O[8][4];
#pragma unroll
    for (int j = 0; j < 8; j++)
#pragma unroll
        for (int e = 0; e < 4; e++) O[j][e] = 0.f;
    float m0 = -1e30f, m1 = -1e30f, l0 = 0.f, l1 = 0.f;

    const int nT = qt * 2 + 2;

    auto fill = [&](int kt, int buf) {
#pragma unroll
        for (int i = 0; i < 8; i++) {
            const int arr = i >> 1;
            const int e = ((i & 1) << 8) + tid;
            const int row = e >> 3;
            const int grp = e & 7;
            const __nv_bfloat16* src = srcs[arr] + (size_t)kt * 64 * DH
                                     + (size_t)row * DH + grp * 8;
            const uint32_t dst = smem_base +
                ((arr * 2 + buf) * TILE_E + row * KSTR + grp * 8) * 2;
            cpasync16(dst, src);
        }
        asm volatile("cp.async.commit_group;\n");
    };

    fill(0, 0);

    for (int kt = 0; kt < nT; kt++) {
        const int buf = kt & 1;
        asm volatile("cp.async.wait_group 0;\n");
        __syncthreads();
        if (kt + 1 < nT) fill(kt + 1, buf ^ 1);

        const uint32_t Kh_t = smem_base + ((0 * 2 + buf) * TILE_E) * 2;
        const uint32_t Kl_t = smem_base + ((1 * 2 + buf) * TILE_E) * 2;
        const uint32_t Vh_t = smem_base + ((2 * 2 + buf) * TILE_E) * 2;
        const uint32_t Vl_t = smem_base + ((3 * 2 + buf) * TILE_E) * 2;

        float S[8][4];
#pragma unroll
        for (int j = 0; j < 8; j++)
#pragma unroll
            for (int e = 0; e < 4; e++) S[j][e] = 0.f;

#pragma unroll
        for (int s = 0; s < 4; s++) {
#pragma unroll
            for (int jp = 0; jp < 4; jp++) {
                const uint32_t off = ((16 * jp + 8 * (g >> 1) + rr) * KSTR
                                    + 16 * s + 8 * (g & 1)) * 2;
                uint32_t bhv[4], blv[4];
                ldsm4(bhv, Kh_t + off);
                ldsm4(blv, Kl_t + off);
                mma16816(S[2 * jp],     Qah[s], &bhv[0]);
                mma16816(S[2 * jp],     Qah[s], &blv[0]);
                mma16816(S[2 * jp],     Qal[s], &bhv[0]);
                mma16816(S[2 * jp + 1], Qah[s], &bhv[2]);
                mma16816(S[2 * jp + 1], Qah[s], &blv[2]);
                mma16816(S[2 * jp + 1], Qal[s], &bhv[2]);
            }
        }

        const int grow0 = rowbase + warp * 16 + qr;
        if (kt * 64 + 63 > rowbase + warp * 16) {
#pragma unroll
            for (int j = 0; j < 8; j++)
#pragma unroll
                for (int e = 0; e < 4; e++) {
                    const int col = kt * 64 + 8 * j + 2 * qc + (e & 1);
                    const int row = grow0 + 8 * (e >> 1);
                    if (col > row) S[j][e] = -1e30f;
                }
        }

        float mx0 = -1e30f, mx1 = -1e30f;
#pragma unroll
        for (int j = 0; j < 8; j++) {
            mx0 = fmaxf(mx0, fmaxf(S[j][0], S[j][1]));
            mx1 = fmaxf(mx1, fmaxf(S[j][2], S[j][3]));
        }
        mx0 = fmaxf(mx0, __shfl_xor_sync(0xffffffffu, mx0, 1));
        mx0 = fmaxf(mx0, __shfl_xor_sync(0xffffffffu, mx0, 2));
        mx1 = fmaxf(mx1, __shfl_xor_sync(0xffffffffu, mx1, 1));
        mx1 = fmaxf(mx1, __shfl_xor_sync(0xffffffffu, mx1, 2));

        const float nm0 = fmaxf(m0, mx0);
        const float nm1 = fmaxf(m1, mx1);
        const float c0 = __expf(m0 - nm0);
        const float c1 = __expf(m1 - nm1);
        m0 = nm0; m1 = nm1;

        float s0 = 0.f, s1 = 0.f;
#pragma unroll
        for (int j = 0; j < 8; j++) {
            S[j][0] = __expf(S[j][0] - m0); s0 += S[j][0];
            S[j][1] = __expf(S[j][1] - m0); s0 += S[j][1];
            S[j][2] = __expf(S[j][2] - m1); s1 += S[j][2];
            S[j][3] = __expf(S[j][3] - m1); s1 += S[j][3];
        }
        s0 += __shfl_xor_sync(0xffffffffu, s0, 1);
        s0 += __shfl_xor_sync(0xffffffffu, s0, 2);
        s1 += __shfl_xor_sync(0xffffffffu, s1, 1);
        s1 += __shfl_xor_sync(0xffffffffu, s1, 2);
        l0 = l0 * c0 + s0;
        l1 = l1 * c1 + s1;
#pragma unroll
        for (int j = 0; j < 8; j++) {
            O[j][0] *= c0; O[j][1] *= c0;
            O[j][2] *= c1; O[j][3] *= c1;
        }

#pragma unroll
        for (int s = 0; s < 4; s++) {
            uint32_t Pah[4], Pal[4];
            split2(S[2 * s][0],     S[2 * s][1],     Pah[0], Pal[0]);
            split2(S[2 * s][2],     S[2 * s][3],     Pah[1], Pal[1]);
            split2(S[2 * s + 1][0], S[2 * s + 1][1], Pah[2], Pal[2]);
            split2(S[2 * s + 1][2], S[2 * s + 1][3], Pah[3], Pal[3]);
#pragma unroll
            for (int jp = 0; jp < 4; jp++) {
                const uint32_t off = ((16 * s + 8 * (g & 1) + rr) * KSTR
                                    + 16 * jp + 8 * (g >> 1)) * 2;
                uint32_t bhv[4], blv[4];
                ldsm4t(bhv, Vh_t + off);
                ldsm4t(blv, Vl_t + off);
                mma16816(O[2 * jp],     Pah, &bhv[0]);
                mma16816(O[2 * jp],     Pah, &blv[0]);
                mma16816(O[2 * jp],     Pal, &bhv[0]);
                mma16816(O[2 * jp + 1], Pah, &bhv[2]);
                mma16816(O[2 * jp + 1], Pah, &blv[2]);
                mma16816(O[2 * jp + 1], Pal, &bhv[2]);
            }
        }
        __syncthreads();
    }

    const float inv0 = 1.f / l0;
    const float inv1 = 1.f / l1;
    const int b = bh >> 3;
    const int h = bh & 7;
    const int row0 = rowbase + warp * 16 + qr;
    const int row1 = row0 + 8;
#pragma unroll
    for (int j = 0; j < 8; j++) {
        const int col = h * DH + 8 * j + 2 * qc;
        uint32_t hh, ll;
        const size_t o0 = ((size_t)b * S_LEN + row0) * EMB + col;
        split2(O[j][0] * inv0, O[j][1] * inv0, hh, ll);
        *(uint32_t*)&g_atth[o0] = hh;
        *(uint32_t*)&g_attl[o0] = ll;
        const size_t o1 = ((size_t)b * S_LEN + row1) * EMB + col;
        split2(O[j][2] * inv1, O[j][3] * inv1, hh, ll);
        *(uint32_t*)&g_atth[o1] = hh;
        *(uint32_t*)&g_attl[o1] = ll;
    }
}

// ---------------------------------------------------------------------------
extern "C" void kernel_launch(void* const* d_in, const int* in_sizes, int n_in,
                              void* d_out, int out_size)
{
    const float* x    = (const float*)d_in[0];
    const float* Wqkv = (const float*)d_in[1];
    const float* bqkv = (const float*)d_in[2];
    const float* Wo   = (const float*)d_in[3];
    const float* bo   = (const float*)d_in[4];
    for (int i = 0; i < n_in; i++) {
        switch (in_sizes[i]) {
            case 8388608: x    = (const float*)d_in[i]; break;
            case 786432:  Wqkv = (const float*)d_in[i]; break;
            case 1536:    bqkv = (const float*)d_in[i]; break;
            case 262144:  Wo   = (const float*)d_in[i]; break;
            case 512:     bo   = (const float*)d_in[i]; break;
        }
    }
    float* out = (float*)d_out;

    static bool init = false;
    static __nv_bfloat16 *p_Woh, *p_Wol, *p_ath, *p_atl;
    if (!init) {
        void* t;
        cudaGetSymbolAddress(&t, g_Woh);   p_Woh = (__nv_bfloat16*)t;
        cudaGetSymbolAddress(&t, g_Wol);   p_Wol = (__nv_bfloat16*)t;
        cudaGetSymbolAddress(&t, g_atth);  p_ath = (__nv_bfloat16*)t;
        cudaGetSymbolAddress(&t, g_attl);  p_atl = (__nv_bfloat16*)t;
        cudaFuncSetAttribute(attn_mma_kernel,
                             cudaFuncAttributeMaxDynamicSharedMemorySize,
                             ATTN_SMEM);
        cudaFuncSetAttribute(gemm_bf3_kernel,
                             cudaFuncAttributeMaxDynamicSharedMemorySize,
                             GSMEM);
        cudaFuncSetAttribute(gemm_qkv_blk_kernel,
                             cudaFuncAttributeMaxDynamicSharedMemorySize,
                             QK_SMEM);
        init = true;
    }

    // 0) splits
    splitA_blk_kernel<<<M_ROWS * EMB / 8 / 256, 256>>>(x);
    splitB_blk_kernel<<<EMB * N_QKV / 8 / 256, 256>>>(Wqkv);
    split_kernel<<<(EMB * EMB / 2 + 255) / 256, 256>>>(Wo, p_Woh, p_Wol,
                                                       EMB * EMB / 2);

    // 1) QKV projection
    gemm_qkv_blk_kernel<<<dim3(N_QKV / 128, M_ROWS / 128), 256, QK_SMEM>>>(bqkv);

    // 2) Attention
    attn_mma_kernel<<<dim3(S_LEN / 128, BATCH * NH), 256, ATTN_SMEM>>>();

    // 3) Output projection
    gemm_bf3_kernel<<<dim3(EMB / 128, M_ROWS / 128), 256, GSMEM>>>(
        p_ath, p_atl, p_Woh, p_Wol, bo, out, EMB, EMB);
}

// round 11
// speedup vs baseline: 8.4501x; 1.1439x over previous
#include <cuda_runtime.h>
#include <cuda_bf16.h>
#include <cuda_fp16.h>
#include <math.h>
#include <stdint.h>

#define S_LEN 4096
#define EMB   512
#define NH    8
#define DH    64
#define BATCH 4
#define M_ROWS (BATCH * S_LEN)          // 16384
#define N_QKV  (3 * EMB)                // 1536
#define KSTR   72                        // attn smem stride (64 + 8 pad)
#define TILE_E (64 * KSTR)
#define ATTN_SMEM (2 * 4 * TILE_E * 2)   // 73728

// out-proj GEMM smem
#define ASTR 40
#define BSTR 136
#define GBUF 18944
#define GSMEM (2 * GBUF * 2)             // 75776

// QKV blocked GEMM smem
#define QK_SMEM (1024 + 2 * 32768)       // 66560

// Scratch (allocation-free: __device__ globals)
__device__ __align__(16) __nv_bfloat16 g_xhB[(size_t)M_ROWS * EMB];
__device__ __align__(16) __nv_bfloat16 g_xlB[(size_t)M_ROWS * EMB];
__device__ __align__(16) __nv_bfloat16 g_WqhB[(size_t)EMB * N_QKV];
__device__ __align__(16) __nv_bfloat16 g_WqlB[(size_t)EMB * N_QKV];
__device__ __align__(16) __nv_bfloat16 g_Woh[(size_t)EMB * EMB];
__device__ __align__(16) __nv_bfloat16 g_Wol[(size_t)EMB * EMB];
// Q pre-scaled by 0.125; all [B,H,S,Dh] — now FP16 hi/lo
__device__ __align__(16) __half g_Qh[(size_t)BATCH * NH * S_LEN * DH];
__device__ __align__(16) __half g_Ql[(size_t)BATCH * NH * S_LEN * DH];
__device__ __align__(16) __half g_Kh[(size_t)BATCH * NH * S_LEN * DH];
__device__ __align__(16) __half g_Kl[(size_t)BATCH * NH * S_LEN * DH];
__device__ __align__(16) __half g_Vh[(size_t)BATCH * NH * S_LEN * DH];
__device__ __align__(16) __half g_Vl[(size_t)BATCH * NH * S_LEN * DH];
// attention output split [B,S,E] (bf16, feeds out-proj)
__device__ __align__(16) __nv_bfloat16 g_atth[(size_t)M_ROWS * EMB];
__device__ __align__(16) __nv_bfloat16 g_attl[(size_t)M_ROWS * EMB];

__device__ __forceinline__ void split2(float x, float y, uint32_t& h, uint32_t& l)
{
    __nv_bfloat16 hx = __float2bfloat16(x);
    __nv_bfloat16 hy = __float2bfloat16(y);
    __nv_bfloat162 hh; hh.x = hx; hh.y = hy;
    __nv_bfloat162 ll;
    ll.x = __float2bfloat16(x - __bfloat162float(hx));
    ll.y = __float2bfloat16(y - __bfloat162float(hy));
    h = *(uint32_t*)&hh;
    l = *(uint32_t*)&ll;
}

// fp16 hi/lo split (22 effective mantissa bits)
__device__ __forceinline__ void split2h(float x, float y, uint32_t& h, uint32_t& l)
{
    __half hx = __float2half_rn(x);
    __half hy = __float2half_rn(y);
    __half2 hh; hh.x = hx; hh.y = hy;
    __half2 ll;
    ll.x = __float2half_rn(x - __half2float(hx));
    ll.y = __float2half_rn(y - __half2float(hy));
    h = *(uint32_t*)&hh;
    l = *(uint32_t*)&ll;
}

__device__ __forceinline__ void mma16816(float c[4], const uint32_t a[4],
                                         const uint32_t* b)
{
    asm volatile(
        "mma.sync.aligned.m16n8k16.row.col.f32.bf16.bf16.f32 "
        "{%0,%1,%2,%3}, {%4,%5,%6,%7}, {%8,%9}, {%0,%1,%2,%3};\n"
        : "+f"(c[0]), "+f"(c[1]), "+f"(c[2]), "+f"(c[3])
        : "r"(a[0]), "r"(a[1]), "r"(a[2]), "r"(a[3]), "r"(b[0]), "r"(b[1]));
}

__device__ __forceinline__ void mma16816h(float c[4], const uint32_t a[4],
                                          const uint32_t* b)
{
    asm volatile(
        "mma.sync.aligned.m16n8k16.row.col.f32.f16.f16.f32 "
        "{%0,%1,%2,%3}, {%4,%5,%6,%7}, {%8,%9}, {%0,%1,%2,%3};\n"
        : "+f"(c[0]), "+f"(c[1]), "+f"(c[2]), "+f"(c[3])
        : "r"(a[0]), "r"(a[1]), "r"(a[2]), "r"(a[3]), "r"(b[0]), "r"(b[1]));
}

__device__ __forceinline__ void ldsm4(uint32_t r[4], uint32_t addr)
{
    asm volatile("ldmatrix.sync.aligned.m8n8.x4.shared.b16 {%0,%1,%2,%3}, [%4];\n"
                 : "=r"(r[0]), "=r"(r[1]), "=r"(r[2]), "=r"(r[3]) : "r"(addr));
}

__device__ __forceinline__ void ldsm4t(uint32_t r[4], uint32_t addr)
{
    asm volatile("ldmatrix.sync.aligned.m8n8.x4.trans.shared.b16 {%0,%1,%2,%3}, [%4];\n"
                 : "=r"(r[0]), "=r"(r[1]), "=r"(r[2]), "=r"(r[3]) : "r"(addr));
}

__device__ __forceinline__ void cpasync16(uint32_t s, const void* g)
{
    asm volatile("cp.async.cg.shared.global [%0], [%1], 16;\n" :: "r"(s), "l"(g));
}

// ---- bulk copy + mbarrier helpers ----
__device__ __forceinline__ void bulk_g2s(uint32_t dst, const void* src,
                                         uint32_t bytes, uint32_t mbar)
{
    asm volatile(
        "cp.async.bulk.shared::cta.global.mbarrier::complete_tx::bytes "
        "[%0], [%1], %2, [%3];\n"
        :: "r"(dst), "l"(src), "r"(bytes), "r"(mbar) : "memory");
}

__device__ __forceinline__ void mbar_init(uint32_t mbar, uint32_t cnt)
{
    asm volatile("mbarrier.init.shared.b64 [%0], %1;" :: "r"(mbar), "r"(cnt) : "memory");
}

__device__ __forceinline__ void mbar_expect_tx(uint32_t mbar, uint32_t bytes)
{
    asm volatile("mbarrier.arrive.expect_tx.shared.b64 _, [%0], %1;"
                 :: "r"(mbar), "r"(bytes) : "memory");
}

__device__ __forceinline__ void mbar_wait(uint32_t mbar, uint32_t parity)
{
    uint32_t done;
    asm volatile(
        "{\n\t.reg .pred p;\n\t"
        "mbarrier.try_wait.parity.acquire.cta.shared::cta.b64 p, [%1], %2;\n\t"
        "selp.b32 %0, 1, 0, p;\n\t}"
        : "=r"(done) : "r"(mbar), "r"(parity) : "memory");
    if (!done) {
        asm volatile(
            "{\n\t.reg .pred P1;\n\t"
            "WL_%=:\n\t"
            "mbarrier.try_wait.parity.acquire.cta.shared::cta.b64 P1, [%0], %1, 0x989680;\n\t"
            "@P1 bra.uni WD_%=;\n\t"
            "bra.uni WL_%=;\n\t"
            "WD_%=:\n\t}"
            :: "r"(mbar), "r"(parity) : "memory");
    }
}

__device__ __forceinline__ uint32_t smem_u32(const void* p)
{
    uint32_t a;
    asm("{ .reg .u64 t; cvta.to.shared.u64 t, %1; cvt.u32.u64 %0, t; }"
        : "=r"(a) : "l"(p));
    return a;
}

// ---------------------------------------------------------------------------
// Splits
// ---------------------------------------------------------------------------
__global__ __launch_bounds__(256) void split_kernel(
    const float* __restrict__ src, __nv_bfloat16* __restrict__ h,
    __nv_bfloat16* __restrict__ l, int n2)
{
    const int idx = blockIdx.x * 256 + threadIdx.x;
    if (idx >= n2) return;
    const float2 v = ((const float2*)src)[idx];
    uint32_t hh, ll;
    split2(v.x, v.y, hh, ll);
    ((uint32_t*)h)[idx] = hh;
    ((uint32_t*)l)[idx] = ll;
}

__global__ __launch_bounds__(256) void splitA_blk_kernel(const float* __restrict__ x)
{
    const int idx = blockIdx.x * 256 + threadIdx.x;
    const int row = idx >> 6;
    const int cu = idx & 63;
    const int kc = cu >> 2;
    const int u = cu & 3;
    const int by = row >> 7;
    const int r = row & 127;
    const int up = (u + (r >> 1)) & 3;
    const size_t off = (size_t)(by * 16 + kc) * 4096 + r * 32 + up * 8;

    const float4 a0 = *(const float4*)(x + (size_t)row * 512 + cu * 8);
    const float4 a1 = *(const float4*)(x + (size_t)row * 512 + cu * 8 + 4);
    uint4 H, L;
    split2(a0.x, a0.y, H.x, L.x);
    split2(a0.z, a0.w, H.y, L.y);
    split2(a1.x, a1.y, H.z, L.z);
    split2(a1.z, a1.w, H.w, L.w);
    *(uint4*)(g_xhB + off) = H;
    *(uint4*)(g_xlB + off) = L;
}

__global__ __launch_bounds__(256) void splitB_blk_kernel(const float* __restrict__ W)
{
    const int idx = blockIdx.x * 256 + threadIdx.x;
    const int k = idx / 192;
    const int cu = idx - k * 192;
    const int bx = cu >> 4;
    const int u = cu & 15;
    const int kc = k >> 5;
    const int r = k & 31;
    const int up = (u & 8) | ((u & 7) ^ (r & 7));
    const size_t off = (size_t)(bx * 16 + kc) * 4096 + r * 128 + up * 8;

    const float4 a0 = *(const float4*)(W + (size_t)k * N_QKV + cu * 8);
    const float4 a1 = *(const float4*)(W + (size_t)k * N_QKV + cu * 8 + 4);
    uint4 H, L;
    split2(a0.x, a0.y, H.x, L.x);
    split2(a0.z, a0.w, H.y, L.y);
    split2(a1.x, a1.y, H.z, L.z);
    split2(a1.z, a1.w, H.w, L.w);
    *(uint4*)(g_WqhB + off) = H;
    *(uint4*)(g_WqlB + off) = L;
}

// ---------------------------------------------------------------------------
// QKV GEMM with cp.async.bulk fill (2 CTAs/SM). Epilogue emits FP16 splits.
// ---------------------------------------------------------------------------
__global__ __launch_bounds__(256, 2) void gemm_qkv_blk_kernel(
    const float* __restrict__ bias)
{
    extern __shared__ __align__(1024) char sq[];
    const uint32_t sb = smem_u32(sq);
    const int tid = threadIdx.x;
    const int bx = blockIdx.x, by = blockIdx.y;
    const int lane = tid & 31, warp = tid >> 5;
    const int wm = warp & 3, wn = warp >> 2;
    const int qr = lane >> 2, qc = lane & 3;
    const int g = lane >> 3, rr = lane & 7;

    float acc[2][8][4];
#pragma unroll
    for (int i = 0; i < 2; i++)
#pragma unroll
        for (int j = 0; j < 8; j++)
#pragma unroll
            for (int e = 0; e < 4; e++) acc[i][j][e] = 0.f;

    if (tid == 0) { mbar_init(sb, 1); mbar_init(sb + 16, 1); }
    __syncthreads();

    auto fill = [&](int kc) {
        const int buf = kc & 1;
        const uint32_t mb = sb + buf * 16;
        const uint32_t dst = sb + 1024 + buf * 32768;
        mbar_expect_tx(mb, 32768);
        bulk_g2s(dst,         g_xhB + (size_t)(by * 16 + kc) * 4096, 8192, mb);
        bulk_g2s(dst + 8192,  g_xlB + (size_t)(by * 16 + kc) * 4096, 8192, mb);
        bulk_g2s(dst + 16384, g_WqhB + (size_t)(bx * 16 + kc) * 4096, 8192, mb);
        bulk_g2s(dst + 24576, g_WqlB + (size_t)(bx * 16 + kc) * 4096, 8192, mb);
    };

    if (tid == 0) fill(0);

    for (int kc = 0; kc < 16; kc++) {
        if (kc + 1 < 16 && tid == 0) fill(kc + 1);
        mbar_wait(sb + (kc & 1) * 16, (kc >> 1) & 1);

        const uint32_t base = sb + 1024 + (kc & 1) * 32768;
        const uint32_t Ah_s = base;
        const uint32_t Al_s = base + 8192;
        const uint32_t Bh_s = base + 16384;
        const uint32_t Bl_s = base + 24576;

#pragma unroll
        for (int s = 0; s < 2; s++) {
            uint32_t afh[2][4], afl[2][4];
#pragma unroll
            for (int i = 0; i < 2; i++) {
                const int ar = wm * 32 + i * 16 + (lane & 15);
                const int au = s * 2 + (lane >> 4);
                const int aup = (au + (ar >> 1)) & 3;
                const uint32_t off = ar * 64 + aup * 16;
                ldsm4(afh[i], Ah_s + off);
                ldsm4(afl[i], Al_s + off);
            }
#pragma unroll
            for (int jp = 0; jp < 4; jp++) {
                const int br = s * 16 + 8 * (g & 1) + rr;
                const int bu = wn * 8 + jp * 2 + (g >> 1);
                const int bup = (bu & 8) | ((bu & 7) ^ (br & 7));
                const uint32_t off = br * 256 + bup * 16;
                uint32_t bh4[4], bl4[4];
                ldsm4t(bh4, Bh_s + off);
                ldsm4t(bl4, Bl_s + off);
#pragma unroll
                for (int i = 0; i < 2; i++) {
                    mma16816(acc[i][2 * jp],     afh[i], &bh4[0]);
                    mma16816(acc[i][2 * jp],     afh[i], &bl4[0]);
                    mma16816(acc[i][2 * jp],     afl[i], &bh4[0]);
                    mma16816(acc[i][2 * jp + 1], afh[i], &bh4[2]);
                    mma16816(acc[i][2 * jp + 1], afh[i], &bl4[2]);
                    mma16816(acc[i][2 * jp + 1], afl[i], &bh4[2]);
                }
            }
        }
        __syncthreads();
    }

    // Epilogue: bias + (Q scale) + FP16 split + scatter to [B,H,S,Dh]
#pragma unroll
    for (int i = 0; i < 2; i++) {
        const int row0 = by * 128 + wm * 32 + i * 16 + qr;
        const int b = row0 >> 12;
        const int s0 = row0 & 4095;
#pragma unroll
        for (int j = 0; j < 8; j++) {
            const int col = bx * 128 + wn * 64 + j * 8 + 2 * qc;
            float v0 = acc[i][j][0] + bias[col];
            float v1 = acc[i][j][1] + bias[col + 1];
            float v2 = acc[i][j][2] + bias[col];
            float v3 = acc[i][j][3] + bias[col + 1];
            const int which = col >> 9;
            const int e = col & 511;
            const int h = e >> 6;
            const int d = e & 63;
            if (which == 0) { v0 *= 0.125f; v1 *= 0.125f;
                              v2 *= 0.125f; v3 *= 0.125f; }
            __half* ph = (which == 0) ? g_Qh : (which == 1) ? g_Kh : g_Vh;
            __half* pl = (which == 0) ? g_Ql : (which == 1) ? g_Kl : g_Vl;
            uint32_t hh, ll;
            const size_t dst0 = (((size_t)(b * NH + h) * S_LEN) + s0) * DH + d;
            split2h(v0, v1, hh, ll);
            *(uint32_t*)&ph[dst0] = hh;
            *(uint32_t*)&pl[dst0] = ll;
            const size_t dst1 = dst0 + (size_t)8 * DH;
            split2h(v2, v3, hh, ll);
            *(uint32_t*)&ph[dst1] = hh;
            *(uint32_t*)&pl[dst1] = ll;
        }
    }
}

// ---------------------------------------------------------------------------
// Out-projection GEMM (unchanged; 2 CTAs/SM)
// ---------------------------------------------------------------------------
__global__ __launch_bounds__(256, 2) void gemm_bf3_kernel(
    const __nv_bfloat16* __restrict__ Ah, const __nv_bfloat16* __restrict__ Al,
    const __nv_bfloat16* __restrict__ Bh, const __nv_bfloat16* __restrict__ Bl,
    const float* __restrict__ bias, float* __restrict__ C,
    int N, int K)
{
    extern __shared__ __align__(16) __nv_bfloat16 sg[];
    const int tid  = threadIdx.x;
    const int bx = blockIdx.x, by = blockIdx.y;
    const int lane = tid & 31, warp = tid >> 5;
    const int wm = warp & 3, wn = warp >> 2;
    const int qr = lane >> 2, qc = lane & 3;
    const int g = lane >> 3, rr = lane & 7;
    const uint32_t sb = (uint32_t)__cvta_generic_to_shared(sg);

    float acc[2][8][4];
#pragma unroll
    for (int i = 0; i < 2; i++)
#pragma unroll
        for (int j = 0; j < 8; j++)
#pragma unroll
            for (int e = 0; e < 4; e++) acc[i][j][e] = 0.f;

    auto fill = [&](int kc, int buf) {
        const int k0 = kc * 32;
        const uint32_t base = sb + buf * GBUF * 2;
#pragma unroll
        for (int t = 0; t < 4; t++) {
            const int idx = t * 256 + tid;
            const int arr = idx >> 9;
            const int rem = idx & 511;
            const int row = rem >> 2, c = rem & 3;
            const __nv_bfloat16* src =
                (arr ? Al : Ah) + (size_t)(by * 128 + row) * K + k0 + c * 8;
            cpasync16(base + (arr * 5120 + row * ASTR + c * 8) * 2, src);
        }
#pragma unroll
        for (int t = 0; t < 4; t++) {
            const int idx = t * 256 + tid;
            const int arr = idx >> 9;
            const int rem = idx & 511;
            const int row = rem >> 4, c = rem & 15;
            const __nv_bfloat16* src =
                (arr ? Bl : Bh) + (size_t)(k0 + row) * N + bx * 128 + c * 8;
            cpasync16(base + (10240 + arr * 4352 + row * BSTR + c * 8) * 2, src);
        }
        asm volatile("cp.async.commit_group;\n");
    };

    fill(0, 0);
    const int nkc = K / 32;

    for (int kc = 0; kc < nkc; kc++) {
        const int buf = kc & 1;
        asm volatile("cp.async.wait_group 0;\n");
        __syncthreads();
        if (kc + 1 < nkc) fill(kc + 1, buf ^ 1);

        const uint32_t base = sb + buf * GBUF * 2;
        const uint32_t Ah_s = base;
        const uint32_t Al_s = base + 5120 * 2;
        const uint32_t Bh_s = base + 10240 * 2;
        const uint32_t Bl_s = base + 14592 * 2;

#pragma unroll
        for (int s = 0; s < 2; s++) {
            uint32_t afh[2][4], afl[2][4];
#pragma unroll
            for (int i = 0; i < 2; i++) {
                const uint32_t off =
                    ((wm * 32 + i * 16 + (lane & 15)) * ASTR
                     + s * 16 + 8 * (lane >> 4)) * 2;
                ldsm4(afh[i], Ah_s + off);
                ldsm4(afl[i], Al_s + off);
            }
#pragma unroll
            for (int jp = 0; jp < 4; jp++) {
                const uint32_t off =
                    ((s * 16 + 8 * (g & 1) + rr) * BSTR
                     + wn * 64 + jp * 16 + 8 * (g >> 1)) * 2;
                uint32_t bh4[4], bl4[4];
                ldsm4t(bh4, Bh_s + off);
                ldsm4t(bl4, Bl_s + off);
#pragma unroll
                for (int i = 0; i < 2; i++) {
                    mma16816(acc[i][2 * jp],     afh[i], &bh4[0]);
                    mma16816(acc[i][2 * jp],     afh[i], &bl4[0]);
                    mma16816(acc[i][2 * jp],     afl[i], &bh4[0]);
                    mma16816(acc[i][2 * jp + 1], afh[i], &bh4[2]);
                    mma16816(acc[i][2 * jp + 1], afh[i], &bl4[2]);
                    mma16816(acc[i][2 * jp + 1], afl[i], &bh4[2]);
                }
            }
        }
        __syncthreads();
    }

#pragma unroll
    for (int i = 0; i < 2; i++) {
        const int row0 = by * 128 + wm * 32 + i * 16 + qr;
#pragma unroll
        for (int j = 0; j < 8; j++) {
            const int col = bx * 128 + wn * 64 + j * 8 + 2 * qc;
            float2 v0 = make_float2(acc[i][j][0] + bias[col],
                                    acc[i][j][1] + bias[col + 1]);
            float2 v1 = make_float2(acc[i][j][2] + bias[col],
                                    acc[i][j][3] + bias[col + 1]);
            *(float2*)(C + (size_t)row0 * N + col) = v0;
            *(float2*)(C + (size_t)(row0 + 8) * N + col) = v1;
        }
    }
}

// ---------------------------------------------------------------------------
// Tensor-core flash attention: fp16x3 QK (exact products), fp16 P x fp16x2 V.
// 1 CTA/SM (no register cap — spills were worse than low occupancy).
// ---------------------------------------------------------------------------
__global__ __launch_bounds__(256) void attn_mma_kernel()
{
    extern __shared__ __align__(16) __half sm[];

    const int tid  = threadIdx.x;
    const int warp = tid >> 5;
    const int lane = tid & 31;
    const int qt = blockIdx.x;
    const int bh = blockIdx.y;
    const int rowbase = qt * 128;
    const int qr = lane >> 2;
    const int qc = lane & 3;
    const int g  = lane >> 3;
    const int rr = lane & 7;

    const uint32_t smem_base = (uint32_t)__cvta_generic_to_shared(sm);

    const __half* srcs[4] = {
        g_Kh + (size_t)bh * S_LEN * DH,
        g_Kl + (size_t)bh * S_LEN * DH,
        g_Vh + (size_t)bh * S_LEN * DH,
        g_Vl + (size_t)bh * S_LEN * DH };

    uint32_t Qah[4][4], Qal[4][4];
    {
        const size_t qoff = ((size_t)bh * S_LEN + rowbase + warp * 16) * DH;
#pragma unroll
        for (int s = 0; s < 4; s++)
#pragma unroll
            for (int e = 0; e < 4; e++) {
                const int r = qr + 8 * (e & 1);
                const int c = 16 * s + 2 * qc + 8 * (e >> 1);
                Qah[s][e] = *(const uint32_t*)(g_Qh + qoff + (size_t)r * DH + c);
                Qal[s][e] = *(const uint32_t*)(g_Ql + qoff + (size_t)r * DH + c);
            }
    }

    float O[8][4];
#pragma unroll
    for (int j = 0; j < 8; j++)
#pragma unroll
        for (int e = 0; e < 4; e++) O[j][e] = 0.f;
    float m0 = -1e30f, m1 = -1e30f, l0 = 0.f, l1 = 0.f;

    const int nT = qt * 2 + 2;

    auto fill = [&](int kt, int buf) {
#pragma unroll
        for (int i = 0; i < 8; i++) {
            const int arr = i >> 1;
            const int e = ((i & 1) << 8) + tid;
            const int row = e >> 3;
            const int grp = e & 7;
            const __half* src = srcs[arr] + (size_t)kt * 64 * DH
                              + (size_t)row * DH + grp * 8;
            const uint32_t dst = smem_base +
                ((arr * 2 + buf) * TILE_E + row * KSTR + grp * 8) * 2;
            cpasync16(dst, src);
        }
        asm volatile("cp.async.commit_group;\n");
    };

    fill(0, 0);

    for (int kt = 0; kt < nT; kt++) {
        const int buf = kt & 1;
        asm volatile("cp.async.wait_group 0;\n");
        __syncthreads();
        if (kt + 1 < nT) fill(kt + 1, buf ^ 1);

        const uint32_t Kh_t = smem_base + ((0 * 2 + buf) * TILE_E) * 2;
        const uint32_t Kl_t = smem_base + ((1 * 2 + buf) * TILE_E) * 2;
        const uint32_t Vh_t = smem_base + ((2 * 2 + buf) * TILE_E) * 2;
        const uint32_t Vl_t = smem_base + ((3 * 2 + buf) * TILE_E) * 2;

        // S = Q K^T  (fp16 3-term: all retained products exact in fp32)
        float S[8][4];
#pragma unroll
        for (int j = 0; j < 8; j++)
#pragma unroll
            for (int e = 0; e < 4; e++) S[j][e] = 0.f;

#pragma unroll
        for (int s = 0; s < 4; s++) {
#pragma unroll
            for (int jp = 0; jp < 4; jp++) {
                const uint32_t off = ((16 * jp + 8 * (g >> 1) + rr) * KSTR
                                    + 16 * s + 8 * (g & 1)) * 2;
                uint32_t bhv[4], blv[4];
                ldsm4(bhv, Kh_t + off);
                ldsm4(blv, Kl_t + off);
                mma16816h(S[2 * jp],     Qah[s], &bhv[0]);
                mma16816h(S[2 * jp],     Qah[s], &blv[0]);
                mma16816h(S[2 * jp],     Qal[s], &bhv[0]);
                mma16816h(S[2 * jp + 1], Qah[s], &bhv[2]);
                mma16816h(S[2 * jp + 1], Qah[s], &blv[2]);
                mma16816h(S[2 * jp + 1], Qal[s], &bhv[2]);
            }
        }

        const int grow0 = rowbase + warp * 16 + qr;
        if (kt * 64 + 63 > rowbase + warp * 16) {
#pragma unroll
            for (int j = 0; j < 8; j++)
#pragma unroll
                for (int e = 0; e < 4; e++) {
                    const int col = kt * 64 + 8 * j + 2 * qc + (e & 1);
                    const int row = grow0 + 8 * (e >> 1);
                    if (col > row) S[j][e] = -1e30f;
                }
        }

        float mx0 = -1e30f, mx1 = -1e30f;
#pragma unroll
        for (int j = 0; j < 8; j++) {
            mx0 = fmaxf(mx0, fmaxf(S[j][0], S[j][1]));
            mx1 = fmaxf(mx1, fmaxf(S[j][2], S[j][3]));
        }
        mx0 = fmaxf(mx0, __shfl_xor_sync(0xffffffffu, mx0, 1));
        mx0 = fmaxf(mx0, __shfl_xor_sync(0xffffffffu, mx0, 2));
        mx1 = fmaxf(mx1, __shfl_xor_sync(0xffffffffu, mx1, 1));
        mx1 = fmaxf(mx1, __shfl_xor_sync(0xffffffffu, mx1, 2));

        const float nm0 = fmaxf(m0, mx0);
        const float nm1 = fmaxf(m1, mx1);
        const float c0 = __expf(m0 - nm0);
        const float c1 = __expf(m1 - nm1);
        m0 = nm0; m1 = nm1;

        float s0 = 0.f, s1 = 0.f;
#pragma unroll
        for (int j = 0; j < 8; j++) {
            S[j][0] = __expf(S[j][0] - m0); s0 += S[j][0];
            S[j][1] = __expf(S[j][1] - m0); s0 += S[j][1];
            S[j][2] = __expf(S[j][2] - m1); s1 += S[j][2];
            S[j][3] = __expf(S[j][3] - m1); s1 += S[j][3];
        }
        s0 += __shfl_xor_sync(0xffffffffu, s0, 1);
        s0 += __shfl_xor_sync(0xffffffffu, s0, 2);
        s1 += __shfl_xor_sync(0xffffffffu, s1, 1);
        s1 += __shfl_xor_sync(0xffffffffu, s1, 2);
        l0 = l0 * c0 + s0;
        l1 = l1 * c1 + s1;
#pragma unroll
        for (int j = 0; j < 8; j++) {
            O[j][0] *= c0; O[j][1] *= c0;
            O[j][2] *= c1; O[j][3] *= c1;
        }

        // O += P V  (P single fp16, V fp16 hi/lo: 4 MMAs per (s,jp))
#pragma unroll
        for (int s = 0; s < 4; s++) {
            uint32_t Pa[4];
            {
                __half2 p0 = __floats2half2_rn(S[2 * s][0],     S[2 * s][1]);
                __half2 p1 = __floats2half2_rn(S[2 * s][2],     S[2 * s][3]);
                __half2 p2 = __floats2half2_rn(S[2 * s + 1][0], S[2 * s + 1][1]);
                __half2 p3 = __floats2half2_rn(S[2 * s + 1][2], S[2 * s + 1][3]);
                Pa[0] = *(uint32_t*)&p0;
                Pa[1] = *(uint32_t*)&p1;
                Pa[2] = *(uint32_t*)&p2;
                Pa[3] = *(uint32_t*)&p3;
            }
#pragma unroll
            for (int jp = 0; jp < 4; jp++) {
                const uint32_t off = ((16 * s + 8 * (g & 1) + rr) * KSTR
                                    + 16 * jp + 8 * (g >> 1)) * 2;
                uint32_t bhv[4], blv[4];
                ldsm4t(bhv, Vh_t + off);
                ldsm4t(blv, Vl_t + off);
                mma16816h(O[2 * jp],     Pa, &bhv[0]);
                mma16816h(O[2 * jp],     Pa, &blv[0]);
                mma16816h(O[2 * jp + 1], Pa, &bhv[2]);
                mma16816h(O[2 * jp + 1], Pa, &blv[2]);
            }
        }
        __syncthreads();
    }

    const float inv0 = 1.f / l0;
    const float inv1 = 1.f / l1;
    const int b = bh >> 3;
    const int h = bh & 7;
    const int row0 = rowbase + warp * 16 + qr;
    const int row1 = row0 + 8;
#pragma unroll
    for (int j = 0; j < 8; j++) {
        const int col = h * DH + 8 * j + 2 * qc;
        uint32_t hh, ll;
        const size_t o0 = ((size_t)b * S_LEN + row0) * EMB + col;
        split2(O[j][0] * inv0, O[j][1] * inv0, hh, ll);
        *(uint32_t*)&g_atth[o0] = hh;
        *(uint32_t*)&g_attl[o0] = ll;
        const size_t o1 = ((size_t)b * S_LEN + row1) * EMB + col;
        split2(O[j][2] * inv1, O[j][3] * inv1, hh, ll);
        *(uint32_t*)&g_atth[o1] = hh;
        *(uint32_t*)&g_attl[o1] = ll;
    }
}

// ---------------------------------------------------------------------------
extern "C" void kernel_launch(void* const* d_in, const int* in_sizes, int n_in,
                              void* d_out, int out_size)
{
    const float* x    = (const float*)d_in[0];
    const float* Wqkv = (const float*)d_in[1];
    const float* bqkv = (const float*)d_in[2];
    const float* Wo   = (const float*)d_in[3];
    const float* bo   = (const float*)d_in[4];
    for (int i = 0; i < n_in; i++) {
        switch (in_sizes[i]) {
            case 8388608: x    = (const float*)d_in[i]; break;
            case 786432:  Wqkv = (const float*)d_in[i]; break;
            case 1536:    bqkv = (const float*)d_in[i]; break;
            case 262144:  Wo   = (const float*)d_in[i]; break;
            case 512:     bo   = (const float*)d_in[i]; break;
        }
    }
    float* out = (float*)d_out;

    static bool init = false;
    static __nv_bfloat16 *p_Woh, *p_Wol, *p_ath, *p_atl;
    if (!init) {
        void* t;
        cudaGetSymbolAddress(&t, g_Woh);   p_Woh = (__nv_bfloat16*)t;
        cudaGetSymbolAddress(&t, g_Wol);   p_Wol = (__nv_bfloat16*)t;
        cudaGetSymbolAddress(&t, g_atth);  p_ath = (__nv_bfloat16*)t;
        cudaGetSymbolAddress(&t, g_attl);  p_atl = (__nv_bfloat16*)t;
        cudaFuncSetAttribute(attn_mma_kernel,
                             cudaFuncAttributeMaxDynamicSharedMemorySize,
                             ATTN_SMEM);
        cudaFuncSetAttribute(gemm_bf3_kernel,
                             cudaFuncAttributeMaxDynamicSharedMemorySize,
                             GSMEM);
        cudaFuncSetAttribute(gemm_qkv_blk_kernel,
                             cudaFuncAttributeMaxDynamicSharedMemorySize,
                             QK_SMEM);
        init = true;
    }

    // 0) splits
    splitA_blk_kernel<<<M_ROWS * EMB / 8 / 256, 256>>>(x);
    splitB_blk_kernel<<<EMB * N_QKV / 8 / 256, 256>>>(Wqkv);
    split_kernel<<<(EMB * EMB / 2 + 255) / 256, 256>>>(Wo, p_Woh, p_Wol,
                                                       EMB * EMB / 2);

    // 1) QKV projection
    gemm_qkv_blk_kernel<<<dim3(N_QKV / 128, M_ROWS / 128), 256, QK_SMEM>>>(bqkv);

    // 2) Attention
    attn_mma_kernel<<<dim3(S_LEN / 128, BATCH * NH), 256, ATTN_SMEM>>>();

    // 3) Output projection
    gemm_bf3_kernel<<<dim3(EMB / 128, M_ROWS / 128), 256, GSMEM>>>(
        p_ath, p_atl, p_Woh, p_Wol, bo, out, EMB, EMB);
}

// round 12
// speedup vs baseline: 11.2697x; 1.3337x over previous
#include <cuda_runtime.h>
#include <cuda_bf16.h>
#include <cuda_fp16.h>
#include <math.h>
#include <stdint.h>

#define S_LEN 4096
#define EMB   512
#define NH    8
#define DH    64
#define BATCH 4
#define M_ROWS (BATCH * S_LEN)          // 16384
#define N_QKV  (3 * EMB)                // 1536
#define KSTR   72                        // attn smem stride (64 + 8 pad)
#define TILE_E (64 * KSTR)
#define ATTN_SMEM (2 * 2 * TILE_E * 2)   // 36864 (K,V single fp16, 2 bufs)

// out-proj GEMM smem
#define ASTR 40
#define BSTR 136
#define GBUF 18944
#define GSMEM (2 * GBUF * 2)             // 75776

// QKV blocked GEMM smem
#define QK_SMEM (1024 + 2 * 32768)       // 66560

// Scratch (allocation-free: __device__ globals)
__device__ __align__(16) __nv_bfloat16 g_xhB[(size_t)M_ROWS * EMB];
__device__ __align__(16) __nv_bfloat16 g_xlB[(size_t)M_ROWS * EMB];
__device__ __align__(16) __nv_bfloat16 g_WqhB[(size_t)EMB * N_QKV];
__device__ __align__(16) __nv_bfloat16 g_WqlB[(size_t)EMB * N_QKV];
__device__ __align__(16) __nv_bfloat16 g_Woh[(size_t)EMB * EMB];
__device__ __align__(16) __nv_bfloat16 g_Wol[(size_t)EMB * EMB];
// Q pre-scaled by 0.125, hi/lo; K,V single fp16. All [B,H,S,Dh].
__device__ __align__(16) __half g_Qh[(size_t)BATCH * NH * S_LEN * DH];
__device__ __align__(16) __half g_Ql[(size_t)BATCH * NH * S_LEN * DH];
__device__ __align__(16) __half g_Kh[(size_t)BATCH * NH * S_LEN * DH];
__device__ __align__(16) __half g_Vh[(size_t)BATCH * NH * S_LEN * DH];
// attention output split [B,S,E] (bf16, feeds out-proj)
__device__ __align__(16) __nv_bfloat16 g_atth[(size_t)M_ROWS * EMB];
__device__ __align__(16) __nv_bfloat16 g_attl[(size_t)M_ROWS * EMB];

__device__ __forceinline__ void split2(float x, float y, uint32_t& h, uint32_t& l)
{
    __nv_bfloat16 hx = __float2bfloat16(x);
    __nv_bfloat16 hy = __float2bfloat16(y);
    __nv_bfloat162 hh; hh.x = hx; hh.y = hy;
    __nv_bfloat162 ll;
    ll.x = __float2bfloat16(x - __bfloat162float(hx));
    ll.y = __float2bfloat16(y - __bfloat162float(hy));
    h = *(uint32_t*)&hh;
    l = *(uint32_t*)&ll;
}

__device__ __forceinline__ void split2h(float x, float y, uint32_t& h, uint32_t& l)
{
    __half hx = __float2half_rn(x);
    __half hy = __float2half_rn(y);
    __half2 hh; hh.x = hx; hh.y = hy;
    __half2 ll;
    ll.x = __float2half_rn(x - __half2float(hx));
    ll.y = __float2half_rn(y - __half2float(hy));
    h = *(uint32_t*)&hh;
    l = *(uint32_t*)&ll;
}

__device__ __forceinline__ void mma16816(float c[4], const uint32_t a[4],
                                         const uint32_t* b)
{
    asm volatile(
        "mma.sync.aligned.m16n8k16.row.col.f32.bf16.bf16.f32 "
        "{%0,%1,%2,%3}, {%4,%5,%6,%7}, {%8,%9}, {%0,%1,%2,%3};\n"
        : "+f"(c[0]), "+f"(c[1]), "+f"(c[2]), "+f"(c[3])
        : "r"(a[0]), "r"(a[1]), "r"(a[2]), "r"(a[3]), "r"(b[0]), "r"(b[1]));
}

__device__ __forceinline__ void mma16816h(float c[4], const uint32_t a[4],
                                          const uint32_t* b)
{
    asm volatile(
        "mma.sync.aligned.m16n8k16.row.col.f32.f16.f16.f32 "
        "{%0,%1,%2,%3}, {%4,%5,%6,%7}, {%8,%9}, {%0,%1,%2,%3};\n"
        : "+f"(c[0]), "+f"(c[1]), "+f"(c[2]), "+f"(c[3])
        : "r"(a[0]), "r"(a[1]), "r"(a[2]), "r"(a[3]), "r"(b[0]), "r"(b[1]));
}

__device__ __forceinline__ void ldsm4(uint32_t r[4], uint32_t addr)
{
    asm volatile("ldmatrix.sync.aligned.m8n8.x4.shared.b16 {%0,%1,%2,%3}, [%4];\n"
                 : "=r"(r[0]), "=r"(r[1]), "=r"(r[2]), "=r"(r[3]) : "r"(addr));
}

__device__ __forceinline__ void ldsm4t(uint32_t r[4], uint32_t addr)
{
    asm volatile("ldmatrix.sync.aligned.m8n8.x4.trans.shared.b16 {%0,%1,%2,%3}, [%4];\n"
                 : "=r"(r[0]), "=r"(r[1]), "=r"(r[2]), "=r"(r[3]) : "r"(addr));
}

__device__ __forceinline__ void cpasync16(uint32_t s, const void* g)
{
    asm volatile("cp.async.cg.shared.global [%0], [%1], 16;\n" :: "r"(s), "l"(g));
}

// ---- bulk copy + mbarrier helpers ----
__device__ __forceinline__ void bulk_g2s(uint32_t dst, const void* src,
                                         uint32_t bytes, uint32_t mbar)
{
    asm volatile(
        "cp.async.bulk.shared::cta.global.mbarrier::complete_tx::bytes "
        "[%0], [%1], %2, [%3];\n"
        :: "r"(dst), "l"(src), "r"(bytes), "r"(mbar) : "memory");
}

__device__ __forceinline__ void mbar_init(uint32_t mbar, uint32_t cnt)
{
    asm volatile("mbarrier.init.shared.b64 [%0], %1;" :: "r"(mbar), "r"(cnt) : "memory");
}

__device__ __forceinline__ void mbar_expect_tx(uint32_t mbar, uint32_t bytes)
{
    asm volatile("mbarrier.arrive.expect_tx.shared.b64 _, [%0], %1;"
                 :: "r"(mbar), "r"(bytes) : "memory");
}

__device__ __forceinline__ void mbar_wait(uint32_t mbar, uint32_t parity)
{
    uint32_t done;
    asm volatile(
        "{\n\t.reg .pred p;\n\t"
        "mbarrier.try_wait.parity.acquire.cta.shared::cta.b64 p, [%1], %2;\n\t"
        "selp.b32 %0, 1, 0, p;\n\t}"
        : "=r"(done) : "r"(mbar), "r"(parity) : "memory");
    if (!done) {
        asm volatile(
            "{\n\t.reg .pred P1;\n\t"
            "WL_%=:\n\t"
            "mbarrier.try_wait.parity.acquire.cta.shared::cta.b64 P1, [%0], %1, 0x989680;\n\t"
            "@P1 bra.uni WD_%=;\n\t"
            "bra.uni WL_%=;\n\t"
            "WD_%=:\n\t}"
            :: "r"(mbar), "r"(parity) : "memory");
    }
}

__device__ __forceinline__ uint32_t smem_u32(const void* p)
{
    uint32_t a;
    asm("{ .reg .u64 t; cvta.to.shared.u64 t, %1; cvt.u32.u64 %0, t; }"
        : "=r"(a) : "l"(p));
    return a;
}

// ---------------------------------------------------------------------------
// Splits
// ---------------------------------------------------------------------------
__global__ __launch_bounds__(256) void split_kernel(
    const float* __restrict__ src, __nv_bfloat16* __restrict__ h,
    __nv_bfloat16* __restrict__ l, int n2)
{
    const int idx = blockIdx.x * 256 + threadIdx.x;
    if (idx >= n2) return;
    const float2 v = ((const float2*)src)[idx];
    uint32_t hh, ll;
    split2(v.x, v.y, hh, ll);
    ((uint32_t*)h)[idx] = hh;
    ((uint32_t*)l)[idx] = ll;
}

__global__ __launch_bounds__(256) void splitA_blk_kernel(const float* __restrict__ x)
{
    const int idx = blockIdx.x * 256 + threadIdx.x;
    const int row = idx >> 6;
    const int cu = idx & 63;
    const int kc = cu >> 2;
    const int u = cu & 3;
    const int by = row >> 7;
    const int r = row & 127;
    const int up = (u + (r >> 1)) & 3;
    const size_t off = (size_t)(by * 16 + kc) * 4096 + r * 32 + up * 8;

    const float4 a0 = *(const float4*)(x + (size_t)row * 512 + cu * 8);
    const float4 a1 = *(const float4*)(x + (size_t)row * 512 + cu * 8 + 4);
    uint4 H, L;
    split2(a0.x, a0.y, H.x, L.x);
    split2(a0.z, a0.w, H.y, L.y);
    split2(a1.x, a1.y, H.z, L.z);
    split2(a1.z, a1.w, H.w, L.w);
    *(uint4*)(g_xhB + off) = H;
    *(uint4*)(g_xlB + off) = L;
}

__global__ __launch_bounds__(256) void splitB_blk_kernel(const float* __restrict__ W)
{
    const int idx = blockIdx.x * 256 + threadIdx.x;
    const int k = idx / 192;
    const int cu = idx - k * 192;
    const int bx = cu >> 4;
    const int u = cu & 15;
    const int kc = k >> 5;
    const int r = k & 31;
    const int up = (u & 8) | ((u & 7) ^ (r & 7));
    const size_t off = (size_t)(bx * 16 + kc) * 4096 + r * 128 + up * 8;

    const float4 a0 = *(const float4*)(W + (size_t)k * N_QKV + cu * 8);
    const float4 a1 = *(const float4*)(W + (size_t)k * N_QKV + cu * 8 + 4);
    uint4 H, L;
    split2(a0.x, a0.y, H.x, L.x);
    split2(a0.z, a0.w, H.y, L.y);
    split2(a1.x, a1.y, H.z, L.z);
    split2(a1.z, a1.w, H.w, L.w);
    *(uint4*)(g_WqhB + off) = H;
    *(uint4*)(g_WqlB + off) = L;
}

// ---------------------------------------------------------------------------
// QKV GEMM with cp.async.bulk fill (2 CTAs/SM).
// Epilogue: Q -> fp16 hi/lo (pre-scaled); K,V -> single fp16.
// ---------------------------------------------------------------------------
__global__ __launch_bounds__(256, 2) void gemm_qkv_blk_kernel(
    const float* __restrict__ bias)
{
    extern __shared__ __align__(1024) char sq[];
    const uint32_t sb = smem_u32(sq);
    const int tid = threadIdx.x;
    const int bx = blockIdx.x, by = blockIdx.y;
    const int lane = tid & 31, warp = tid >> 5;
    const int wm = warp & 3, wn = warp >> 2;
    const int qr = lane >> 2, qc = lane & 3;
    const int g = lane >> 3, rr = lane & 7;

    float acc[2][8][4];
#pragma unroll
    for (int i = 0; i < 2; i++)
#pragma unroll
        for (int j = 0; j < 8; j++)
#pragma unroll
            for (int e = 0; e < 4; e++) acc[i][j][e] = 0.f;

    if (tid == 0) { mbar_init(sb, 1); mbar_init(sb + 16, 1); }
    __syncthreads();

    auto fill = [&](int kc) {
        const int buf = kc & 1;
        const uint32_t mb = sb + buf * 16;
        const uint32_t dst = sb + 1024 + buf * 32768;
        mbar_expect_tx(mb, 32768);
        bulk_g2s(dst,         g_xhB + (size_t)(by * 16 + kc) * 4096, 8192, mb);
        bulk_g2s(dst + 8192,  g_xlB + (size_t)(by * 16 + kc) * 4096, 8192, mb);
        bulk_g2s(dst + 16384, g_WqhB + (size_t)(bx * 16 + kc) * 4096, 8192, mb);
        bulk_g2s(dst + 24576, g_WqlB + (size_t)(bx * 16 + kc) * 4096, 8192, mb);
    };

    if (tid == 0) fill(0);

    for (int kc = 0; kc < 16; kc++) {
        if (kc + 1 < 16 && tid == 0) fill(kc + 1);
        mbar_wait(sb + (kc & 1) * 16, (kc >> 1) & 1);

        const uint32_t base = sb + 1024 + (kc & 1) * 32768;
        const uint32_t Ah_s = base;
        const uint32_t Al_s = base + 8192;
        const uint32_t Bh_s = base + 16384;
        const uint32_t Bl_s = base + 24576;

#pragma unroll
        for (int s = 0; s < 2; s++) {
            uint32_t afh[2][4], afl[2][4];
#pragma unroll
            for (int i = 0; i < 2; i++) {
                const int ar = wm * 32 + i * 16 + (lane & 15);
                const int au = s * 2 + (lane >> 4);
                const int aup = (au + (ar >> 1)) & 3;
                const uint32_t off = ar * 64 + aup * 16;
                ldsm4(afh[i], Ah_s + off);
                ldsm4(afl[i], Al_s + off);
            }
#pragma unroll
            for (int jp = 0; jp < 4; jp++) {
                const int br = s * 16 + 8 * (g & 1) + rr;
                const int bu = wn * 8 + jp * 2 + (g >> 1);
                const int bup = (bu & 8) | ((bu & 7) ^ (br & 7));
                const uint32_t off = br * 256 + bup * 16;
                uint32_t bh4[4], bl4[4];
                ldsm4t(bh4, Bh_s + off);
                ldsm4t(bl4, Bl_s + off);
#pragma unroll
                for (int i = 0; i < 2; i++) {
                    mma16816(acc[i][2 * jp],     afh[i], &bh4[0]);
                    mma16816(acc[i][2 * jp],     afh[i], &bl4[0]);
                    mma16816(acc[i][2 * jp],     afl[i], &bh4[0]);
                    mma16816(acc[i][2 * jp + 1], afh[i], &bh4[2]);
                    mma16816(acc[i][2 * jp + 1], afh[i], &bl4[2]);
                    mma16816(acc[i][2 * jp + 1], afl[i], &bh4[2]);
                }
            }
        }
        __syncthreads();
    }

    // Epilogue: bias; Q: scale + fp16 split; K/V: single fp16
#pragma unroll
    for (int i = 0; i < 2; i++) {
        const int row0 = by * 128 + wm * 32 + i * 16 + qr;
        const int b = row0 >> 12;
        const int s0 = row0 & 4095;
#pragma unroll
        for (int j = 0; j < 8; j++) {
            const int col = bx * 128 + wn * 64 + j * 8 + 2 * qc;
            float v0 = acc[i][j][0] + bias[col];
            float v1 = acc[i][j][1] + bias[col + 1];
            float v2 = acc[i][j][2] + bias[col];
            float v3 = acc[i][j][3] + bias[col + 1];
            const int which = col >> 9;
            const int e = col & 511;
            const int h = e >> 6;
            const int d = e & 63;
            const size_t dst0 = (((size_t)(b * NH + h) * S_LEN) + s0) * DH + d;
            const size_t dst1 = dst0 + (size_t)8 * DH;
            if (which == 0) {
                v0 *= 0.125f; v1 *= 0.125f; v2 *= 0.125f; v3 *= 0.125f;
                uint32_t hh, ll;
                split2h(v0, v1, hh, ll);
                *(uint32_t*)&g_Qh[dst0] = hh;
                *(uint32_t*)&g_Ql[dst0] = ll;
                split2h(v2, v3, hh, ll);
                *(uint32_t*)&g_Qh[dst1] = hh;
                *(uint32_t*)&g_Ql[dst1] = ll;
            } else {
                __half* ph = (which == 1) ? g_Kh : g_Vh;
                __half2 h0 = __floats2half2_rn(v0, v1);
                __half2 h1 = __floats2half2_rn(v2, v3);
                *(uint32_t*)&ph[dst0] = *(uint32_t*)&h0;
                *(uint32_t*)&ph[dst1] = *(uint32_t*)&h1;
            }
        }
    }
}

// ---------------------------------------------------------------------------
// Out-projection GEMM (unchanged; 2 CTAs/SM)
// ---------------------------------------------------------------------------
__global__ __launch_bounds__(256, 2) void gemm_bf3_kernel(
    const __nv_bfloat16* __restrict__ Ah, const __nv_bfloat16* __restrict__ Al,
    const __nv_bfloat16* __restrict__ Bh, const __nv_bfloat16* __restrict__ Bl,
    const float* __restrict__ bias, float* __restrict__ C,
    int N, int K)
{
    extern __shared__ __align__(16) __nv_bfloat16 sg[];
    const int tid  = threadIdx.x;
    const int bx = blockIdx.x, by = blockIdx.y;
    const int lane = tid & 31, warp = tid >> 5;
    const int wm = warp & 3, wn = warp >> 2;
    const int qr = lane >> 2, qc = lane & 3;
    const int g = lane >> 3, rr = lane & 7;
    const uint32_t sb = (uint32_t)__cvta_generic_to_shared(sg);

    float acc[2][8][4];
#pragma unroll
    for (int i = 0; i < 2; i++)
#pragma unroll
        for (int j = 0; j < 8; j++)
#pragma unroll
            for (int e = 0; e < 4; e++) acc[i][j][e] = 0.f;

    auto fill = [&](int kc, int buf) {
        const int k0 = kc * 32;
        const uint32_t base = sb + buf * GBUF * 2;
#pragma unroll
        for (int t = 0; t < 4; t++) {
            const int idx = t * 256 + tid;
            const int arr = idx >> 9;
            const int rem = idx & 511;
            const int row = rem >> 2, c = rem & 3;
            const __nv_bfloat16* src =
                (arr ? Al : Ah) + (size_t)(by * 128 + row) * K + k0 + c * 8;
            cpasync16(base + (arr * 5120 + row * ASTR + c * 8) * 2, src);
        }
#pragma unroll
        for (int t = 0; t < 4; t++) {
            const int idx = t * 256 + tid;
            const int arr = idx >> 9;
            const int rem = idx & 511;
            const int row = rem >> 4, c = rem & 15;
            const __nv_bfloat16* src =
                (arr ? Bl : Bh) + (size_t)(k0 + row) * N + bx * 128 + c * 8;
            cpasync16(base + (10240 + arr * 4352 + row * BSTR + c * 8) * 2, src);
        }
        asm volatile("cp.async.commit_group;\n");
    };

    fill(0, 0);
    const int nkc = K / 32;

    for (int kc = 0; kc < nkc; kc++) {
        const int buf = kc & 1;
        asm volatile("cp.async.wait_group 0;\n");
        __syncthreads();
        if (kc + 1 < nkc) fill(kc + 1, buf ^ 1);

        const uint32_t base = sb + buf * GBUF * 2;
        const uint32_t Ah_s = base;
        const uint32_t Al_s = base + 5120 * 2;
        const uint32_t Bh_s = base + 10240 * 2;
        const uint32_t Bl_s = base + 14592 * 2;

#pragma unroll
        for (int s = 0; s < 2; s++) {
            uint32_t afh[2][4], afl[2][4];
#pragma unroll
            for (int i = 0; i < 2; i++) {
                const uint32_t off =
                    ((wm * 32 + i * 16 + (lane & 15)) * ASTR
                     + s * 16 + 8 * (lane >> 4)) * 2;
                ldsm4(afh[i], Ah_s + off);
                ldsm4(afl[i], Al_s + off);
            }
#pragma unroll
            for (int jp = 0; jp < 4; jp++) {
                const uint32_t off =
                    ((s * 16 + 8 * (g & 1) + rr) * BSTR
                     + wn * 64 + jp * 16 + 8 * (g >> 1)) * 2;
                uint32_t bh4[4], bl4[4];
                ldsm4t(bh4, Bh_s + off);
                ldsm4t(bl4, Bl_s + off);
#pragma unroll
                for (int i = 0; i < 2; i++) {
                    mma16816(acc[i][2 * jp],     afh[i], &bh4[0]);
                    mma16816(acc[i][2 * jp],     afh[i], &bl4[0]);
                    mma16816(acc[i][2 * jp],     afl[i], &bh4[0]);
                    mma16816(acc[i][2 * jp + 1], afh[i], &bh4[2]);
                    mma16816(acc[i][2 * jp + 1], afh[i], &bl4[2]);
                    mma16816(acc[i][2 * jp + 1], afl[i], &bh4[2]);
                }
            }
        }
        __syncthreads();
    }

#pragma unroll
    for (int i = 0; i < 2; i++) {
        const int row0 = by * 128 + wm * 32 + i * 16 + qr;
#pragma unroll
        for (int j = 0; j < 8; j++) {
            const int col = bx * 128 + wn * 64 + j * 8 + 2 * qc;
            float2 v0 = make_float2(acc[i][j][0] + bias[col],
                                    acc[i][j][1] + bias[col + 1]);
            float2 v1 = make_float2(acc[i][j][2] + bias[col],
                                    acc[i][j][3] + bias[col + 1]);
            *(float2*)(C + (size_t)row0 * N + col) = v0;
            *(float2*)(C + (size_t)(row0 + 8) * N + col) = v1;
        }
    }
}

// ---------------------------------------------------------------------------
// Tensor-core flash attention: Q fp16 hi/lo (2-term QK), K/V single fp16.
// ---------------------------------------------------------------------------
__global__ __launch_bounds__(256) void attn_mma_kernel()
{
    extern __shared__ __align__(16) __half sm[];

    const int tid  = threadIdx.x;
    const int warp = tid >> 5;
    const int lane = tid & 31;
    const int qt = blockIdx.x;
    const int bh = blockIdx.y;
    const int rowbase = qt * 128;
    const int qr = lane >> 2;
    const int qc = lane & 3;
    const int g  = lane >> 3;
    const int rr = lane & 7;

    const uint32_t smem_base = (uint32_t)__cvta_generic_to_shared(sm);

    const __half* srcs[2] = {
        g_Kh + (size_t)bh * S_LEN * DH,
        g_Vh + (size_t)bh * S_LEN * DH };

    uint32_t Qah[4][4], Qal[4][4];
    {
        const size_t qoff = ((size_t)bh * S_LEN + rowbase + warp * 16) * DH;
#pragma unroll
        for (int s = 0; s < 4; s++)
#pragma unroll
            for (int e = 0; e < 4; e++) {
                const int r = qr + 8 * (e & 1);
                const int c = 16 * s + 2 * qc + 8 * (e >> 1);
                Qah[s][e] = *(const uint32_t*)(g_Qh + qoff + (size_t)r * DH + c);
                Qal[s][e] = *(const uint32_t*)(g_Ql + qoff + (size_t)r * DH + c);
            }
    }

    float O[8][4];
#pragma unroll
    for (int j = 0; j < 8; j++)
#pragma unroll
        for (int e = 0; e < 4; e++) O[j][e] = 0.f;
    float m0 = -1e30f, m1 = -1e30f, l0 = 0.f, l1 = 0.f;

    const int nT = qt * 2 + 2;

    auto fill = [&](int kt, int buf) {
#pragma unroll
        for (int i = 0; i < 4; i++) {
            const int arr = i >> 1;                 // 0=K, 1=V
            const int e = ((i & 1) << 8) + tid;     // 0..511
            const int row = e >> 3;
            const int grp = e & 7;
            const __half* src = srcs[arr] + (size_t)kt * 64 * DH
                              + (size_t)row * DH + grp * 8;
            const uint32_t dst = smem_base +
                ((arr * 2 + buf) * TILE_E + row * KSTR + grp * 8) * 2;
            cpasync16(dst, src);
        }
        asm volatile("cp.async.commit_group;\n");
    };

    fill(0, 0);

    for (int kt = 0; kt < nT; kt++) {
        const int buf = kt & 1;
        asm volatile("cp.async.wait_group 0;\n");
        __syncthreads();
        if (kt + 1 < nT) fill(kt + 1, buf ^ 1);

        const uint32_t K_t = smem_base + ((0 * 2 + buf) * TILE_E) * 2;
        const uint32_t V_t = smem_base + ((1 * 2 + buf) * TILE_E) * 2;

        // S = Q K^T  (Q hi/lo exact, K fp16: 2 MMAs per col-half)
        float S[8][4];
#pragma unroll
        for (int j = 0; j < 8; j++)
#pragma unroll
            for (int e = 0; e < 4; e++) S[j][e] = 0.f;

#pragma unroll
        for (int s = 0; s < 4; s++) {
#pragma unroll
            for (int jp = 0; jp < 4; jp++) {
                const uint32_t off = ((16 * jp + 8 * (g >> 1) + rr) * KSTR
                                    + 16 * s + 8 * (g & 1)) * 2;
                uint32_t bv[4];
                ldsm4(bv, K_t + off);
                mma16816h(S[2 * jp],     Qah[s], &bv[0]);
                mma16816h(S[2 * jp],     Qal[s], &bv[0]);
                mma16816h(S[2 * jp + 1], Qah[s], &bv[2]);
                mma16816h(S[2 * jp + 1], Qal[s], &bv[2]);
            }
        }

        const int grow0 = rowbase + warp * 16 + qr;
        if (kt * 64 + 63 > rowbase + warp * 16) {
#pragma unroll
            for (int j = 0; j < 8; j++)
#pragma unroll
                for (int e = 0; e < 4; e++) {
                    const int col = kt * 64 + 8 * j + 2 * qc + (e & 1);
                    const int row = grow0 + 8 * (e >> 1);
                    if (col > row) S[j][e] = -1e30f;
                }
        }

        float mx0 = -1e30f, mx1 = -1e30f;
#pragma unroll
        for (int j = 0; j < 8; j++) {
            mx0 = fmaxf(mx0, fmaxf(S[j][0], S[j][1]));
            mx1 = fmaxf(mx1, fmaxf(S[j][2], S[j][3]));
        }
        mx0 = fmaxf(mx0, __shfl_xor_sync(0xffffffffu, mx0, 1));
        mx0 = fmaxf(mx0, __shfl_xor_sync(0xffffffffu, mx0, 2));
        mx1 = fmaxf(mx1, __shfl_xor_sync(0xffffffffu, mx1, 1));
        mx1 = fmaxf(mx1, __shfl_xor_sync(0xffffffffu, mx1, 2));

        const float nm0 = fmaxf(m0, mx0);
        const float nm1 = fmaxf(m1, mx1);
        const float c0 = __expf(m0 - nm0);
        const float c1 = __expf(m1 - nm1);
        m0 = nm0; m1 = nm1;

        float s0 = 0.f, s1 = 0.f;
#pragma unroll
        for (int j = 0; j < 8; j++) {
            S[j][0] = __expf(S[j][0] - m0); s0 += S[j][0];
            S[j][1] = __expf(S[j][1] - m0); s0 += S[j][1];
            S[j][2] = __expf(S[j][2] - m1); s1 += S[j][2];
            S[j][3] = __expf(S[j][3] - m1); s1 += S[j][3];
        }
        s0 += __shfl_xor_sync(0xffffffffu, s0, 1);
        s0 += __shfl_xor_sync(0xffffffffu, s0, 2);
        s1 += __shfl_xor_sync(0xffffffffu, s1, 1);
        s1 += __shfl_xor_sync(0xffffffffu, s1, 2);
        l0 = l0 * c0 + s0;
        l1 = l1 * c1 + s1;
#pragma unroll
        for (int j = 0; j < 8; j++) {
            O[j][0] *= c0; O[j][1] *= c0;
            O[j][2] *= c1; O[j][3] *= c1;
        }

        // O += P V  (P fp16, V fp16: 1 MMA per col-half)
#pragma unroll
        for (int s = 0; s < 4; s++) {
            uint32_t Pa[4];
            {
                __half2 p0 = __floats2half2_rn(S[2 * s][0],     S[2 * s][1]);
                __half2 p1 = __floats2half2_rn(S[2 * s][2],     S[2 * s][3]);
                __half2 p2 = __floats2half2_rn(S[2 * s + 1][0], S[2 * s + 1][1]);
                __half2 p3 = __floats2half2_rn(S[2 * s + 1][2], S[2 * s + 1][3]);
                Pa[0] = *(uint32_t*)&p0;
                Pa[1] = *(uint32_t*)&p1;
                Pa[2] = *(uint32_t*)&p2;
                Pa[3] = *(uint32_t*)&p3;
            }
#pragma unroll
            for (int jp = 0; jp < 4; jp++) {
                const uint32_t off = ((16 * s + 8 * (g & 1) + rr) * KSTR
                                    + 16 * jp + 8 * (g >> 1)) * 2;
                uint32_t bv[4];
                ldsm4t(bv, V_t + off);
                mma16816h(O[2 * jp],     Pa, &bv[0]);
                mma16816h(O[2 * jp + 1], Pa, &bv[2]);
            }
        }
        __syncthreads();
    }

    const float inv0 = 1.f / l0;
    const float inv1 = 1.f / l1;
    const int b = bh >> 3;
    const int h = bh & 7;
    const int row0 = rowbase + warp * 16 + qr;
    const int row1 = row0 + 8;
#pragma unroll
    for (int j = 0; j < 8; j++) {
        const int col = h * DH + 8 * j + 2 * qc;
        uint32_t hh, ll;
        const size_t o0 = ((size_t)b * S_LEN + row0) * EMB + col;
        split2(O[j][0] * inv0, O[j][1] * inv0, hh, ll);
        *(uint32_t*)&g_atth[o0] = hh;
        *(uint32_t*)&g_attl[o0] = ll;
        const size_t o1 = ((size_t)b * S_LEN + row1) * EMB + col;
        split2(O[j][2] * inv1, O[j][3] * inv1, hh, ll);
        *(uint32_t*)&g_atth[o1] = hh;
        *(uint32_t*)&g_attl[o1] = ll;
    }
}

// ---------------------------------------------------------------------------
extern "C" void kernel_launch(void* const* d_in, const int* in_sizes, int n_in,
                              void* d_out, int out_size)
{
    const float* x    = (const float*)d_in[0];
    const float* Wqkv = (const float*)d_in[1];
    const float* bqkv = (const float*)d_in[2];
    const float* Wo   = (const float*)d_in[3];
    const float* bo   = (const float*)d_in[4];
    for (int i = 0; i < n_in; i++) {
        switch (in_sizes[i]) {
            case 8388608: x    = (const float*)d_in[i]; break;
            case 786432:  Wqkv = (const float*)d_in[i]; break;
            case 1536:    bqkv = (const float*)d_in[i]; break;
            case 262144:  Wo   = (const float*)d_in[i]; break;
            case 512:     bo   = (const float*)d_in[i]; break;
        }
    }
    float* out = (float*)d_out;

    static bool init = false;
    static __nv_bfloat16 *p_Woh, *p_Wol, *p_ath, *p_atl;
    if (!init) {
        void* t;
        cudaGetSymbolAddress(&t, g_Woh);   p_Woh = (__nv_bfloat16*)t;
        cudaGetSymbolAddress(&t, g_Wol);   p_Wol = (__nv_bfloat16*)t;
        cudaGetSymbolAddress(&t, g_atth);  p_ath = (__nv_bfloat16*)t;
        cudaGetSymbolAddress(&t, g_attl);  p_atl = (__nv_bfloat16*)t;
        cudaFuncSetAttribute(attn_mma_kernel,
                             cudaFuncAttributeMaxDynamicSharedMemorySize,
                             ATTN_SMEM);
        cudaFuncSetAttribute(gemm_bf3_kernel,
                             cudaFuncAttributeMaxDynamicSharedMemorySize,
                             GSMEM);
        cudaFuncSetAttribute(gemm_qkv_blk_kernel,
                             cudaFuncAttributeMaxDynamicSharedMemorySize,
                             QK_SMEM);
        init = true;
    }

    // 0) splits
    splitA_blk_kernel<<<M_ROWS * EMB / 8 / 256, 256>>>(x);
    splitB_blk_kernel<<<EMB * N_QKV / 8 / 256, 256>>>(Wqkv);
    split_kernel<<<(EMB * EMB / 2 + 255) / 256, 256>>>(Wo, p_Woh, p_Wol,
                                                       EMB * EMB / 2);

    // 1) QKV projection
    gemm_qkv_blk_kernel<<<dim3(N_QKV / 128, M_ROWS / 128), 256, QK_SMEM>>>(bqkv);

    // 2) Attention
    attn_mma_kernel<<<dim3(S_LEN / 128, BATCH * NH), 256, ATTN_SMEM>>>();

    // 3) Output projection
    gemm_bf3_kernel<<<dim3(EMB / 128, M_ROWS / 128), 256, GSMEM>>>(
        p_ath, p_atl, p_Woh, p_Wol, bo, out, EMB, EMB);
}

// round 13
// speedup vs baseline: 12.7893x; 1.1348x over previous
#include <cuda_runtime.h>
#include <cuda_bf16.h>
#include <cuda_fp16.h>
#include <math.h>
#include <stdint.h>

#define S_LEN 4096
#define EMB   512
#define NH    8
#define DH    64
#define BATCH 4
#define M_ROWS (BATCH * S_LEN)          // 16384
#define N_QKV  (3 * EMB)                // 1536
#define KSTR   72                        // attn smem stride (64 + 8 pad)
#define TILE_E (64 * KSTR)
#define ATTN_SMEM (2 * 2 * TILE_E * 2)   // 36864 (K,V single fp16, 2 bufs)

// out-proj GEMM smem
#define ASTR 40
#define BSTR 136
#define GBUF 18944
#define GSMEM (2 * GBUF * 2)             // 75776

// QKV blocked GEMM smem
#define QK_SMEM (1024 + 2 * 32768)       // 66560

// Scratch (allocation-free: __device__ globals)
__device__ __align__(16) __nv_bfloat16 g_xhB[(size_t)M_ROWS * EMB];
__device__ __align__(16) __nv_bfloat16 g_xlB[(size_t)M_ROWS * EMB];
__device__ __align__(16) __nv_bfloat16 g_WqhB[(size_t)EMB * N_QKV];
__device__ __align__(16) __nv_bfloat16 g_WqlB[(size_t)EMB * N_QKV];
__device__ __align__(16) __nv_bfloat16 g_Woh[(size_t)EMB * EMB];
__device__ __align__(16) __nv_bfloat16 g_Wol[(size_t)EMB * EMB];
// Q pre-scaled by 0.125; Q,K,V single fp16. All [B,H,S,Dh].
__device__ __align__(16) __half g_Qh[(size_t)BATCH * NH * S_LEN * DH];
__device__ __align__(16) __half g_Kh[(size_t)BATCH * NH * S_LEN * DH];
__device__ __align__(16) __half g_Vh[(size_t)BATCH * NH * S_LEN * DH];
// attention output split [B,S,E] (bf16, feeds out-proj)
__device__ __align__(16) __nv_bfloat16 g_atth[(size_t)M_ROWS * EMB];
__device__ __align__(16) __nv_bfloat16 g_attl[(size_t)M_ROWS * EMB];

__device__ __forceinline__ void split2(float x, float y, uint32_t& h, uint32_t& l)
{
    __nv_bfloat16 hx = __float2bfloat16(x);
    __nv_bfloat16 hy = __float2bfloat16(y);
    __nv_bfloat162 hh; hh.x = hx; hh.y = hy;
    __nv_bfloat162 ll;
    ll.x = __float2bfloat16(x - __bfloat162float(hx));
    ll.y = __float2bfloat16(y - __bfloat162float(hy));
    h = *(uint32_t*)&hh;
    l = *(uint32_t*)&ll;
}

__device__ __forceinline__ void mma16816(float c[4], const uint32_t a[4],
                                         const uint32_t* b)
{
    asm volatile(
        "mma.sync.aligned.m16n8k16.row.col.f32.bf16.bf16.f32 "
        "{%0,%1,%2,%3}, {%4,%5,%6,%7}, {%8,%9}, {%0,%1,%2,%3};\n"
        : "+f"(c[0]), "+f"(c[1]), "+f"(c[2]), "+f"(c[3])
        : "r"(a[0]), "r"(a[1]), "r"(a[2]), "r"(a[3]), "r"(b[0]), "r"(b[1]));
}

__device__ __forceinline__ void mma16816h(float c[4], const uint32_t a[4],
                                          const uint32_t* b)
{
    asm volatile(
        "mma.sync.aligned.m16n8k16.row.col.f32.f16.f16.f32 "
        "{%0,%1,%2,%3}, {%4,%5,%6,%7}, {%8,%9}, {%0,%1,%2,%3};\n"
        : "+f"(c[0]), "+f"(c[1]), "+f"(c[2]), "+f"(c[3])
        : "r"(a[0]), "r"(a[1]), "r"(a[2]), "r"(a[3]), "r"(b[0]), "r"(b[1]));
}

__device__ __forceinline__ void ldsm4(uint32_t r[4], uint32_t addr)
{
    asm volatile("ldmatrix.sync.aligned.m8n8.x4.shared.b16 {%0,%1,%2,%3}, [%4];\n"
                 : "=r"(r[0]), "=r"(r[1]), "=r"(r[2]), "=r"(r[3]) : "r"(addr));
}

__device__ __forceinline__ void ldsm4t(uint32_t r[4], uint32_t addr)
{
    asm volatile("ldmatrix.sync.aligned.m8n8.x4.trans.shared.b16 {%0,%1,%2,%3}, [%4];\n"
                 : "=r"(r[0]), "=r"(r[1]), "=r"(r[2]), "=r"(r[3]) : "r"(addr));
}

__device__ __forceinline__ void cpasync16(uint32_t s, const void* g)
{
    asm volatile("cp.async.cg.shared.global [%0], [%1], 16;\n" :: "r"(s), "l"(g));
}

// ---- bulk copy + mbarrier helpers ----
__device__ __forceinline__ void bulk_g2s(uint32_t dst, const void* src,
                                         uint32_t bytes, uint32_t mbar)
{
    asm volatile(
        "cp.async.bulk.shared::cta.global.mbarrier::complete_tx::bytes "
        "[%0], [%1], %2, [%3];\n"
        :: "r"(dst), "l"(src), "r"(bytes), "r"(mbar) : "memory");
}

__device__ __forceinline__ void mbar_init(uint32_t mbar, uint32_t cnt)
{
    asm volatile("mbarrier.init.shared.b64 [%0], %1;" :: "r"(mbar), "r"(cnt) : "memory");
}

__device__ __forceinline__ void mbar_expect_tx(uint32_t mbar, uint32_t bytes)
{
    asm volatile("mbarrier.arrive.expect_tx.shared.b64 _, [%0], %1;"
                 :: "r"(mbar), "r"(bytes) : "memory");
}

__device__ __forceinline__ void mbar_wait(uint32_t mbar, uint32_t parity)
{
    uint32_t done;
    asm volatile(
        "{\n\t.reg .pred p;\n\t"
        "mbarrier.try_wait.parity.acquire.cta.shared::cta.b64 p, [%1], %2;\n\t"
        "selp.b32 %0, 1, 0, p;\n\t}"
        : "=r"(done) : "r"(mbar), "r"(parity) : "memory");
    if (!done) {
        asm volatile(
            "{\n\t.reg .pred P1;\n\t"
            "WL_%=:\n\t"
            "mbarrier.try_wait.parity.acquire.cta.shared::cta.b64 P1, [%0], %1, 0x989680;\n\t"
            "@P1 bra.uni WD_%=;\n\t"
            "bra.uni WL_%=;\n\t"
            "WD_%=:\n\t}"
            :: "r"(mbar), "r"(parity) : "memory");
    }
}

__device__ __forceinline__ uint32_t smem_u32(const void* p)
{
    uint32_t a;
    asm("{ .reg .u64 t; cvta.to.shared.u64 t, %1; cvt.u32.u64 %0, t; }"
        : "=r"(a) : "l"(p));
    return a;
}

// ---------------------------------------------------------------------------
// Splits
// ---------------------------------------------------------------------------
__global__ __launch_bounds__(256) void split_kernel(
    const float* __restrict__ src, __nv_bfloat16* __restrict__ h,
    __nv_bfloat16* __restrict__ l, int n2)
{
    const int idx = blockIdx.x * 256 + threadIdx.x;
    if (idx >= n2) return;
    const float2 v = ((const float2*)src)[idx];
    uint32_t hh, ll;
    split2(v.x, v.y, hh, ll);
    ((uint32_t*)h)[idx] = hh;
    ((uint32_t*)l)[idx] = ll;
}

__global__ __launch_bounds__(256) void splitA_blk_kernel(const float* __restrict__ x)
{
    const int idx = blockIdx.x * 256 + threadIdx.x;
    const int row = idx >> 6;
    const int cu = idx & 63;
    const int kc = cu >> 2;
    const int u = cu & 3;
    const int by = row >> 7;
    const int r = row & 127;
    const int up = (u + (r >> 1)) & 3;
    const size_t off = (size_t)(by * 16 + kc) * 4096 + r * 32 + up * 8;

    const float4 a0 = *(const float4*)(x + (size_t)row * 512 + cu * 8);
    const float4 a1 = *(const float4*)(x + (size_t)row * 512 + cu * 8 + 4);
    uint4 H, L;
    split2(a0.x, a0.y, H.x, L.x);
    split2(a0.z, a0.w, H.y, L.y);
    split2(a1.x, a1.y, H.z, L.z);
    split2(a1.z, a1.w, H.w, L.w);
    *(uint4*)(g_xhB + off) = H;
    *(uint4*)(g_xlB + off) = L;
}

__global__ __launch_bounds__(256) void splitB_blk_kernel(const float* __restrict__ W)
{
    const int idx = blockIdx.x * 256 + threadIdx.x;
    const int k = idx / 192;
    const int cu = idx - k * 192;
    const int bx = cu >> 4;
    const int u = cu & 15;
    const int kc = k >> 5;
    const int r = k & 31;
    const int up = (u & 8) | ((u & 7) ^ (r & 7));
    const size_t off = (size_t)(bx * 16 + kc) * 4096 + r * 128 + up * 8;

    const float4 a0 = *(const float4*)(W + (size_t)k * N_QKV + cu * 8);
    const float4 a1 = *(const float4*)(W + (size_t)k * N_QKV + cu * 8 + 4);
    uint4 H, L;
    split2(a0.x, a0.y, H.x, L.x);
    split2(a0.z, a0.w, H.y, L.y);
    split2(a1.x, a1.y, H.z, L.z);
    split2(a1.z, a1.w, H.w, L.w);
    *(uint4*)(g_WqhB + off) = H;
    *(uint4*)(g_WqlB + off) = L;
}

// ---------------------------------------------------------------------------
// QKV GEMM with cp.async.bulk fill (2 CTAs/SM).
// Epilogue: Q (scaled), K, V -> single fp16.
// ---------------------------------------------------------------------------
__global__ __launch_bounds__(256, 2) void gemm_qkv_blk_kernel(
    const float* __restrict__ bias)
{
    extern __shared__ __align__(1024) char sq[];
    const uint32_t sb = smem_u32(sq);
    const int tid = threadIdx.x;
    const int bx = blockIdx.x, by = blockIdx.y;
    const int lane = tid & 31, warp = tid >> 5;
    const int wm = warp & 3, wn = warp >> 2;
    const int qr = lane >> 2, qc = lane & 3;
    const int g = lane >> 3, rr = lane & 7;

    float acc[2][8][4];
#pragma unroll
    for (int i = 0; i < 2; i++)
#pragma unroll
        for (int j = 0; j < 8; j++)
#pragma unroll
            for (int e = 0; e < 4; e++) acc[i][j][e] = 0.f;

    if (tid == 0) { mbar_init(sb, 1); mbar_init(sb + 16, 1); }
    __syncthreads();

    auto fill = [&](int kc) {
        const int buf = kc & 1;
        const uint32_t mb = sb + buf * 16;
        const uint32_t dst = sb + 1024 + buf * 32768;
        mbar_expect_tx(mb, 32768);
        bulk_g2s(dst,         g_xhB + (size_t)(by * 16 + kc) * 4096, 8192, mb);
        bulk_g2s(dst + 8192,  g_xlB + (size_t)(by * 16 + kc) * 4096, 8192, mb);
        bulk_g2s(dst + 16384, g_WqhB + (size_t)(bx * 16 + kc) * 4096, 8192, mb);
        bulk_g2s(dst + 24576, g_WqlB + (size_t)(bx * 16 + kc) * 4096, 8192, mb);
    };

    if (tid == 0) fill(0);

    for (int kc = 0; kc < 16; kc++) {
        if (kc + 1 < 16 && tid == 0) fill(kc + 1);
        mbar_wait(sb + (kc & 1) * 16, (kc >> 1) & 1);

        const uint32_t base = sb + 1024 + (kc & 1) * 32768;
        const uint32_t Ah_s = base;
        const uint32_t Al_s = base + 8192;
        const uint32_t Bh_s = base + 16384;
        const uint32_t Bl_s = base + 24576;

#pragma unroll
        for (int s = 0; s < 2; s++) {
            uint32_t afh[2][4], afl[2][4];
#pragma unroll
            for (int i = 0; i < 2; i++) {
                const int ar = wm * 32 + i * 16 + (lane & 15);
                const int au = s * 2 + (lane >> 4);
                const int aup = (au + (ar >> 1)) & 3;
                const uint32_t off = ar * 64 + aup * 16;
                ldsm4(afh[i], Ah_s + off);
                ldsm4(afl[i], Al_s + off);
            }
#pragma unroll
            for (int jp = 0; jp < 4; jp++) {
                const int br = s * 16 + 8 * (g & 1) + rr;
                const int bu = wn * 8 + jp * 2 + (g >> 1);
                const int bup = (bu & 8) | ((bu & 7) ^ (br & 7));
                const uint32_t off = br * 256 + bup * 16;
                uint32_t bh4[4], bl4[4];
                ldsm4t(bh4, Bh_s + off);
                ldsm4t(bl4, Bl_s + off);
#pragma unroll
                for (int i = 0; i < 2; i++) {
                    mma16816(acc[i][2 * jp],     afh[i], &bh4[0]);
                    mma16816(acc[i][2 * jp],     afh[i], &bl4[0]);
                    mma16816(acc[i][2 * jp],     afl[i], &bh4[0]);
                    mma16816(acc[i][2 * jp + 1], afh[i], &bh4[2]);
                    mma16816(acc[i][2 * jp + 1], afh[i], &bl4[2]);
                    mma16816(acc[i][2 * jp + 1], afl[i], &bh4[2]);
                }
            }
        }
        __syncthreads();
    }

    // Epilogue: bias; Q scale; all -> single fp16
#pragma unroll
    for (int i = 0; i < 2; i++) {
        const int row0 = by * 128 + wm * 32 + i * 16 + qr;
        const int b = row0 >> 12;
        const int s0 = row0 & 4095;
#pragma unroll
        for (int j = 0; j < 8; j++) {
            const int col = bx * 128 + wn * 64 + j * 8 + 2 * qc;
            float v0 = acc[i][j][0] + bias[col];
            float v1 = acc[i][j][1] + bias[col + 1];
            float v2 = acc[i][j][2] + bias[col];
            float v3 = acc[i][j][3] + bias[col + 1];
            const int which = col >> 9;
            const int e = col & 511;
            const int h = e >> 6;
            const int d = e & 63;
            const size_t dst0 = (((size_t)(b * NH + h) * S_LEN) + s0) * DH + d;
            const size_t dst1 = dst0 + (size_t)8 * DH;
            if (which == 0) { v0 *= 0.125f; v1 *= 0.125f;
                              v2 *= 0.125f; v3 *= 0.125f; }
            __half* ph = (which == 0) ? g_Qh : (which == 1) ? g_Kh : g_Vh;
            __half2 h0 = __floats2half2_rn(v0, v1);
            __half2 h1 = __floats2half2_rn(v2, v3);
            *(uint32_t*)&ph[dst0] = *(uint32_t*)&h0;
            *(uint32_t*)&ph[dst1] = *(uint32_t*)&h1;
        }
    }
}

// ---------------------------------------------------------------------------
// Out-projection GEMM (unchanged; 2 CTAs/SM)
// ---------------------------------------------------------------------------
__global__ __launch_bounds__(256, 2) void gemm_bf3_kernel(
    const __nv_bfloat16* __restrict__ Ah, const __nv_bfloat16* __restrict__ Al,
    const __nv_bfloat16* __restrict__ Bh, const __nv_bfloat16* __restrict__ Bl,
    const float* __restrict__ bias, float* __restrict__ C,
    int N, int K)
{
    extern __shared__ __align__(16) __nv_bfloat16 sg[];
    const int tid  = threadIdx.x;
    const int bx = blockIdx.x, by = blockIdx.y;
    const int lane = tid & 31, warp = tid >> 5;
    const int wm = warp & 3, wn = warp >> 2;
    const int qr = lane >> 2, qc = lane & 3;
    const int g = lane >> 3, rr = lane & 7;
    const uint32_t sb = (uint32_t)__cvta_generic_to_shared(sg);

    float acc[2][8][4];
#pragma unroll
    for (int i = 0; i < 2; i++)
#pragma unroll
        for (int j = 0; j < 8; j++)
#pragma unroll
            for (int e = 0; e < 4; e++) acc[i][j][e] = 0.f;

    auto fill = [&](int kc, int buf) {
        const int k0 = kc * 32;
        const uint32_t base = sb + buf * GBUF * 2;
#pragma unroll
        for (int t = 0; t < 4; t++) {
            const int idx = t * 256 + tid;
            const int arr = idx >> 9;
            const int rem = idx & 511;
            const int row = rem >> 2, c = rem & 3;
            const __nv_bfloat16* src =
                (arr ? Al : Ah) + (size_t)(by * 128 + row) * K + k0 + c * 8;
            cpasync16(base + (arr * 5120 + row * ASTR + c * 8) * 2, src);
        }
#pragma unroll
        for (int t = 0; t < 4; t++) {
            const int idx = t * 256 + tid;
            const int arr = idx >> 9;
            const int rem = idx & 511;
            const int row = rem >> 4, c = rem & 15;
            const __nv_bfloat16* src =
                (arr ? Bl : Bh) + (size_t)(k0 + row) * N + bx * 128 + c * 8;
            cpasync16(base + (10240 + arr * 4352 + row * BSTR + c * 8) * 2, src);
        }
        asm volatile("cp.async.commit_group;\n");
    };

    fill(0, 0);
    const int nkc = K / 32;

    for (int kc = 0; kc < nkc; kc++) {
        const int buf = kc & 1;
        asm volatile("cp.async.wait_group 0;\n");
        __syncthreads();
        if (kc + 1 < nkc) fill(kc + 1, buf ^ 1);

        const uint32_t base = sb + buf * GBUF * 2;
        const uint32_t Ah_s = base;
        const uint32_t Al_s = base + 5120 * 2;
        const uint32_t Bh_s = base + 10240 * 2;
        const uint32_t Bl_s = base + 14592 * 2;

#pragma unroll
        for (int s = 0; s < 2; s++) {
            uint32_t afh[2][4], afl[2][4];
#pragma unroll
            for (int i = 0; i < 2; i++) {
                const uint32_t off =
                    ((wm * 32 + i * 16 + (lane & 15)) * ASTR
                     + s * 16 + 8 * (lane >> 4)) * 2;
                ldsm4(afh[i], Ah_s + off);
                ldsm4(afl[i], Al_s + off);
            }
#pragma unroll
            for (int jp = 0; jp < 4; jp++) {
                const uint32_t off =
                    ((s * 16 + 8 * (g & 1) + rr) * BSTR
                     + wn * 64 + jp * 16 + 8 * (g >> 1)) * 2;
                uint32_t bh4[4], bl4[4];
                ldsm4t(bh4, Bh_s + off);
                ldsm4t(bl4, Bl_s + off);
#pragma unroll
                for (int i = 0; i < 2; i++) {
                    mma16816(acc[i][2 * jp],     afh[i], &bh4[0]);
                    mma16816(acc[i][2 * jp],     afh[i], &bl4[0]);
                    mma16816(acc[i][2 * jp],     afl[i], &bh4[0]);
                    mma16816(acc[i][2 * jp + 1], afh[i], &bh4[2]);
                    mma16816(acc[i][2 * jp + 1], afh[i], &bl4[2]);
                    mma16816(acc[i][2 * jp + 1], afl[i], &bh4[2]);
                }
            }
        }
        __syncthreads();
    }

#pragma unroll
    for (int i = 0; i < 2; i++) {
        const int row0 = by * 128 + wm * 32 + i * 16 + qr;
#pragma unroll
        for (int j = 0; j < 8; j++) {
            const int col = bx * 128 + wn * 64 + j * 8 + 2 * qc;
            float2 v0 = make_float2(acc[i][j][0] + bias[col],
                                    acc[i][j][1] + bias[col + 1]);
            float2 v1 = make_float2(acc[i][j][2] + bias[col],
                                    acc[i][j][3] + bias[col + 1]);
            *(float2*)(C + (size_t)row0 * N + col) = v0;
            *(float2*)(C + (size_t)(row0 + 8) * N + col) = v1;
        }
    }
}

// ---------------------------------------------------------------------------
// Tensor-core flash attention: Q,K,V single fp16 (1-term QK), 2 CTAs/SM,
// longest-first scheduling.
// ---------------------------------------------------------------------------
__global__ __launch_bounds__(256, 2) void attn_mma_kernel()
{
    extern __shared__ __align__(16) __half sm[];

    const int tid  = threadIdx.x;
    const int warp = tid >> 5;
    const int lane = tid & 31;
    const int qt = gridDim.x - 1 - blockIdx.x;   // longest-first
    const int bh = blockIdx.y;
    const int rowbase = qt * 128;
    const int qr = lane >> 2;
    const int qc = lane & 3;
    const int g  = lane >> 3;
    const int rr = lane & 7;

    const uint32_t smem_base = (uint32_t)__cvta_generic_to_shared(sm);

    const __half* srcs[2] = {
        g_Kh + (size_t)bh * S_LEN * DH,
        g_Vh + (size_t)bh * S_LEN * DH };

    uint32_t Qa[4][4];
    {
        const size_t qoff = ((size_t)bh * S_LEN + rowbase + warp * 16) * DH;
#pragma unroll
        for (int s = 0; s < 4; s++)
#pragma unroll
            for (int e = 0; e < 4; e++) {
                const int r = qr + 8 * (e & 1);
                const int c = 16 * s + 2 * qc + 8 * (e >> 1);
                Qa[s][e] = *(const uint32_t*)(g_Qh + qoff + (size_t)r * DH + c);
            }
    }

    float O[8][4];
#pragma unroll
    for (int j = 0; j < 8; j++)
#pragma unroll
        for (int e = 0; e < 4; e++) O[j][e] = 0.f;
    float m0 = -1e30f, m1 = -1e30f, l0 = 0.f, l1 = 0.f;

    const int nT = qt * 2 + 2;

    auto fill = [&](int kt, int buf) {
#pragma unroll
        for (int i = 0; i < 4; i++) {
            const int arr = i >> 1;                 // 0=K, 1=V
            const int e = ((i & 1) << 8) + tid;     // 0..511
            const int row = e >> 3;
            const int grp = e & 7;
            const __half* src = srcs[arr] + (size_t)kt * 64 * DH
                              + (size_t)row * DH + grp * 8;
            const uint32_t dst = smem_base +
                ((arr * 2 + buf) * TILE_E + row * KSTR + grp * 8) * 2;
            cpasync16(dst, src);
        }
        asm volatile("cp.async.commit_group;\n");
    };

    fill(0, 0);

    for (int kt = 0; kt < nT; kt++) {
        const int buf = kt & 1;
        asm volatile("cp.async.wait_group 0;\n");
        __syncthreads();
        if (kt + 1 < nT) fill(kt + 1, buf ^ 1);

        const uint32_t K_t = smem_base + ((0 * 2 + buf) * TILE_E) * 2;
        const uint32_t V_t = smem_base + ((1 * 2 + buf) * TILE_E) * 2;

        // S = Q K^T  (single fp16 term)
        float S[8][4];
#pragma unroll
        for (int j = 0; j < 8; j++)
#pragma unroll
            for (int e = 0; e < 4; e++) S[j][e] = 0.f;

#pragma unroll
        for (int s = 0; s < 4; s++) {
#pragma unroll
            for (int jp = 0; jp < 4; jp++) {
                const uint32_t off = ((16 * jp + 8 * (g >> 1) + rr) * KSTR
                                    + 16 * s + 8 * (g & 1)) * 2;
                uint32_t bv[4];
                ldsm4(bv, K_t + off);
                mma16816h(S[2 * jp],     Qa[s], &bv[0]);
                mma16816h(S[2 * jp + 1], Qa[s], &bv[2]);
            }
        }

        const int grow0 = rowbase + warp * 16 + qr;
        if (kt * 64 + 63 > rowbase + warp * 16) {
#pragma unroll
            for (int j = 0; j < 8; j++)
#pragma unroll
                for (int e = 0; e < 4; e++) {
                    const int col = kt * 64 + 8 * j + 2 * qc + (e & 1);
                    const int row = grow0 + 8 * (e >> 1);
                    if (col > row) S[j][e] = -1e30f;
                }
        }

        float mx0 = -1e30f, mx1 = -1e30f;
#pragma unroll
        for (int j = 0; j < 8; j++) {
            mx0 = fmaxf(mx0, fmaxf(S[j][0], S[j][1]));
            mx1 = fmaxf(mx1, fmaxf(S[j][2], S[j][3]));
        }
        mx0 = fmaxf(mx0, __shfl_xor_sync(0xffffffffu, mx0, 1));
        mx0 = fmaxf(mx0, __shfl_xor_sync(0xffffffffu, mx0, 2));
        mx1 = fmaxf(mx1, __shfl_xor_sync(0xffffffffu, mx1, 1));
        mx1 = fmaxf(mx1, __shfl_xor_sync(0xffffffffu, mx1, 2));

        const float nm0 = fmaxf(m0, mx0);
        const float nm1 = fmaxf(m1, mx1);
        const float c0 = __expf(m0 - nm0);
        const float c1 = __expf(m1 - nm1);
        m0 = nm0; m1 = nm1;

        float s0 = 0.f, s1 = 0.f;
#pragma unroll
        for (int j = 0; j < 8; j++) {
            S[j][0] = __expf(S[j][0] - m0); s0 += S[j][0];
            S[j][1] = __expf(S[j][1] - m0); s0 += S[j][1];
            S[j][2] = __expf(S[j][2] - m1); s1 += S[j][2];
            S[j][3] = __expf(S[j][3] - m1); s1 += S[j][3];
        }
        s0 += __shfl_xor_sync(0xffffffffu, s0, 1);
        s0 += __shfl_xor_sync(0xffffffffu, s0, 2);
        s1 += __shfl_xor_sync(0xffffffffu, s1, 1);
        s1 += __shfl_xor_sync(0xffffffffu, s1, 2);
        l0 = l0 * c0 + s0;
        l1 = l1 * c1 + s1;
#pragma unroll
        for (int j = 0; j < 8; j++) {
            O[j][0] *= c0; O[j][1] *= c0;
            O[j][2] *= c1; O[j][3] *= c1;
        }

        // O += P V
#pragma unroll
        for (int s = 0; s < 4; s++) {
            uint32_t Pa[4];
            {
                __half2 p0 = __floats2half2_rn(S[2 * s][0],     S[2 * s][1]);
                __half2 p1 = __floats2half2_rn(S[2 * s][2],     S[2 * s][3]);
                __half2 p2 = __floats2half2_rn(S[2 * s + 1][0], S[2 * s + 1][1]);
                __half2 p3 = __floats2half2_rn(S[2 * s + 1][2], S[2 * s + 1][3]);
                Pa[0] = *(uint32_t*)&p0;
                Pa[1] = *(uint32_t*)&p1;
                Pa[2] = *(uint32_t*)&p2;
                Pa[3] = *(uint32_t*)&p3;
            }
#pragma unroll
            for (int jp = 0; jp < 4; jp++) {
                const uint32_t off = ((16 * s + 8 * (g & 1) + rr) * KSTR
                                    + 16 * jp + 8 * (g >> 1)) * 2;
                uint32_t bv[4];
                ldsm4t(bv, V_t + off);
                mma16816h(O[2 * jp],     Pa, &bv[0]);
                mma16816h(O[2 * jp + 1], Pa, &bv[2]);
            }
        }
        __syncthreads();
    }

    const float inv0 = 1.f / l0;
    const float inv1 = 1.f / l1;
    const int b = bh >> 3;
    const int h = bh & 7;
    const int row0 = rowbase + warp * 16 + qr;
    const int row1 = row0 + 8;
#pragma unroll
    for (int j = 0; j < 8; j++) {
        const int col = h * DH + 8 * j + 2 * qc;
        uint32_t hh, ll;
        const size_t o0 = ((size_t)b * S_LEN + row0) * EMB + col;
        split2(O[j][0] * inv0, O[j][1] * inv0, hh, ll);
        *(uint32_t*)&g_atth[o0] = hh;
        *(uint32_t*)&g_attl[o0] = ll;
        const size_t o1 = ((size_t)b * S_LEN + row1) * EMB + col;
        split2(O[j][2] * inv1, O[j][3] * inv1, hh, ll);
        *(uint32_t*)&g_atth[o1] = hh;
        *(uint32_t*)&g_attl[o1] = ll;
    }
}

// ---------------------------------------------------------------------------
extern "C" void kernel_launch(void* const* d_in, const int* in_sizes, int n_in,
                              void* d_out, int out_size)
{
    const float* x    = (const float*)d_in[0];
    const float* Wqkv = (const float*)d_in[1];
    const float* bqkv = (const float*)d_in[2];
    const float* Wo   = (const float*)d_in[3];
    const float* bo   = (const float*)d_in[4];
    for (int i = 0; i < n_in; i++) {
        switch (in_sizes[i]) {
            case 8388608: x    = (const float*)d_in[i]; break;
            case 786432:  Wqkv = (const float*)d_in[i]; break;
            case 1536:    bqkv = (const float*)d_in[i]; break;
            case 262144:  Wo   = (const float*)d_in[i]; break;
            case 512:     bo   = (const float*)d_in[i]; break;
        }
    }
    float* out = (float*)d_out;

    static bool init = false;
    static __nv_bfloat16 *p_Woh, *p_Wol, *p_ath, *p_atl;
    if (!init) {
        void* t;
        cudaGetSymbolAddress(&t, g_Woh);   p_Woh = (__nv_bfloat16*)t;
        cudaGetSymbolAddress(&t, g_Wol);   p_Wol = (__nv_bfloat16*)t;
        cudaGetSymbolAddress(&t, g_atth);  p_ath = (__nv_bfloat16*)t;
        cudaGetSymbolAddress(&t, g_attl);  p_atl = (__nv_bfloat16*)t;
        cudaFuncSetAttribute(attn_mma_kernel,
                             cudaFuncAttributeMaxDynamicSharedMemorySize,
                             ATTN_SMEM);
        cudaFuncSetAttribute(gemm_bf3_kernel,
                             cudaFuncAttributeMaxDynamicSharedMemorySize,
                             GSMEM);
        cudaFuncSetAttribute(gemm_qkv_blk_kernel,
                             cudaFuncAttributeMaxDynamicSharedMemorySize,
                             QK_SMEM);
        init = true;
    }

    // 0) splits
    splitA_blk_kernel<<<M_ROWS * EMB / 8 / 256, 256>>>(x);
    splitB_blk_kernel<<<EMB * N_QKV / 8 / 256, 256>>>(Wqkv);
    split_kernel<<<(EMB * EMB / 2 + 255) / 256, 256>>>(Wo, p_Woh, p_Wol,
                                                       EMB * EMB / 2);

    // 1) QKV projection
    gemm_qkv_blk_kernel<<<dim3(N_QKV / 128, M_ROWS / 128), 256, QK_SMEM>>>(bqkv);

    // 2) Attention
    attn_mma_kernel<<<dim3(S_LEN / 128, BATCH * NH), 256, ATTN_SMEM>>>();

    // 3) Output projection
    gemm_bf3_kernel<<<dim3(EMB / 128, M_ROWS / 128), 256, GSMEM>>>(
        p_ath, p_atl, p_Woh, p_Wol, bo, out, EMB, EMB);
}

// round 14
// speedup vs baseline: 14.5794x; 1.1400x over previous
#include <cuda_runtime.h>
#include <cuda_bf16.h>
#include <cuda_fp16.h>
#include <math.h>
#include <stdint.h>

#define S_LEN 4096
#define EMB   512
#define NH    8
#define DH    64
#define BATCH 4
#define M_ROWS (BATCH * S_LEN)          // 16384
#define N_QKV  (3 * EMB)                // 1536
#define KSTR   72                        // attn smem stride (64 + 8 pad)
#define TILE_E (64 * KSTR)
#define ATTN_SMEM (2 * 2 * TILE_E * 2)   // 36864

// out-proj GEMM smem (fp16 2-term): A hi/lo + B single
#define ASTR 40
#define BSTR 136
#define GBUF 14592                       // halves per buffer (10240 A + 4352 B)
#define GSMEM (2 * GBUF * 2)             // 58368

// QKV blocked GEMM smem: mbars @0, 2 stages x 24KB
#define QK_SMEM (1024 + 2 * 24576)       // 50176

// Scratch (allocation-free: __device__ globals)
// x pre-split fp16 hi/lo, blocked; Wqkv single fp16, blocked
__device__ __align__(16) __half g_xhB[(size_t)M_ROWS * EMB];
__device__ __align__(16) __half g_xlB[(size_t)M_ROWS * EMB];
__device__ __align__(16) __half g_WqB[(size_t)EMB * N_QKV];
// Wo single fp16 flat
__device__ __align__(16) __half g_Wo16[(size_t)EMB * EMB];
// Q pre-scaled by 0.125; Q,K,V single fp16. All [B,H,S,Dh].
__device__ __align__(16) __half g_Qh[(size_t)BATCH * NH * S_LEN * DH];
__device__ __align__(16) __half g_Kh[(size_t)BATCH * NH * S_LEN * DH];
__device__ __align__(16) __half g_Vh[(size_t)BATCH * NH * S_LEN * DH];
// attention output fp16 hi/lo [B,S,E]
__device__ __align__(16) __half g_atth[(size_t)M_ROWS * EMB];
__device__ __align__(16) __half g_attl[(size_t)M_ROWS * EMB];

__device__ __forceinline__ void split2h(float x, float y, uint32_t& h, uint32_t& l)
{
    __half hx = __float2half_rn(x);
    __half hy = __float2half_rn(y);
    __half2 hh; hh.x = hx; hh.y = hy;
    __half2 ll;
    ll.x = __float2half_rn(x - __half2float(hx));
    ll.y = __float2half_rn(y - __half2float(hy));
    h = *(uint32_t*)&hh;
    l = *(uint32_t*)&ll;
}

__device__ __forceinline__ void mma16816h(float c[4], const uint32_t a[4],
                                          const uint32_t* b)
{
    asm volatile(
        "mma.sync.aligned.m16n8k16.row.col.f32.f16.f16.f32 "
        "{%0,%1,%2,%3}, {%4,%5,%6,%7}, {%8,%9}, {%0,%1,%2,%3};\n"
        : "+f"(c[0]), "+f"(c[1]), "+f"(c[2]), "+f"(c[3])
        : "r"(a[0]), "r"(a[1]), "r"(a[2]), "r"(a[3]), "r"(b[0]), "r"(b[1]));
}

__device__ __forceinline__ void ldsm4(uint32_t r[4], uint32_t addr)
{
    asm volatile("ldmatrix.sync.aligned.m8n8.x4.shared.b16 {%0,%1,%2,%3}, [%4];\n"
                 : "=r"(r[0]), "=r"(r[1]), "=r"(r[2]), "=r"(r[3]) : "r"(addr));
}

__device__ __forceinline__ void ldsm4t(uint32_t r[4], uint32_t addr)
{
    asm volatile("ldmatrix.sync.aligned.m8n8.x4.trans.shared.b16 {%0,%1,%2,%3}, [%4];\n"
                 : "=r"(r[0]), "=r"(r[1]), "=r"(r[2]), "=r"(r[3]) : "r"(addr));
}

__device__ __forceinline__ void cpasync16(uint32_t s, const void* g)
{
    asm volatile("cp.async.cg.shared.global [%0], [%1], 16;\n" :: "r"(s), "l"(g));
}

__device__ __forceinline__ void bulk_g2s(uint32_t dst, const void* src,
                                         uint32_t bytes, uint32_t mbar)
{
    asm volatile(
        "cp.async.bulk.shared::cta.global.mbarrier::complete_tx::bytes "
        "[%0], [%1], %2, [%3];\n"
        :: "r"(dst), "l"(src), "r"(bytes), "r"(mbar) : "memory");
}

__device__ __forceinline__ void mbar_init(uint32_t mbar, uint32_t cnt)
{
    asm volatile("mbarrier.init.shared.b64 [%0], %1;" :: "r"(mbar), "r"(cnt) : "memory");
}

__device__ __forceinline__ void mbar_expect_tx(uint32_t mbar, uint32_t bytes)
{
    asm volatile("mbarrier.arrive.expect_tx.shared.b64 _, [%0], %1;"
                 :: "r"(mbar), "r"(bytes) : "memory");
}

__device__ __forceinline__ void mbar_wait(uint32_t mbar, uint32_t parity)
{
    uint32_t done;
    asm volatile(
        "{\n\t.reg .pred p;\n\t"
        "mbarrier.try_wait.parity.acquire.cta.shared::cta.b64 p, [%1], %2;\n\t"
        "selp.b32 %0, 1, 0, p;\n\t}"
        : "=r"(done) : "r"(mbar), "r"(parity) : "memory");
    if (!done) {
        asm volatile(
            "{\n\t.reg .pred P1;\n\t"
            "WL_%=:\n\t"
            "mbarrier.try_wait.parity.acquire.cta.shared::cta.b64 P1, [%0], %1, 0x989680;\n\t"
            "@P1 bra.uni WD_%=;\n\t"
            "bra.uni WL_%=;\n\t"
            "WD_%=:\n\t}"
            :: "r"(mbar), "r"(parity) : "memory");
    }
}

__device__ __forceinline__ uint32_t smem_u32(const void* p)
{
    uint32_t a;
    asm("{ .reg .u64 t; cvta.to.shared.u64 t, %1; cvt.u32.u64 %0, t; }"
        : "=r"(a) : "l"(p));
    return a;
}

// ---------------------------------------------------------------------------
// Splits
// ---------------------------------------------------------------------------
// x -> fp16 hi/lo blocked
__global__ __launch_bounds__(256) void splitA_blk_kernel(const float* __restrict__ x)
{
    const int idx = blockIdx.x * 256 + threadIdx.x;
    const int row = idx >> 6;
    const int cu = idx & 63;
    const int kc = cu >> 2;
    const int u = cu & 3;
    const int by = row >> 7;
    const int r = row & 127;
    const int up = (u + (r >> 1)) & 3;
    const size_t off = (size_t)(by * 16 + kc) * 4096 + r * 32 + up * 8;

    const float4 a0 = *(const float4*)(x + (size_t)row * 512 + cu * 8);
    const float4 a1 = *(const float4*)(x + (size_t)row * 512 + cu * 8 + 4);
    uint4 H, L;
    split2h(a0.x, a0.y, H.x, L.x);
    split2h(a0.z, a0.w, H.y, L.y);
    split2h(a1.x, a1.y, H.z, L.z);
    split2h(a1.z, a1.w, H.w, L.w);
    *(uint4*)(g_xhB + off) = H;
    *(uint4*)(g_xlB + off) = L;
}

// Wqkv -> single fp16 blocked
__global__ __launch_bounds__(256) void splitB_blk_kernel(const float* __restrict__ W)
{
    const int idx = blockIdx.x * 256 + threadIdx.x;
    const int k = idx / 192;
    const int cu = idx - k * 192;
    const int bx = cu >> 4;
    const int u = cu & 15;
    const int kc = k >> 5;
    const int r = k & 31;
    const int up = (u & 8) | ((u & 7) ^ (r & 7));
    const size_t off = (size_t)(bx * 16 + kc) * 4096 + r * 128 + up * 8;

    const float4 a0 = *(const float4*)(W + (size_t)k * N_QKV + cu * 8);
    const float4 a1 = *(const float4*)(W + (size_t)k * N_QKV + cu * 8 + 4);
    uint4 H;
    __half2 h;
    h = __floats2half2_rn(a0.x, a0.y); H.x = *(uint32_t*)&h;
    h = __floats2half2_rn(a0.z, a0.w); H.y = *(uint32_t*)&h;
    h = __floats2half2_rn(a1.x, a1.y); H.z = *(uint32_t*)&h;
    h = __floats2half2_rn(a1.z, a1.w); H.w = *(uint32_t*)&h;
    *(uint4*)(g_WqB + off) = H;
}

// Wo -> single fp16 flat
__global__ __launch_bounds__(256) void convWo_kernel(const float* __restrict__ src)
{
    const int idx = blockIdx.x * 256 + threadIdx.x;
    if (idx >= EMB * EMB / 2) return;
    const float2 v = ((const float2*)src)[idx];
    __half2 h = __floats2half2_rn(v.x, v.y);
    ((uint32_t*)g_Wo16)[idx] = *(uint32_t*)&h;
}

// ---------------------------------------------------------------------------
// QKV GEMM, fp16 2-term, cp.async.bulk fill (2 CTAs/SM).
// ---------------------------------------------------------------------------
__global__ __launch_bounds__(256, 2) void gemm_qkv_blk_kernel(
    const float* __restrict__ bias)
{
    extern __shared__ __align__(1024) char sq[];
    const uint32_t sb = smem_u32(sq);
    const int tid = threadIdx.x;
    const int bx = blockIdx.x, by = blockIdx.y;
    const int lane = tid & 31, warp = tid >> 5;
    const int wm = warp & 3, wn = warp >> 2;
    const int qr = lane >> 2, qc = lane & 3;
    const int g = lane >> 3, rr = lane & 7;

    float acc[2][8][4];
#pragma unroll
    for (int i = 0; i < 2; i++)
#pragma unroll
        for (int j = 0; j < 8; j++)
#pragma unroll
            for (int e = 0; e < 4; e++) acc[i][j][e] = 0.f;

    if (tid == 0) { mbar_init(sb, 1); mbar_init(sb + 16, 1); }
    __syncthreads();

    auto fill = [&](int kc) {
        const int buf = kc & 1;
        const uint32_t mb = sb + buf * 16;
        const uint32_t dst = sb + 1024 + buf * 24576;
        mbar_expect_tx(mb, 24576);
        bulk_g2s(dst,         g_xhB + (size_t)(by * 16 + kc) * 4096, 8192, mb);
        bulk_g2s(dst + 8192,  g_xlB + (size_t)(by * 16 + kc) * 4096, 8192, mb);
        bulk_g2s(dst + 16384, g_WqB + (size_t)(bx * 16 + kc) * 4096, 8192, mb);
    };

    if (tid == 0) fill(0);

    for (int kc = 0; kc < 16; kc++) {
        if (kc + 1 < 16 && tid == 0) fill(kc + 1);
        mbar_wait(sb + (kc & 1) * 16, (kc >> 1) & 1);

        const uint32_t base = sb + 1024 + (kc & 1) * 24576;
        const uint32_t Ah_s = base;
        const uint32_t Al_s = base + 8192;
        const uint32_t B_s  = base + 16384;

#pragma unroll
        for (int s = 0; s < 2; s++) {
            uint32_t afh[2][4], afl[2][4];
#pragma unroll
            for (int i = 0; i < 2; i++) {
                const int ar = wm * 32 + i * 16 + (lane & 15);
                const int au = s * 2 + (lane >> 4);
                const int aup = (au + (ar >> 1)) & 3;
                const uint32_t off = ar * 64 + aup * 16;
                ldsm4(afh[i], Ah_s + off);
                ldsm4(afl[i], Al_s + off);
            }
#pragma unroll
            for (int jp = 0; jp < 4; jp++) {
                const int br = s * 16 + 8 * (g & 1) + rr;
                const int bu = wn * 8 + jp * 2 + (g >> 1);
                const int bup = (bu & 8) | ((bu & 7) ^ (br & 7));
                const uint32_t off = br * 256 + bup * 16;
                uint32_t b4[4];
                ldsm4t(b4, B_s + off);
#pragma unroll
                for (int i = 0; i < 2; i++) {
                    mma16816h(acc[i][2 * jp],     afh[i], &b4[0]);
                    mma16816h(acc[i][2 * jp],     afl[i], &b4[0]);
                    mma16816h(acc[i][2 * jp + 1], afh[i], &b4[2]);
                    mma16816h(acc[i][2 * jp + 1], afl[i], &b4[2]);
                }
            }
        }
        __syncthreads();
    }

    // Epilogue: bias; Q scale; all -> single fp16
#pragma unroll
    for (int i = 0; i < 2; i++) {
        const int row0 = by * 128 + wm * 32 + i * 16 + qr;
        const int b = row0 >> 12;
        const int s0 = row0 & 4095;
#pragma unroll
        for (int j = 0; j < 8; j++) {
            const int col = bx * 128 + wn * 64 + j * 8 + 2 * qc;
            float v0 = acc[i][j][0] + bias[col];
            float v1 = acc[i][j][1] + bias[col + 1];
            float v2 = acc[i][j][2] + bias[col];
            float v3 = acc[i][j][3] + bias[col + 1];
            const int which = col >> 9;
            const int e = col & 511;
            const int h = e >> 6;
            const int d = e & 63;
            const size_t dst0 = (((size_t)(b * NH + h) * S_LEN) + s0) * DH + d;
            const size_t dst1 = dst0 + (size_t)8 * DH;
            if (which == 0) { v0 *= 0.125f; v1 *= 0.125f;
                              v2 *= 0.125f; v3 *= 0.125f; }
            __half* ph = (which == 0) ? g_Qh : (which == 1) ? g_Kh : g_Vh;
            __half2 h0 = __floats2half2_rn(v0, v1);
            __half2 h1 = __floats2half2_rn(v2, v3);
            *(uint32_t*)&ph[dst0] = *(uint32_t*)&h0;
            *(uint32_t*)&ph[dst1] = *(uint32_t*)&h1;
        }
    }
}

// ---------------------------------------------------------------------------
// Out-projection GEMM, fp16 2-term (A hi/lo, B single), 2 CTAs/SM.
// ---------------------------------------------------------------------------
__global__ __launch_bounds__(256, 2) void gemm_out_f16_kernel(
    const float* __restrict__ bias, float* __restrict__ C)
{
    extern __shared__ __align__(16) __half sg[];
    const int tid  = threadIdx.x;
    const int bx = blockIdx.x, by = blockIdx.y;
    const int lane = tid & 31, warp = tid >> 5;
    const int wm = warp & 3, wn = warp >> 2;
    const int qr = lane >> 2, qc = lane & 3;
    const int g = lane >> 3, rr = lane & 7;
    const uint32_t sb = (uint32_t)__cvta_generic_to_shared(sg);
    const int N = EMB, K = EMB;

    float acc[2][8][4];
#pragma unroll
    for (int i = 0; i < 2; i++)
#pragma unroll
        for (int j = 0; j < 8; j++)
#pragma unroll
            for (int e = 0; e < 4; e++) acc[i][j][e] = 0.f;

    auto fill = [&](int kc, int buf) {
        const int k0 = kc * 32;
        const uint32_t base = sb + buf * GBUF * 2;
        // A: 2 arrays x 512 chunks
#pragma unroll
        for (int t = 0; t < 4; t++) {
            const int idx = t * 256 + tid;
            const int arr = idx >> 9;
            const int rem = idx & 511;
            const int row = rem >> 2, c = rem & 3;
            const __half* src =
                (arr ? g_attl : g_atth) + (size_t)(by * 128 + row) * K + k0 + c * 8;
            cpasync16(base + (arr * 5120 + row * ASTR + c * 8) * 2, src);
        }
        // B: 512 chunks
#pragma unroll
        for (int t = 0; t < 2; t++) {
            const int idx = t * 256 + tid;
            const int row = idx >> 4, c = idx & 15;
            const __half* src =
                g_Wo16 + (size_t)(k0 + row) * N + bx * 128 + c * 8;
            cpasync16(base + (10240 + row * BSTR + c * 8) * 2, src);
        }
        asm volatile("cp.async.commit_group;\n");
    };

    fill(0, 0);
    const int nkc = K / 32;

    for (int kc = 0; kc < nkc; kc++) {
        const int buf = kc & 1;
        asm volatile("cp.async.wait_group 0;\n");
        __syncthreads();
        if (kc + 1 < nkc) fill(kc + 1, buf ^ 1);

        const uint32_t base = sb + buf * GBUF * 2;
        const uint32_t Ah_s = base;
        const uint32_t Al_s = base + 5120 * 2;
        const uint32_t B_s  = base + 10240 * 2;

#pragma unroll
        for (int s = 0; s < 2; s++) {
            uint32_t afh[2][4], afl[2][4];
#pragma unroll
            for (int i = 0; i < 2; i++) {
                const uint32_t off =
                    ((wm * 32 + i * 16 + (lane & 15)) * ASTR
                     + s * 16 + 8 * (lane >> 4)) * 2;
                ldsm4(afh[i], Ah_s + off);
                ldsm4(afl[i], Al_s + off);
            }
#pragma unroll
            for (int jp = 0; jp < 4; jp++) {
                const uint32_t off =
                    ((s * 16 + 8 * (g & 1) + rr) * BSTR
                     + wn * 64 + jp * 16 + 8 * (g >> 1)) * 2;
                uint32_t b4[4];
                ldsm4t(b4, B_s + off);
#pragma unroll
                for (int i = 0; i < 2; i++) {
                    mma16816h(acc[i][2 * jp],     afh[i], &b4[0]);
                    mma16816h(acc[i][2 * jp],     afl[i], &b4[0]);
                    mma16816h(acc[i][2 * jp + 1], afh[i], &b4[2]);
                    mma16816h(acc[i][2 * jp + 1], afl[i], &b4[2]);
                }
            }
        }
        __syncthreads();
    }

#pragma unroll
    for (int i = 0; i < 2; i++) {
        const int row0 = by * 128 + wm * 32 + i * 16 + qr;
#pragma unroll
        for (int j = 0; j < 8; j++) {
            const int col = bx * 128 + wn * 64 + j * 8 + 2 * qc;
            float2 v0 = make_float2(acc[i][j][0] + bias[col],
                                    acc[i][j][1] + bias[col + 1]);
            float2 v1 = make_float2(acc[i][j][2] + bias[col],
                                    acc[i][j][3] + bias[col + 1]);
            *(float2*)(C + (size_t)row0 * N + col) = v0;
            *(float2*)(C + (size_t)(row0 + 8) * N + col) = v1;
        }
    }
}

// ---------------------------------------------------------------------------
// Tensor-core flash attention (frozen from R13; epilogue -> fp16 hi/lo)
// ---------------------------------------------------------------------------
__global__ __launch_bounds__(256, 2) void attn_mma_kernel()
{
    extern __shared__ __align__(16) __half sm[];

    const int tid  = threadIdx.x;
    const int warp = tid >> 5;
    const int lane = tid & 31;
    const int qt = gridDim.x - 1 - blockIdx.x;   // longest-first
    const int bh = blockIdx.y;
    const int rowbase = qt * 128;
    const int qr = lane >> 2;
    const int qc = lane & 3;
    const int g  = lane >> 3;
    const int rr = lane & 7;

    const uint32_t smem_base = (uint32_t)__cvta_generic_to_shared(sm);

    const __half* srcs[2] = {
        g_Kh + (size_t)bh * S_LEN * DH,
        g_Vh + (size_t)bh * S_LEN * DH };

    uint32_t Qa[4][4];
    {
        const size_t qoff = ((size_t)bh * S_LEN + rowbase + warp * 16) * DH;
#pragma unroll
        for (int s = 0; s < 4; s++)
#pragma unroll
            for (int e = 0; e < 4; e++) {
                const int r = qr + 8 * (e & 1);
                const int c = 16 * s + 2 * qc + 8 * (e >> 1);
                Qa[s][e] = *(const uint32_t*)(g_Qh + qoff + (size_t)r * DH + c);
            }
    }

    float O[8][4];
#pragma unroll
    for (int j = 0; j < 8; j++)
#pragma unroll
        for (int e = 0; e < 4; e++) O[j][e] = 0.f;
    float m0 = -1e30f, m1 = -1e30f, l0 = 0.f, l1 = 0.f;

    const int nT = qt * 2 + 2;

    auto fill = [&](int kt, int buf) {
#pragma unroll
        for (int i = 0; i < 4; i++) {
            const int arr = i >> 1;
            const int e = ((i & 1) << 8) + tid;
            const int row = e >> 3;
            const int grp = e & 7;
            const __half* src = srcs[arr] + (size_t)kt * 64 * DH
                              + (size_t)row * DH + grp * 8;
            const uint32_t dst = smem_base +
                ((arr * 2 + buf) * TILE_E + row * KSTR + grp * 8) * 2;
            cpasync16(dst, src);
        }
        asm volatile("cp.async.commit_group;\n");
    };

    fill(0, 0);

    for (int kt = 0; kt < nT; kt++) {
        const int buf = kt & 1;
        asm volatile("cp.async.wait_group 0;\n");
        __syncthreads();
        if (kt + 1 < nT) fill(kt + 1, buf ^ 1);

        const uint32_t K_t = smem_base + ((0 * 2 + buf) * TILE_E) * 2;
        const uint32_t V_t = smem_base + ((1 * 2 + buf) * TILE_E) * 2;

        float S[8][4];
#pragma unroll
        for (int j = 0; j < 8; j++)
#pragma unroll
            for (int e = 0; e < 4; e++) S[j][e] = 0.f;

#pragma unroll
        for (int s = 0; s < 4; s++) {
#pragma unroll
            for (int jp = 0; jp < 4; jp++) {
                const uint32_t off = ((16 * jp + 8 * (g >> 1) + rr) * KSTR
                                    + 16 * s + 8 * (g & 1)) * 2;
                uint32_t bv[4];
                ldsm4(bv, K_t + off);
                mma16816h(S[2 * jp],     Qa[s], &bv[0]);
                mma16816h(S[2 * jp + 1], Qa[s], &bv[2]);
            }
        }

        const int grow0 = rowbase + warp * 16 + qr;
        if (kt * 64 + 63 > rowbase + warp * 16) {
#pragma unroll
            for (int j = 0; j < 8; j++)
#pragma unroll
                for (int e = 0; e < 4; e++) {
                    const int col = kt * 64 + 8 * j + 2 * qc + (e & 1);
                    const int row = grow0 + 8 * (e >> 1);
                    if (col > row) S[j][e] = -1e30f;
                }
        }

        float mx0 = -1e30f, mx1 = -1e30f;
#pragma unroll
        for (int j = 0; j < 8; j++) {
            mx0 = fmaxf(mx0, fmaxf(S[j][0], S[j][1]));
            mx1 = fmaxf(mx1, fmaxf(S[j][2], S[j][3]));
        }
        mx0 = fmaxf(mx0, __shfl_xor_sync(0xffffffffu, mx0, 1));
        mx0 = fmaxf(mx0, __shfl_xor_sync(0xffffffffu, mx0, 2));
        mx1 = fmaxf(mx1, __shfl_xor_sync(0xffffffffu, mx1, 1));
        mx1 = fmaxf(mx1, __shfl_xor_sync(0xffffffffu, mx1, 2));

        const float nm0 = fmaxf(m0, mx0);
        const float nm1 = fmaxf(m1, mx1);
        const float c0 = __expf(m0 - nm0);
        const float c1 = __expf(m1 - nm1);
        m0 = nm0; m1 = nm1;

        float s0 = 0.f, s1 = 0.f;
#pragma unroll
        for (int j = 0; j < 8; j++) {
            S[j][0] = __expf(S[j][0] - m0); s0 += S[j][0];
            S[j][1] = __expf(S[j][1] - m0); s0 += S[j][1];
            S[j][2] = __expf(S[j][2] - m1); s1 += S[j][2];
            S[j][3] = __expf(S[j][3] - m1); s1 += S[j][3];
        }
        s0 += __shfl_xor_sync(0xffffffffu, s0, 1);
        s0 += __shfl_xor_sync(0xffffffffu, s0, 2);
        s1 += __shfl_xor_sync(0xffffffffu, s1, 1);
        s1 += __shfl_xor_sync(0xffffffffu, s1, 2);
        l0 = l0 * c0 + s0;
        l1 = l1 * c1 + s1;
#pragma unroll
        for (int j = 0; j < 8; j++) {
            O[j][0] *= c0; O[j][1] *= c0;
            O[j][2] *= c1; O[j][3] *= c1;
        }

#pragma unroll
        for (int s = 0; s < 4; s++) {
            uint32_t Pa[4];
            {
                __half2 p0 = __floats2half2_rn(S[2 * s][0],     S[2 * s][1]);
                __half2 p1 = __floats2half2_rn(S[2 * s][2],     S[2 * s][3]);
                __half2 p2 = __floats2half2_rn(S[2 * s + 1][0], S[2 * s + 1][1]);
                __half2 p3 = __floats2half2_rn(S[2 * s + 1][2], S[2 * s + 1][3]);
                Pa[0] = *(uint32_t*)&p0;
                Pa[1] = *(uint32_t*)&p1;
                Pa[2] = *(uint32_t*)&p2;
                Pa[3] = *(uint32_t*)&p3;
            }
#pragma unroll
            for (int jp = 0; jp < 4; jp++) {
                const uint32_t off = ((16 * s + 8 * (g & 1) + rr) * KSTR
                                    + 16 * jp + 8 * (g >> 1)) * 2;
                uint32_t bv[4];
                ldsm4t(bv, V_t + off);
                mma16816h(O[2 * jp],     Pa, &bv[0]);
                mma16816h(O[2 * jp + 1], Pa, &bv[2]);
            }
        }
        __syncthreads();
    }

    const float inv0 = 1.f / l0;
    const float inv1 = 1.f / l1;
    const int b = bh >> 3;
    const int h = bh & 7;
    const int row0 = rowbase + warp * 16 + qr;
    const int row1 = row0 + 8;
#pragma unroll
    for (int j = 0; j < 8; j++) {
        const int col = h * DH + 8 * j + 2 * qc;
        uint32_t hh, ll;
        const size_t o0 = ((size_t)b * S_LEN + row0) * EMB + col;
        split2h(O[j][0] * inv0, O[j][1] * inv0, hh, ll);
        *(uint32_t*)&g_atth[o0] = hh;
        *(uint32_t*)&g_attl[o0] = ll;
        const size_t o1 = ((size_t)b * S_LEN + row1) * EMB + col;
        split2h(O[j][2] * inv1, O[j][3] * inv1, hh, ll);
        *(uint32_t*)&g_atth[o1] = hh;
        *(uint32_t*)&g_attl[o1] = ll;
    }
}

// ---------------------------------------------------------------------------
extern "C" void kernel_launch(void* const* d_in, const int* in_sizes, int n_in,
                              void* d_out, int out_size)
{
    const float* x    = (const float*)d_in[0];
    const float* Wqkv = (const float*)d_in[1];
    const float* bqkv = (const float*)d_in[2];
    const float* Wo   = (const float*)d_in[3];
    const float* bo   = (const float*)d_in[4];
    for (int i = 0; i < n_in; i++) {
        switch (in_sizes[i]) {
            case 8388608: x    = (const float*)d_in[i]; break;
            case 786432:  Wqkv = (const float*)d_in[i]; break;
            case 1536:    bqkv = (const float*)d_in[i]; break;
            case 262144:  Wo   = (const float*)d_in[i]; break;
            case 512:     bo   = (const float*)d_in[i]; break;
        }
    }
    float* out = (float*)d_out;

    static bool init = false;
    if (!init) {
        cudaFuncSetAttribute(attn_mma_kernel,
                             cudaFuncAttributeMaxDynamicSharedMemorySize,
                             ATTN_SMEM);
        cudaFuncSetAttribute(gemm_out_f16_kernel,
                             cudaFuncAttributeMaxDynamicSharedMemorySize,
                             GSMEM);
        cudaFuncSetAttribute(gemm_qkv_blk_kernel,
                             cudaFuncAttributeMaxDynamicSharedMemorySize,
                             QK_SMEM);
        init = true;
    }

    // 0) splits
    splitA_blk_kernel<<<M_ROWS * EMB / 8 / 256, 256>>>(x);
    splitB_blk_kernel<<<EMB * N_QKV / 8 / 256, 256>>>(Wqkv);
    convWo_kernel<<<(EMB * EMB / 2 + 255) / 256, 256>>>(Wo);

    // 1) QKV projection (fp16 2-term)
    gemm_qkv_blk_kernel<<<dim3(N_QKV / 128, M_ROWS / 128), 256, QK_SMEM>>>(bqkv);

    // 2) Attention
    attn_mma_kernel<<<dim3(S_LEN / 128, BATCH * NH), 256, ATTN_SMEM>>>();

    // 3) Output projection (fp16 2-term)
    gemm_out_f16_kernel<<<dim3(EMB / 128, M_ROWS / 128), 256, GSMEM>>>(bo, out);
}

// round 15
// speedup vs baseline: 15.2070x; 1.0430x over previous
#include <cuda_runtime.h>
#include <cuda_bf16.h>
#include <cuda_fp16.h>
#include <math.h>
#include <stdint.h>

#define S_LEN 4096
#define EMB   512
#define NH    8
#define DH    64
#define BATCH 4
#define M_ROWS (BATCH * S_LEN)          // 16384
#define N_QKV  (3 * EMB)                // 1536
#define KSTR   72                        // attn smem stride (64 + 8 pad)
#define TILE_E (64 * KSTR)
#define ATTN_SMEM (2 * 2 * TILE_E * 2)   // 36864

// out-proj GEMM smem (fp16 1-term A + 1-term B)
#define ASTR 40
#define BSTR 136
#define GBUF 9472                        // halves per buffer (5120 A + 4352 B)
#define GSMEM (2 * GBUF * 2)             // 37888

// QKV blocked GEMM smem: mbars @0, 3 stages x 24KB
#define QK_STAGES 3
#define QK_SMEM (1024 + QK_STAGES * 24576)   // 74752

// Q scale * log2(e): softmax computed in exp2 domain
#define QSCALE 0.18033688f

// Scratch (allocation-free: __device__ globals)
__device__ __align__(16) __half g_xhB[(size_t)M_ROWS * EMB];
__device__ __align__(16) __half g_xlB[(size_t)M_ROWS * EMB];
__device__ __align__(16) __half g_WqB[(size_t)EMB * N_QKV];
__device__ __align__(16) __half g_Wo16[(size_t)EMB * EMB];
// Q pre-scaled by 0.125*log2e; Q,K,V single fp16. All [B,H,S,Dh].
__device__ __align__(16) __half g_Qh[(size_t)BATCH * NH * S_LEN * DH];
__device__ __align__(16) __half g_Kh[(size_t)BATCH * NH * S_LEN * DH];
__device__ __align__(16) __half g_Vh[(size_t)BATCH * NH * S_LEN * DH];
// attention output single fp16 [B,S,E]
__device__ __align__(16) __half g_atth[(size_t)M_ROWS * EMB];

__device__ __forceinline__ float ex2a(float x)
{
    float y;
    asm("ex2.approx.f32 %0, %1;" : "=f"(y) : "f"(x));
    return y;
}

__device__ __forceinline__ void split2h(float x, float y, uint32_t& h, uint32_t& l)
{
    __half hx = __float2half_rn(x);
    __half hy = __float2half_rn(y);
    __half2 hh; hh.x = hx; hh.y = hy;
    __half2 ll;
    ll.x = __float2half_rn(x - __half2float(hx));
    ll.y = __float2half_rn(y - __half2float(hy));
    h = *(uint32_t*)&hh;
    l = *(uint32_t*)&ll;
}

__device__ __forceinline__ void mma16816h(float c[4], const uint32_t a[4],
                                          const uint32_t* b)
{
    asm volatile(
        "mma.sync.aligned.m16n8k16.row.col.f32.f16.f16.f32 "
        "{%0,%1,%2,%3}, {%4,%5,%6,%7}, {%8,%9}, {%0,%1,%2,%3};\n"
        : "+f"(c[0]), "+f"(c[1]), "+f"(c[2]), "+f"(c[3])
        : "r"(a[0]), "r"(a[1]), "r"(a[2]), "r"(a[3]), "r"(b[0]), "r"(b[1]));
}

__device__ __forceinline__ void ldsm4(uint32_t r[4], uint32_t addr)
{
    asm volatile("ldmatrix.sync.aligned.m8n8.x4.shared.b16 {%0,%1,%2,%3}, [%4];\n"
                 : "=r"(r[0]), "=r"(r[1]), "=r"(r[2]), "=r"(r[3]) : "r"(addr));
}

__device__ __forceinline__ void ldsm4t(uint32_t r[4], uint32_t addr)
{
    asm volatile("ldmatrix.sync.aligned.m8n8.x4.trans.shared.b16 {%0,%1,%2,%3}, [%4];\n"
                 : "=r"(r[0]), "=r"(r[1]), "=r"(r[2]), "=r"(r[3]) : "r"(addr));
}

__device__ __forceinline__ void cpasync16(uint32_t s, const void* g)
{
    asm volatile("cp.async.cg.shared.global [%0], [%1], 16;\n" :: "r"(s), "l"(g));
}

__device__ __forceinline__ void bulk_g2s(uint32_t dst, const void* src,
                                         uint32_t bytes, uint32_t mbar)
{
    asm volatile(
        "cp.async.bulk.shared::cta.global.mbarrier::complete_tx::bytes "
        "[%0], [%1], %2, [%3];\n"
        :: "r"(dst), "l"(src), "r"(bytes), "r"(mbar) : "memory");
}

__device__ __forceinline__ void mbar_init(uint32_t mbar, uint32_t cnt)
{
    asm volatile("mbarrier.init.shared.b64 [%0], %1;" :: "r"(mbar), "r"(cnt) : "memory");
}

__device__ __forceinline__ void mbar_expect_tx(uint32_t mbar, uint32_t bytes)
{
    asm volatile("mbarrier.arrive.expect_tx.shared.b64 _, [%0], %1;"
                 :: "r"(mbar), "r"(bytes) : "memory");
}

__device__ __forceinline__ void mbar_wait(uint32_t mbar, uint32_t parity)
{
    uint32_t done;
    asm volatile(
        "{\n\t.reg .pred p;\n\t"
        "mbarrier.try_wait.parity.acquire.cta.shared::cta.b64 p, [%1], %2;\n\t"
        "selp.b32 %0, 1, 0, p;\n\t}"
        : "=r"(done) : "r"(mbar), "r"(parity) : "memory");
    if (!done) {
        asm volatile(
            "{\n\t.reg .pred P1;\n\t"
            "WL_%=:\n\t"
            "mbarrier.try_wait.parity.acquire.cta.shared::cta.b64 P1, [%0], %1, 0x989680;\n\t"
            "@P1 bra.uni WD_%=;\n\t"
            "bra.uni WL_%=;\n\t"
            "WD_%=:\n\t}"
            :: "r"(mbar), "r"(parity) : "memory");
    }
}

__device__ __forceinline__ uint32_t smem_u32(const void* p)
{
    uint32_t a;
    asm("{ .reg .u64 t; cvta.to.shared.u64 t, %1; cvt.u32.u64 %0, t; }"
        : "=r"(a) : "l"(p));
    return a;
}

// ---------------------------------------------------------------------------
// Splits
// ---------------------------------------------------------------------------
__global__ __launch_bounds__(256) void splitA_blk_kernel(const float* __restrict__ x)
{
    const int idx = blockIdx.x * 256 + threadIdx.x;
    const int row = idx >> 6;
    const int cu = idx & 63;
    const int kc = cu >> 2;
    const int u = cu & 3;
    const int by = row >> 7;
    const int r = row & 127;
    const int up = (u + (r >> 1)) & 3;
    const size_t off = (size_t)(by * 16 + kc) * 4096 + r * 32 + up * 8;

    const float4 a0 = *(const float4*)(x + (size_t)row * 512 + cu * 8);
    const float4 a1 = *(const float4*)(x + (size_t)row * 512 + cu * 8 + 4);
    uint4 H, L;
    split2h(a0.x, a0.y, H.x, L.x);
    split2h(a0.z, a0.w, H.y, L.y);
    split2h(a1.x, a1.y, H.z, L.z);
    split2h(a1.z, a1.w, H.w, L.w);
    *(uint4*)(g_xhB + off) = H;
    *(uint4*)(g_xlB + off) = L;
}

__global__ __launch_bounds__(256) void splitB_blk_kernel(const float* __restrict__ W)
{
    const int idx = blockIdx.x * 256 + threadIdx.x;
    const int k = idx / 192;
    const int cu = idx - k * 192;
    const int bx = cu >> 4;
    const int u = cu & 15;
    const int kc = k >> 5;
    const int r = k & 31;
    const int up = (u & 8) | ((u & 7) ^ (r & 7));
    const size_t off = (size_t)(bx * 16 + kc) * 4096 + r * 128 + up * 8;

    const float4 a0 = *(const float4*)(W + (size_t)k * N_QKV + cu * 8);
    const float4 a1 = *(const float4*)(W + (size_t)k * N_QKV + cu * 8 + 4);
    uint4 H;
    __half2 h;
    h = __floats2half2_rn(a0.x, a0.y); H.x = *(uint32_t*)&h;
    h = __floats2half2_rn(a0.z, a0.w); H.y = *(uint32_t*)&h;
    h = __floats2half2_rn(a1.x, a1.y); H.z = *(uint32_t*)&h;
    h = __floats2half2_rn(a1.z, a1.w); H.w = *(uint32_t*)&h;
    *(uint4*)(g_WqB + off) = H;
}

__global__ __launch_bounds__(256) void convWo_kernel(const float* __restrict__ src)
{
    const int idx = blockIdx.x * 256 + threadIdx.x;
    if (idx >= EMB * EMB / 2) return;
    const float2 v = ((const float2*)src)[idx];
    __half2 h = __floats2half2_rn(v.x, v.y);
    ((uint32_t*)g_Wo16)[idx] = *(uint32_t*)&h;
}

// ---------------------------------------------------------------------------
// QKV GEMM, fp16 2-term, 3-stage cp.async.bulk pipeline (2 CTAs/SM).
// ---------------------------------------------------------------------------
__global__ __launch_bounds__(256, 2) void gemm_qkv_blk_kernel(
    const float* __restrict__ bias)
{
    extern __shared__ __align__(1024) char sq[];
    const uint32_t sb = smem_u32(sq);
    const int tid = threadIdx.x;
    const int bx = blockIdx.x, by = blockIdx.y;
    const int lane = tid & 31, warp = tid >> 5;
    const int wm = warp & 3, wn = warp >> 2;
    const int qr = lane >> 2, qc = lane & 3;
    const int g = lane >> 3, rr = lane & 7;

    float acc[2][8][4];
#pragma unroll
    for (int i = 0; i < 2; i++)
#pragma unroll
        for (int j = 0; j < 8; j++)
#pragma unroll
            for (int e = 0; e < 4; e++) acc[i][j][e] = 0.f;

    if (tid == 0) {
        mbar_init(sb, 1); mbar_init(sb + 16, 1); mbar_init(sb + 32, 1);
    }
    __syncthreads();

    auto fill = [&](int kc) {
        const int buf = kc % QK_STAGES;
        const uint32_t mb = sb + buf * 16;
        const uint32_t dst = sb + 1024 + buf * 24576;
        mbar_expect_tx(mb, 24576);
        bulk_g2s(dst,         g_xhB + (size_t)(by * 16 + kc) * 4096, 8192, mb);
        bulk_g2s(dst + 8192,  g_xlB + (size_t)(by * 16 + kc) * 4096, 8192, mb);
        bulk_g2s(dst + 16384, g_WqB + (size_t)(bx * 16 + kc) * 4096, 8192, mb);
    };

    if (tid == 0) { fill(0); fill(1); }

    for (int kc = 0; kc < 16; kc++) {
        const int buf = kc % QK_STAGES;
        mbar_wait(sb + buf * 16, (kc / QK_STAGES) & 1);

        const uint32_t base = sb + 1024 + buf * 24576;
        const uint32_t Ah_s = base;
        const uint32_t Al_s = base + 8192;
        const uint32_t B_s  = base + 16384;

#pragma unroll
        for (int s = 0; s < 2; s++) {
            uint32_t afh[2][4], afl[2][4];
#pragma unroll
            for (int i = 0; i < 2; i++) {
                const int ar = wm * 32 + i * 16 + (lane & 15);
                const int au = s * 2 + (lane >> 4);
                const int aup = (au + (ar >> 1)) & 3;
                const uint32_t off = ar * 64 + aup * 16;
                ldsm4(afh[i], Ah_s + off);
                ldsm4(afl[i], Al_s + off);
            }
#pragma unroll
            for (int jp = 0; jp < 4; jp++) {
                const int br = s * 16 + 8 * (g & 1) + rr;
                const int bu = wn * 8 + jp * 2 + (g >> 1);
                const int bup = (bu & 8) | ((bu & 7) ^ (br & 7));
                const uint32_t off = br * 256 + bup * 16;
                uint32_t b4[4];
                ldsm4t(b4, B_s + off);
#pragma unroll
                for (int i = 0; i < 2; i++) {
                    mma16816h(acc[i][2 * jp],     afh[i], &b4[0]);
                    mma16816h(acc[i][2 * jp],     afl[i], &b4[0]);
                    mma16816h(acc[i][2 * jp + 1], afh[i], &b4[2]);
                    mma16816h(acc[i][2 * jp + 1], afl[i], &b4[2]);
                }
            }
        }
        __syncthreads();
        if (kc + 2 < 16 && tid == 0) fill(kc + 2);
    }

    // Epilogue: bias; Q scale (0.125*log2e); all -> single fp16
#pragma unroll
    for (int i = 0; i < 2; i++) {
        const int row0 = by * 128 + wm * 32 + i * 16 + qr;
        const int b = row0 >> 12;
        const int s0 = row0 & 4095;
#pragma unroll
        for (int j = 0; j < 8; j++) {
            const int col = bx * 128 + wn * 64 + j * 8 + 2 * qc;
            float v0 = acc[i][j][0] + bias[col];
            float v1 = acc[i][j][1] + bias[col + 1];
            float v2 = acc[i][j][2] + bias[col];
            float v3 = acc[i][j][3] + bias[col + 1];
            const int which = col >> 9;
            const int e = col & 511;
            const int h = e >> 6;
            const int d = e & 63;
            const size_t dst0 = (((size_t)(b * NH + h) * S_LEN) + s0) * DH + d;
            const size_t dst1 = dst0 + (size_t)8 * DH;
            if (which == 0) { v0 *= QSCALE; v1 *= QSCALE;
                              v2 *= QSCALE; v3 *= QSCALE; }
            __half* ph = (which == 0) ? g_Qh : (which == 1) ? g_Kh : g_Vh;
            __half2 h0 = __floats2half2_rn(v0, v1);
            __half2 h1 = __floats2half2_rn(v2, v3);
            *(uint32_t*)&ph[dst0] = *(uint32_t*)&h0;
            *(uint32_t*)&ph[dst1] = *(uint32_t*)&h1;
        }
    }
}

// ---------------------------------------------------------------------------
// Out-projection GEMM, fp16 1-term (A single, B single), 2 CTAs/SM.
// ---------------------------------------------------------------------------
__global__ __launch_bounds__(256, 2) void gemm_out_f16_kernel(
    const float* __restrict__ bias, float* __restrict__ C)
{
    extern __shared__ __align__(16) __half sg[];
    const int tid  = threadIdx.x;
    const int bx = blockIdx.x, by = blockIdx.y;
    const int lane = tid & 31, warp = tid >> 5;
    const int wm = warp & 3, wn = warp >> 2;
    const int qr = lane >> 2, qc = lane & 3;
    const int g = lane >> 3, rr = lane & 7;
    const uint32_t sb = (uint32_t)__cvta_generic_to_shared(sg);
    const int N = EMB, K = EMB;

    float acc[2][8][4];
#pragma unroll
    for (int i = 0; i < 2; i++)
#pragma unroll
        for (int j = 0; j < 8; j++)
#pragma unroll
            for (int e = 0; e < 4; e++) acc[i][j][e] = 0.f;

    auto fill = [&](int kc, int buf) {
        const int k0 = kc * 32;
        const uint32_t base = sb + buf * GBUF * 2;
        // A: 512 chunks
#pragma unroll
        for (int t = 0; t < 2; t++) {
            const int idx = t * 256 + tid;
            const int row = idx >> 2, c = idx & 3;
            const __half* src =
                g_atth + (size_t)(by * 128 + row) * K + k0 + c * 8;
            cpasync16(base + (row * ASTR + c * 8) * 2, src);
        }
        // B: 512 chunks
#pragma unroll
        for (int t = 0; t < 2; t++) {
            const int idx = t * 256 + tid;
            const int row = idx >> 4, c = idx & 15;
            const __half* src =
                g_Wo16 + (size_t)(k0 + row) * N + bx * 128 + c * 8;
            cpasync16(base + (5120 + row * BSTR + c * 8) * 2, src);
        }
        asm volatile("cp.async.commit_group;\n");
    };

    fill(0, 0);
    const int nkc = K / 32;

    for (int kc = 0; kc < nkc; kc++) {
        const int buf = kc & 1;
        asm volatile("cp.async.wait_group 0;\n");
        __syncthreads();
        if (kc + 1 < nkc) fill(kc + 1, buf ^ 1);

        const uint32_t base = sb + buf * GBUF * 2;
        const uint32_t A_s = base;
        const uint32_t B_s = base + 5120 * 2;

#pragma unroll
        for (int s = 0; s < 2; s++) {
            uint32_t af[2][4];
#pragma unroll
            for (int i = 0; i < 2; i++) {
                const uint32_t off =
                    ((wm * 32 + i * 16 + (lane & 15)) * ASTR
                     + s * 16 + 8 * (lane >> 4)) * 2;
                ldsm4(af[i], A_s + off);
            }
#pragma unroll
            for (int jp = 0; jp < 4; jp++) {
                const uint32_t off =
                    ((s * 16 + 8 * (g & 1) + rr) * BSTR
                     + wn * 64 + jp * 16 + 8 * (g >> 1)) * 2;
                uint32_t b4[4];
                ldsm4t(b4, B_s + off);
#pragma unroll
                for (int i = 0; i < 2; i++) {
                    mma16816h(acc[i][2 * jp],     af[i], &b4[0]);
                    mma16816h(acc[i][2 * jp + 1], af[i], &b4[2]);
                }
            }
        }
        __syncthreads();
    }

#pragma unroll
    for (int i = 0; i < 2; i++) {
        const int row0 = by * 128 + wm * 32 + i * 16 + qr;
#pragma unroll
        for (int j = 0; j < 8; j++) {
            const int col = bx * 128 + wn * 64 + j * 8 + 2 * qc;
            float2 v0 = make_float2(acc[i][j][0] + bias[col],
                                    acc[i][j][1] + bias[col + 1]);
            float2 v1 = make_float2(acc[i][j][2] + bias[col],
                                    acc[i][j][3] + bias[col + 1]);
            *(float2*)(C + (size_t)row0 * N + col) = v0;
            *(float2*)(C + (size_t)(row0 + 8) * N + col) = v1;
        }
    }
}

// ---------------------------------------------------------------------------
// Flash attention: exp2-domain softmax, conditional rescale, fp16 epilogue.
// ---------------------------------------------------------------------------
__global__ __launch_bounds__(256, 2) void attn_mma_kernel()
{
    extern __shared__ __align__(16) __half sm[];

    const int tid  = threadIdx.x;
    const int warp = tid >> 5;
    const int lane = tid & 31;
    const int qt = gridDim.x - 1 - blockIdx.x;   // longest-first
    const int bh = blockIdx.y;
    const int rowbase = qt * 128;
    const int qr = lane >> 2;
    const int qc = lane & 3;
    const int g  = lane >> 3;
    const int rr = lane & 7;

    const uint32_t smem_base = (uint32_t)__cvta_generic_to_shared(sm);

    const __half* srcs[2] = {
        g_Kh + (size_t)bh * S_LEN * DH,
        g_Vh + (size_t)bh * S_LEN * DH };

    uint32_t Qa[4][4];
    {
        const size_t qoff = ((size_t)bh * S_LEN + rowbase + warp * 16) * DH;
#pragma unroll
        for (int s = 0; s < 4; s++)
#pragma unroll
            for (int e = 0; e < 4; e++) {
                const int r = qr + 8 * (e & 1);
                const int c = 16 * s + 2 * qc + 8 * (e >> 1);
                Qa[s][e] = *(const uint32_t*)(g_Qh + qoff + (size_t)r * DH + c);
            }
    }

    float O[8][4];
#pragma unroll
    for (int j = 0; j < 8; j++)
#pragma unroll
        for (int e = 0; e < 4; e++) O[j][e] = 0.f;
    float m0 = -1e30f, m1 = -1e30f, l0 = 0.f, l1 = 0.f;

    const int nT = qt * 2 + 2;

    auto fill = [&](int kt, int buf) {
#pragma unroll
        for (int i = 0; i < 4; i++) {
            const int arr = i >> 1;
            const int e = ((i & 1) << 8) + tid;
            const int row = e >> 3;
            const int grp = e & 7;
            const __half* src = srcs[arr] + (size_t)kt * 64 * DH
                              + (size_t)row * DH + grp * 8;
            const uint32_t dst = smem_base +
                ((arr * 2 + buf) * TILE_E + row * KSTR + grp * 8) * 2;
            cpasync16(dst, src);
        }
        asm volatile("cp.async.commit_group;\n");
    };

    fill(0, 0);

    for (int kt = 0; kt < nT; kt++) {
        const int buf = kt & 1;
        asm volatile("cp.async.wait_group 0;\n");
        __syncthreads();
        if (kt + 1 < nT) fill(kt + 1, buf ^ 1);

        const uint32_t K_t = smem_base + ((0 * 2 + buf) * TILE_E) * 2;
        const uint32_t V_t = smem_base + ((1 * 2 + buf) * TILE_E) * 2;

        float S[8][4];
#pragma unroll
        for (int j = 0; j < 8; j++)
#pragma unroll
            for (int e = 0; e < 4; e++) S[j][e] = 0.f;

#pragma unroll
        for (int s = 0; s < 4; s++) {
#pragma unroll
            for (int jp = 0; jp < 4; jp++) {
                const uint32_t off = ((16 * jp + 8 * (g >> 1) + rr) * KSTR
                                    + 16 * s + 8 * (g & 1)) * 2;
                uint32_t bv[4];
                ldsm4(bv, K_t + off);
                mma16816h(S[2 * jp],     Qa[s], &bv[0]);
                mma16816h(S[2 * jp + 1], Qa[s], &bv[2]);
            }
        }

        const int grow0 = rowbase + warp * 16 + qr;
        if (kt * 64 + 63 > rowbase + warp * 16) {
#pragma unroll
            for (int j = 0; j < 8; j++)
#pragma unroll
                for (int e = 0; e < 4; e++) {
                    const int col = kt * 64 + 8 * j + 2 * qc + (e & 1);
                    const int row = grow0 + 8 * (e >> 1);
                    if (col > row) S[j][e] = -1e30f;
                }
        }

        float mx0 = -1e30f, mx1 = -1e30f;
#pragma unroll
        for (int j = 0; j < 8; j++) {
            mx0 = fmaxf(mx0, fmaxf(S[j][0], S[j][1]));
            mx1 = fmaxf(mx1, fmaxf(S[j][2], S[j][3]));
        }
        mx0 = fmaxf(mx0, __shfl_xor_sync(0xffffffffu, mx0, 1));
        mx0 = fmaxf(mx0, __shfl_xor_sync(0xffffffffu, mx0, 2));
        mx1 = fmaxf(mx1, __shfl_xor_sync(0xffffffffu, mx1, 1));
        mx1 = fmaxf(mx1, __shfl_xor_sync(0xffffffffu, mx1, 2));

        const float nm0 = fmaxf(m0, mx0);
        const float nm1 = fmaxf(m1, mx1);
        const float c0 = ex2a(m0 - nm0);
        const float c1 = ex2a(m1 - nm1);
        m0 = nm0; m1 = nm1;

        // exp2-domain probabilities
        float s0 = 0.f, s1 = 0.f;
#pragma unroll
        for (int j = 0; j < 8; j++) {
            S[j][0] = ex2a(S[j][0] - m0); s0 += S[j][0];
            S[j][1] = ex2a(S[j][1] - m0); s0 += S[j][1];
            S[j][2] = ex2a(S[j][2] - m1); s1 += S[j][2];
            S[j][3] = ex2a(S[j][3] - m1); s1 += S[j][3];
        }
        s0 += __shfl_xor_sync(0xffffffffu, s0, 1);
        s0 += __shfl_xor_sync(0xffffffffu, s0, 2);
        s1 += __shfl_xor_sync(0xffffffffu, s1, 1);
        s1 += __shfl_xor_sync(0xffffffffu, s1, 2);
        l0 = l0 * c0 + s0;
        l1 = l1 * c1 + s1;

        // conditional rescale: skip when no lane's max moved (c==1 exactly)
        if (__any_sync(0xffffffffu, (c0 != 1.f) || (c1 != 1.f))) {
#pragma unroll
            for (int j = 0; j < 8; j++) {
                O[j][0] *= c0; O[j][1] *= c0;
                O[j][2] *= c1; O[j][3] *= c1;
            }
        }

#pragma unroll
        for (int s = 0; s < 4; s++) {
            uint32_t Pa[4];
            {
                __half2 p0 = __floats2half2_rn(S[2 * s][0],     S[2 * s][1]);
                __half2 p1 = __floats2half2_rn(S[2 * s][2],     S[2 * s][3]);
                __half2 p2 = __floats2half2_rn(S[2 * s + 1][0], S[2 * s + 1][1]);
                __half2 p3 = __floats2half2_rn(S[2 * s + 1][2], S[2 * s + 1][3]);
                Pa[0] = *(uint32_t*)&p0;
                Pa[1] = *(uint32_t*)&p1;
                Pa[2] = *(uint32_t*)&p2;
                Pa[3] = *(uint32_t*)&p3;
            }
#pragma unroll
            for (int jp = 0; jp < 4; jp++) {
                const uint32_t off = ((16 * s + 8 * (g & 1) + rr) * KSTR
                                    + 16 * jp + 8 * (g >> 1)) * 2;
                uint32_t bv[4];
                ldsm4t(bv, V_t + off);
                mma16816h(O[2 * jp],     Pa, &bv[0]);
                mma16816h(O[2 * jp + 1], Pa, &bv[2]);
            }
        }
        __syncthreads();
    }

    const float inv0 = 1.f / l0;
    const float inv1 = 1.f / l1;
    const int b = bh >> 3;
    const int h = bh & 7;
    const int row0 = rowbase + warp * 16 + qr;
    const int row1 = row0 + 8;
#pragma unroll
    for (int j = 0; j < 8; j++) {
        const int col = h * DH + 8 * j + 2 * qc;
        const size_t o0 = ((size_t)b * S_LEN + row0) * EMB + col;
        const size_t o1 = ((size_t)b * S_LEN + row1) * EMB + col;
        __half2 h0 = __floats2half2_rn(O[j][0] * inv0, O[j][1] * inv0);
        __half2 h1 = __floats2half2_rn(O[j][2] * inv1, O[j][3] * inv1);
        *(uint32_t*)&g_atth[o0] = *(uint32_t*)&h0;
        *(uint32_t*)&g_atth[o1] = *(uint32_t*)&h1;
    }
}

// ---------------------------------------------------------------------------
extern "C" void kernel_launch(void* const* d_in, const int* in_sizes, int n_in,
                              void* d_out, int out_size)
{
    const float* x    = (const float*)d_in[0];
    const float* Wqkv = (const float*)d_in[1];
    const float* bqkv = (const float*)d_in[2];
    const float* Wo   = (const float*)d_in[3];
    const float* bo   = (const float*)d_in[4];
    for (int i = 0; i < n_in; i++) {
        switch (in_sizes[i]) {
            case 8388608: x    = (const float*)d_in[i]; break;
            case 786432:  Wqkv = (const float*)d_in[i]; break;
            case 1536:    bqkv = (const float*)d_in[i]; break;
            case 262144:  Wo   = (const float*)d_in[i]; break;
            case 512:     bo   = (const float*)d_in[i]; break;
        }
    }
    float* out = (float*)d_out;

    static bool init = false;
    if (!init) {
        cudaFuncSetAttribute(attn_mma_kernel,
                             cudaFuncAttributeMaxDynamicSharedMemorySize,
                             ATTN_SMEM);
        cudaFuncSetAttribute(gemm_out_f16_kernel,
                             cudaFuncAttributeMaxDynamicSharedMemorySize,
                             GSMEM);
        cudaFuncSetAttribute(gemm_qkv_blk_kernel,
                             cudaFuncAttributeMaxDynamicSharedMemorySize,
                             QK_SMEM);
        init = true;
    }

    // 0) splits
    splitA_blk_kernel<<<M_ROWS * EMB / 8 / 256, 256>>>(x);
    splitB_blk_kernel<<<EMB * N_QKV / 8 / 256, 256>>>(Wqkv);
    convWo_kernel<<<(EMB * EMB / 2 + 255) / 256, 256>>>(Wo);

    // 1) QKV projection (fp16 2-term, 3-stage bulk pipeline)
    gemm_qkv_blk_kernel<<<dim3(N_QKV / 128, M_ROWS / 128), 256, QK_SMEM>>>(bqkv);

    // 2) Attention (exp2 softmax)
    attn_mma_kernel<<<dim3(S_LEN / 128, BATCH * NH), 256, ATTN_SMEM>>>();

    // 3) Output projection (fp16 1-term)
    gemm_out_f16_kernel<<<dim3(EMB / 128, M_ROWS / 128), 256, GSMEM>>>(bo, out);
}

// round 16
// speedup vs baseline: 15.5280x; 1.0211x over previous
#include <cuda_runtime.h>
#include <cuda_bf16.h>
#include <cuda_fp16.h>
#include <math.h>
#include <stdint.h>

#define S_LEN 4096
#define EMB   512
#define NH    8
#define DH    64
#define BATCH 4
#define M_ROWS (BATCH * S_LEN)          // 16384
#define N_QKV  (3 * EMB)                // 1536
#define KSTR   72                        // attn smem stride (64 + 8 pad)
#define TILE_E (64 * KSTR)
#define ATTN_STAGES 3
#define ATTN_SMEM (ATTN_STAGES * 2 * TILE_E * 2)   // 55296

// out-proj GEMM smem (fp16 1-term A + 1-term B)
#define ASTR 40
#define BSTR 136
#define GBUF 9472
#define GSMEM (2 * GBUF * 2)             // 37888

// QKV persistent GEMM smem: mbars @0, 3 stages x 24KB
#define QK_STAGES 3
#define QK_SMEM (1024 + QK_STAGES * 24576)   // 74752
#define QK_GRID 296                          // 2 CTAs x 148 SMs

// Q scale * log2(e)
#define QSCALE 0.18033688f

// Scratch (allocation-free: __device__ globals)
__device__ __align__(16) __half g_xhB[(size_t)M_ROWS * EMB];
__device__ __align__(16) __half g_xlB[(size_t)M_ROWS * EMB];
__device__ __align__(16) __half g_WqB[(size_t)EMB * N_QKV];
__device__ __align__(16) __half g_Wo16[(size_t)EMB * EMB];
__device__ __align__(16) __half g_Qh[(size_t)BATCH * NH * S_LEN * DH];
__device__ __align__(16) __half g_Kh[(size_t)BATCH * NH * S_LEN * DH];
__device__ __align__(16) __half g_Vh[(size_t)BATCH * NH * S_LEN * DH];
__device__ __align__(16) __half g_atth[(size_t)M_ROWS * EMB];

__device__ __forceinline__ float ex2a(float x)
{
    float y;
    asm("ex2.approx.f32 %0, %1;" : "=f"(y) : "f"(x));
    return y;
}

__device__ __forceinline__ void split2h(float x, float y, uint32_t& h, uint32_t& l)
{
    __half hx = __float2half_rn(x);
    __half hy = __float2half_rn(y);
    __half2 hh; hh.x = hx; hh.y = hy;
    __half2 ll;
    ll.x = __float2half_rn(x - __half2float(hx));
    ll.y = __float2half_rn(y - __half2float(hy));
    h = *(uint32_t*)&hh;
    l = *(uint32_t*)&ll;
}

__device__ __forceinline__ void mma16816h(float c[4], const uint32_t a[4],
                                          const uint32_t* b)
{
    asm volatile(
        "mma.sync.aligned.m16n8k16.row.col.f32.f16.f16.f32 "
        "{%0,%1,%2,%3}, {%4,%5,%6,%7}, {%8,%9}, {%0,%1,%2,%3};\n"
        : "+f"(c[0]), "+f"(c[1]), "+f"(c[2]), "+f"(c[3])
        : "r"(a[0]), "r"(a[1]), "r"(a[2]), "r"(a[3]), "r"(b[0]), "r"(b[1]));
}

__device__ __forceinline__ void ldsm4(uint32_t r[4], uint32_t addr)
{
    asm volatile("ldmatrix.sync.aligned.m8n8.x4.shared.b16 {%0,%1,%2,%3}, [%4];\n"
                 : "=r"(r[0]), "=r"(r[1]), "=r"(r[2]), "=r"(r[3]) : "r"(addr));
}

__device__ __forceinline__ void ldsm4t(uint32_t r[4], uint32_t addr)
{
    asm volatile("ldmatrix.sync.aligned.m8n8.x4.trans.shared.b16 {%0,%1,%2,%3}, [%4];\n"
                 : "=r"(r[0]), "=r"(r[1]), "=r"(r[2]), "=r"(r[3]) : "r"(addr));
}

__device__ __forceinline__ void cpasync16(uint32_t s, const void* g)
{
    asm volatile("cp.async.cg.shared.global [%0], [%1], 16;\n" :: "r"(s), "l"(g));
}

__device__ __forceinline__ void bulk_g2s(uint32_t dst, const void* src,
                                         uint32_t bytes, uint32_t mbar)
{
    asm volatile(
        "cp.async.bulk.shared::cta.global.mbarrier::complete_tx::bytes "
        "[%0], [%1], %2, [%3];\n"
        :: "r"(dst), "l"(src), "r"(bytes), "r"(mbar) : "memory");
}

__device__ __forceinline__ void mbar_init(uint32_t mbar, uint32_t cnt)
{
    asm volatile("mbarrier.init.shared.b64 [%0], %1;" :: "r"(mbar), "r"(cnt) : "memory");
}

__device__ __forceinline__ void mbar_expect_tx(uint32_t mbar, uint32_t bytes)
{
    asm volatile("mbarrier.arrive.expect_tx.shared.b64 _, [%0], %1;"
                 :: "r"(mbar), "r"(bytes) : "memory");
}

__device__ __forceinline__ void mbar_wait(uint32_t mbar, uint32_t parity)
{
    uint32_t done;
    asm volatile(
        "{\n\t.reg .pred p;\n\t"
        "mbarrier.try_wait.parity.acquire.cta.shared::cta.b64 p, [%1], %2;\n\t"
        "selp.b32 %0, 1, 0, p;\n\t}"
        : "=r"(done) : "r"(mbar), "r"(parity) : "memory");
    if (!done) {
        asm volatile(
            "{\n\t.reg .pred P1;\n\t"
            "WL_%=:\n\t"
            "mbarrier.try_wait.parity.acquire.cta.shared::cta.b64 P1, [%0], %1, 0x989680;\n\t"
            "@P1 bra.uni WD_%=;\n\t"
            "bra.uni WL_%=;\n\t"
            "WD_%=:\n\t}"
            :: "r"(mbar), "r"(parity) : "memory");
    }
}

__device__ __forceinline__ uint32_t smem_u32(const void* p)
{
    uint32_t a;
    asm("{ .reg .u64 t; cvta.to.shared.u64 t, %1; cvt.u32.u64 %0, t; }"
        : "=r"(a) : "l"(p));
    return a;
}

// ---------------------------------------------------------------------------
// Merged splits: blocks [0,4096) -> x hi/lo; [4096,4480) -> Wqkv; rest -> Wo
// ---------------------------------------------------------------------------
__global__ __launch_bounds__(256) void split_all_kernel(
    const float* __restrict__ x, const float* __restrict__ Wq,
    const float* __restrict__ Wo)
{
    const int bid = blockIdx.x;
    if (bid < 4096) {
        const int idx = bid * 256 + threadIdx.x;
        const int row = idx >> 6;
        const int cu = idx & 63;
        const int kc = cu >> 2;
        const int u = cu & 3;
        const int by = row >> 7;
        const int r = row & 127;
        const int up = (u + (r >> 1)) & 3;
        const size_t off = (size_t)(by * 16 + kc) * 4096 + r * 32 + up * 8;

        const float4 a0 = *(const float4*)(x + (size_t)row * 512 + cu * 8);
        const float4 a1 = *(const float4*)(x + (size_t)row * 512 + cu * 8 + 4);
        uint4 H, L;
        split2h(a0.x, a0.y, H.x, L.x);
        split2h(a0.z, a0.w, H.y, L.y);
        split2h(a1.x, a1.y, H.z, L.z);
        split2h(a1.z, a1.w, H.w, L.w);
        *(uint4*)(g_xhB + off) = H;
        *(uint4*)(g_xlB + off) = L;
    } else if (bid < 4480) {
        const int idx = (bid - 4096) * 256 + threadIdx.x;
        const int k = idx / 192;
        const int cu = idx - k * 192;
        const int bx = cu >> 4;
        const int u = cu & 15;
        const int kc = k >> 5;
        const int r = k & 31;
        const int up = (u & 8) | ((u & 7) ^ (r & 7));
        const size_t off = (size_t)(bx * 16 + kc) * 4096 + r * 128 + up * 8;

        const float4 a0 = *(const float4*)(Wq + (size_t)k * N_QKV + cu * 8);
        const float4 a1 = *(const float4*)(Wq + (size_t)k * N_QKV + cu * 8 + 4);
        uint4 H;
        __half2 h;
        h = __floats2half2_rn(a0.x, a0.y); H.x = *(uint32_t*)&h;
        h = __floats2half2_rn(a0.z, a0.w); H.y = *(uint32_t*)&h;
        h = __floats2half2_rn(a1.x, a1.y); H.z = *(uint32_t*)&h;
        h = __floats2half2_rn(a1.z, a1.w); H.w = *(uint32_t*)&h;
        *(uint4*)(g_WqB + off) = H;
    } else {
        const int idx = (bid - 4480) * 256 + threadIdx.x;
        if (idx >= EMB * EMB / 2) return;
        const float2 v = ((const float2*)Wo)[idx];
        __half2 h = __floats2half2_rn(v.x, v.y);
        ((uint32_t*)g_Wo16)[idx] = *(uint32_t*)&h;
    }
}

// ---------------------------------------------------------------------------
// PERSISTENT QKV GEMM, fp16 2-term, continuous 3-stage bulk pipeline.
// grid = 296 (2 CTAs/SM), each CTA streams its tiles' chunks back-to-back.
// ---------------------------------------------------------------------------
__global__ __launch_bounds__(256, 2) void gemm_qkv_blk_kernel(
    const float* __restrict__ bias)
{
    extern __shared__ __align__(1024) char sq[];
    const uint32_t sb = smem_u32(sq);
    const int tid = threadIdx.x;
    const int bid = blockIdx.x;
    const int lane = tid & 31, warp = tid >> 5;
    const int wm = warp & 3, wn = warp >> 2;
    const int qr = lane >> 2, qc = lane & 3;
    const int g = lane >> 3, rr = lane & 7;

    const int NT = (N_QKV / 128) * (M_ROWS / 128);    // 1536
    const int myTiles = (NT - bid + QK_GRID - 1) / QK_GRID;
    const int totalC = myTiles * 16;

    float acc[2][8][4];
#pragma unroll
    for (int i = 0; i < 2; i++)
#pragma unroll
        for (int j = 0; j < 8; j++)
#pragma unroll
            for (int e = 0; e < 4; e++) acc[i][j][e] = 0.f;

    if (tid == 0) {
        mbar_init(sb, 1); mbar_init(sb + 16, 1); mbar_init(sb + 32, 1);
    }
    __syncthreads();

    auto fillc = [&](int c) {
        const int t = bid + (c >> 4) * QK_GRID;
        const int kc = c & 15;
        const int bx = t % 12;
        const int by = t / 12;
        const int buf = c % 3;
        const uint32_t mb = sb + buf * 16;
        const uint32_t dst = sb + 1024 + buf * 24576;
        mbar_expect_tx(mb, 24576);
        bulk_g2s(dst,         g_xhB + (size_t)(by * 16 + kc) * 4096, 8192, mb);
        bulk_g2s(dst + 8192,  g_xlB + (size_t)(by * 16 + kc) * 4096, 8192, mb);
        bulk_g2s(dst + 16384, g_WqB + (size_t)(bx * 16 + kc) * 4096, 8192, mb);
    };

    if (tid == 0) { fillc(0); if (totalC > 1) fillc(1); }

    for (int c = 0; c < totalC; c++) {
        const int buf = c % 3;
        mbar_wait(sb + buf * 16, (c / 3) & 1);

        const uint32_t base = sb + 1024 + buf * 24576;
        const uint32_t Ah_s = base;
        const uint32_t Al_s = base + 8192;
        const uint32_t B_s  = base + 16384;

#pragma unroll
        for (int s = 0; s < 2; s++) {
            uint32_t afh[2][4], afl[2][4];
#pragma unroll
            for (int i = 0; i < 2; i++) {
                const int ar = wm * 32 + i * 16 + (lane & 15);
                const int au = s * 2 + (lane >> 4);
                const int aup = (au + (ar >> 1)) & 3;
                const uint32_t off = ar * 64 + aup * 16;
                ldsm4(afh[i], Ah_s + off);
                ldsm4(afl[i], Al_s + off);
            }
#pragma unroll
            for (int jp = 0; jp < 4; jp++) {
                const int br = s * 16 + 8 * (g & 1) + rr;
                const int bu = wn * 8 + jp * 2 + (g >> 1);
                const int bup = (bu & 8) | ((bu & 7) ^ (br & 7));
                const uint32_t off = br * 256 + bup * 16;
                uint32_t b4[4];
                ldsm4t(b4, B_s + off);
#pragma unroll
                for (int i = 0; i < 2; i++) {
                    mma16816h(acc[i][2 * jp],     afh[i], &b4[0]);
                    mma16816h(acc[i][2 * jp],     afl[i], &b4[0]);
                    mma16816h(acc[i][2 * jp + 1], afh[i], &b4[2]);
                    mma16816h(acc[i][2 * jp + 1], afl[i], &b4[2]);
                }
            }
        }
        __syncthreads();
        if (tid == 0 && c + 2 < totalC) fillc(c + 2);

        if ((c & 15) == 15) {
            // Epilogue for this tile; then reset acc.
            const int t = bid + (c >> 4) * QK_GRID;
            const int bx = t % 12;
            const int by = t / 12;
#pragma unroll
            for (int i = 0; i < 2; i++) {
                const int row0 = by * 128 + wm * 32 + i * 16 + qr;
                const int b = row0 >> 12;
                const int s0 = row0 & 4095;
#pragma unroll
                for (int j = 0; j < 8; j++) {
                    const int col = bx * 128 + wn * 64 + j * 8 + 2 * qc;
                    float v0 = acc[i][j][0] + bias[col];
                    float v1 = acc[i][j][1] + bias[col + 1];
                    float v2 = acc[i][j][2] + bias[col];
                    float v3 = acc[i][j][3] + bias[col + 1];
                    const int which = col >> 9;
                    const int e = col & 511;
                    const int h = e >> 6;
                    const int d = e & 63;
                    const size_t dst0 =
                        (((size_t)(b * NH + h) * S_LEN) + s0) * DH + d;
                    const size_t dst1 = dst0 + (size_t)8 * DH;
                    if (which == 0) { v0 *= QSCALE; v1 *= QSCALE;
                                      v2 *= QSCALE; v3 *= QSCALE; }
                    __half* ph = (which == 0) ? g_Qh : (which == 1) ? g_Kh : g_Vh;
                    __half2 h0 = __floats2half2_rn(v0, v1);
                    __half2 h1 = __floats2half2_rn(v2, v3);
                    *(uint32_t*)&ph[dst0] = *(uint32_t*)&h0;
                    *(uint32_t*)&ph[dst1] = *(uint32_t*)&h1;
                    acc[i][j][0] = 0.f; acc[i][j][1] = 0.f;
                    acc[i][j][2] = 0.f; acc[i][j][3] = 0.f;
                }
            }
        }
    }
}

// ---------------------------------------------------------------------------
// Out-projection GEMM, fp16 1-term (frozen from R15)
// ---------------------------------------------------------------------------
__global__ __launch_bounds__(256, 2) void gemm_out_f16_kernel(
    const float* __restrict__ bias, float* __restrict__ C)
{
    extern __shared__ __align__(16) __half sg[];
    const int tid  = threadIdx.x;
    const int bx = blockIdx.x, by = blockIdx.y;
    const int lane = tid & 31, warp = tid >> 5;
    const int wm = warp & 3, wn = warp >> 2;
    const int qr = lane >> 2, qc = lane & 3;
    const int g = lane >> 3, rr = lane & 7;
    const uint32_t sb = (uint32_t)__cvta_generic_to_shared(sg);
    const int N = EMB, K = EMB;

    float acc[2][8][4];
#pragma unroll
    for (int i = 0; i < 2; i++)
#pragma unroll
        for (int j = 0; j < 8; j++)
#pragma unroll
            for (int e = 0; e < 4; e++) acc[i][j][e] = 0.f;

    auto fill = [&](int kc, int buf) {
        const int k0 = kc * 32;
        const uint32_t base = sb + buf * GBUF * 2;
#pragma unroll
        for (int t = 0; t < 2; t++) {
            const int idx = t * 256 + tid;
            const int row = idx >> 2, c = idx & 3;
            const __half* src =
                g_atth + (size_t)(by * 128 + row) * K + k0 + c * 8;
            cpasync16(base + (row * ASTR + c * 8) * 2, src);
        }
#pragma unroll
        for (int t = 0; t < 2; t++) {
            const int idx = t * 256 + tid;
            const int row = idx >> 4, c = idx & 15;
            const __half* src =
                g_Wo16 + (size_t)(k0 + row) * N + bx * 128 + c * 8;
            cpasync16(base + (5120 + row * BSTR + c * 8) * 2, src);
        }
        asm volatile("cp.async.commit_group;\n");
    };

    fill(0, 0);
    const int nkc = K / 32;

    for (int kc = 0; kc < nkc; kc++) {
        const int buf = kc & 1;
        asm volatile("cp.async.wait_group 0;\n");
        __syncthreads();
        if (kc + 1 < nkc) fill(kc + 1, buf ^ 1);

        const uint32_t base = sb + buf * GBUF * 2;
        const uint32_t A_s = base;
        const uint32_t B_s = base + 5120 * 2;

#pragma unroll
        for (int s = 0; s < 2; s++) {
            uint32_t af[2][4];
#pragma unroll
            for (int i = 0; i < 2; i++) {
                const uint32_t off =
                    ((wm * 32 + i * 16 + (lane & 15)) * ASTR
                     + s * 16 + 8 * (lane >> 4)) * 2;
                ldsm4(af[i], A_s + off);
            }
#pragma unroll
            for (int jp = 0; jp < 4; jp++) {
                const uint32_t off =
                    ((s * 16 + 8 * (g & 1) + rr) * BSTR
                     + wn * 64 + jp * 16 + 8 * (g >> 1)) * 2;
                uint32_t b4[4];
                ldsm4t(b4, B_s + off);
#pragma unroll
                for (int i = 0; i < 2; i++) {
                    mma16816h(acc[i][2 * jp],     af[i], &b4[0]);
                    mma16816h(acc[i][2 * jp + 1], af[i], &b4[2]);
                }
            }
        }
        __syncthreads();
    }

#pragma unroll
    for (int i = 0; i < 2; i++) {
        const int row0 = by * 128 + wm * 32 + i * 16 + qr;
#pragma unroll
        for (int j = 0; j < 8; j++) {
            const int col = bx * 128 + wn * 64 + j * 8 + 2 * qc;
            float2 v0 = make_float2(acc[i][j][0] + bias[col],
                                    acc[i][j][1] + bias[col + 1]);
            float2 v1 = make_float2(acc[i][j][2] + bias[col],
                                    acc[i][j][3] + bias[col + 1]);
            *(float2*)(C + (size_t)row0 * N + col) = v0;
            *(float2*)(C + (size_t)(row0 + 8) * N + col) = v1;
        }
    }
}

// ---------------------------------------------------------------------------
// Flash attention: 3-stage pipeline, ONE sync per tile, exp2 softmax.
// ---------------------------------------------------------------------------
__global__ __launch_bounds__(256, 2) void attn_mma_kernel()
{
    extern __shared__ __align__(16) __half sm[];

    const int tid  = threadIdx.x;
    const int warp = tid >> 5;
    const int lane = tid & 31;
    const int qt = gridDim.x - 1 - blockIdx.x;   // longest-first
    const int bh = blockIdx.y;
    const int rowbase = qt * 128;
    const int qr = lane >> 2;
    const int qc = lane & 3;
    const int g  = lane >> 3;
    const int rr = lane & 7;

    const uint32_t smem_base = (uint32_t)__cvta_generic_to_shared(sm);

    const __half* srcs[2] = {
        g_Kh + (size_t)bh * S_LEN * DH,
        g_Vh + (size_t)bh * S_LEN * DH };

    uint32_t Qa[4][4];
    {
        const size_t qoff = ((size_t)bh * S_LEN + rowbase + warp * 16) * DH;
#pragma unroll
        for (int s = 0; s < 4; s++)
#pragma unroll
            for (int e = 0; e < 4; e++) {
                const int r = qr + 8 * (e & 1);
                const int c = 16 * s + 2 * qc + 8 * (e >> 1);
                Qa[s][e] = *(const uint32_t*)(g_Qh + qoff + (size_t)r * DH + c);
            }
    }

    float O[8][4];
#pragma unroll
    for (int j = 0; j < 8; j++)
#pragma unroll
        for (int e = 0; e < 4; e++) O[j][e] = 0.f;
    float m0 = -1e30f, m1 = -1e30f, l0 = 0.f, l1 = 0.f;

    const int nT = qt * 2 + 2;

    auto fill = [&](int kt) {
        const int buf = kt % ATTN_STAGES;
#pragma unroll
        for (int i = 0; i < 4; i++) {
            const int arr = i >> 1;
            const int e = ((i & 1) << 8) + tid;
            const int row = e >> 3;
            const int grp = e & 7;
            const __half* src = srcs[arr] + (size_t)kt * 64 * DH
                              + (size_t)row * DH + grp * 8;
            const uint32_t dst = smem_base +
                ((arr * ATTN_STAGES + buf) * TILE_E + row * KSTR + grp * 8) * 2;
            cpasync16(dst, src);
        }
        asm volatile("cp.async.commit_group;\n");
    };

    fill(0);
    if (nT > 1) fill(1);

    for (int kt = 0; kt < nT; kt++) {
        const int buf = kt % ATTN_STAGES;
        asm volatile("cp.async.wait_group 1;\n");
        __syncthreads();
        if (kt + 2 < nT) fill(kt + 2);

        const uint32_t K_t = smem_base + ((0 * ATTN_STAGES + buf) * TILE_E) * 2;
        const uint32_t V_t = smem_base + ((1 * ATTN_STAGES + buf) * TILE_E) * 2;

        float S[8][4];
#pragma unroll
        for (int j = 0; j < 8; j++)
#pragma unroll
            for (int e = 0; e < 4; e++) S[j][e] = 0.f;

#pragma unroll
        for (int s = 0; s < 4; s++) {
#pragma unroll
            for (int jp = 0; jp < 4; jp++) {
                const uint32_t off = ((16 * jp + 8 * (g >> 1) + rr) * KSTR
                                    + 16 * s + 8 * (g & 1)) * 2;
                uint32_t bv[4];
                ldsm4(bv, K_t + off);
                mma16816h(S[2 * jp],     Qa[s], &bv[0]);
                mma16816h(S[2 * jp + 1], Qa[s], &bv[2]);
            }
        }

        const int grow0 = rowbase + warp * 16 + qr;
        if (kt * 64 + 63 > rowbase + warp * 16) {
#pragma unroll
            for (int j = 0; j < 8; j++)
#pragma unroll
                for (int e = 0; e < 4; e++) {
                    const int col = kt * 64 + 8 * j + 2 * qc + (e & 1);
                    const int row = grow0 + 8 * (e >> 1);
                    if (col > row) S[j][e] = -1e30f;
                }
        }

        float mx0 = -1e30f, mx1 = -1e30f;
#pragma unroll
        for (int j = 0; j < 8; j++) {
            mx0 = fmaxf(mx0, fmaxf(S[j][0], S[j][1]));
            mx1 = fmaxf(mx1, fmaxf(S[j][2], S[j][3]));
        }
        mx0 = fmaxf(mx0, __shfl_xor_sync(0xffffffffu, mx0, 1));
        mx0 = fmaxf(mx0, __shfl_xor_sync(0xffffffffu, mx0, 2));
        mx1 = fmaxf(mx1, __shfl_xor_sync(0xffffffffu, mx1, 1));
        mx1 = fmaxf(mx1, __shfl_xor_sync(0xffffffffu, mx1, 2));

        const float nm0 = fmaxf(m0, mx0);
        const float nm1 = fmaxf(m1, mx1);
        const float c0 = ex2a(m0 - nm0);
        const float c1 = ex2a(m1 - nm1);
        m0 = nm0; m1 = nm1;

        float s0 = 0.f, s1 = 0.f;
#pragma unroll
        for (int j = 0; j < 8; j++) {
            S[j][0] = ex2a(S[j][0] - m0); s0 += S[j][0];
            S[j][1] = ex2a(S[j][1] - m0); s0 += S[j][1];
            S[j][2] = ex2a(S[j][2] - m1); s1 += S[j][2];
            S[j][3] = ex2a(S[j][3] - m1); s1 += S[j][3];
        }
        s0 += __shfl_xor_sync(0xffffffffu, s0, 1);
        s0 += __shfl_xor_sync(0xffffffffu, s0, 2);
        s1 += __shfl_xor_sync(0xffffffffu, s1, 1);
        s1 += __shfl_xor_sync(0xffffffffu, s1, 2);
        l0 = l0 * c0 + s0;
        l1 = l1 * c1 + s1;

        if (__any_sync(0xffffffffu, (c0 != 1.f) || (c1 != 1.f))) {
#pragma unroll
            for (int j = 0; j < 8; j++) {
                O[j][0] *= c0; O[j][1] *= c0;
                O[j][2] *= c1; O[j][3] *= c1;
            }
        }

#pragma unroll
        for (int s = 0; s < 4; s++) {
            uint32_t Pa[4];
            {
                __half2 p0 = __floats2half2_rn(S[2 * s][0],     S[2 * s][1]);
                __half2 p1 = __floats2half2_rn(S[2 * s][2],     S[2 * s][3]);
                __half2 p2 = __floats2half2_rn(S[2 * s + 1][0], S[2 * s + 1][1]);
                __half2 p3 = __floats2half2_rn(S[2 * s + 1][2], S[2 * s + 1][3]);
                Pa[0] = *(uint32_t*)&p0;
                Pa[1] = *(uint32_t*)&p1;
                Pa[2] = *(uint32_t*)&p2;
                Pa[3] = *(uint32_t*)&p3;
            }
#pragma unroll
            for (int jp = 0; jp < 4; jp++) {
                const uint32_t off = ((16 * s + 8 * (g & 1) + rr) * KSTR
                                    + 16 * jp + 8 * (g >> 1)) * 2;
                uint32_t bv[4];
                ldsm4t(bv, V_t + off);
                mma16816h(O[2 * jp],     Pa, &bv[0]);
                mma16816h(O[2 * jp + 1], Pa, &bv[2]);
            }
        }
        // no bottom sync: 3-stage buffering makes it safe
    }

    const float inv0 = 1.f / l0;
    const float inv1 = 1.f / l1;
    const int b = bh >> 3;
    const int h = bh & 7;
    const int row0 = rowbase + warp * 16 + qr;
    const int row1 = row0 + 8;
#pragma unroll
    for (int j = 0; j < 8; j++) {
        const int col = h * DH + 8 * j + 2 * qc;
        const size_t o0 = ((size_t)b * S_LEN + row0) * EMB + col;
        const size_t o1 = ((size_t)b * S_LEN + row1) * EMB + col;
        __half2 h0 = __floats2half2_rn(O[j][0] * inv0, O[j][1] * inv0);
        __half2 h1 = __floats2half2_rn(O[j][2] * inv1, O[j][3] * inv1);
        *(uint32_t*)&g_atth[o0] = *(uint32_t*)&h0;
        *(uint32_t*)&g_atth[o1] = *(uint32_t*)&h1;
    }
}

// ---------------------------------------------------------------------------
extern "C" void kernel_launch(void* const* d_in, const int* in_sizes, int n_in,
                              void* d_out, int out_size)
{
    const float* x    = (const float*)d_in[0];
    const float* Wqkv = (const float*)d_in[1];
    const float* bqkv = (const float*)d_in[2];
    const float* Wo   = (const float*)d_in[3];
    const float* bo   = (const float*)d_in[4];
    for (int i = 0; i < n_in; i++) {
        switch (in_sizes[i]) {
            case 8388608: x    = (const float*)d_in[i]; break;
            case 786432:  Wqkv = (const float*)d_in[i]; break;
            case 1536:    bqkv = (const float*)d_in[i]; break;
            case 262144:  Wo   = (const float*)d_in[i]; break;
            case 512:     bo   = (const float*)d_in[i]; break;
        }
    }
    float* out = (float*)d_out;

    static bool init = false;
    if (!init) {
        cudaFuncSetAttribute(attn_mma_kernel,
                             cudaFuncAttributeMaxDynamicSharedMemorySize,
                             ATTN_SMEM);
        cudaFuncSetAttribute(gemm_out_f16_kernel,
                             cudaFuncAttributeMaxDynamicSharedMemorySize,
                             GSMEM);
        cudaFuncSetAttribute(gemm_qkv_blk_kernel,
                             cudaFuncAttributeMaxDynamicSharedMemorySize,
                             QK_SMEM);
        init = true;
    }

    // 0) merged splits
    split_all_kernel<<<4992, 256>>>(x, Wqkv, Wo);

    // 1) QKV projection (persistent, continuous pipeline)
    gemm_qkv_blk_kernel<<<QK_GRID, 256, QK_SMEM>>>(bqkv);

    // 2) Attention
    attn_mma_kernel<<<dim3(S_LEN / 128, BATCH * NH), 256, ATTN_SMEM>>>();

    // 3) Output projection
    gemm_out_f16_kernel<<<dim3(EMB / 128, M_ROWS / 128), 256, GSMEM>>>(bo, out);
}

// round 17
// speedup vs baseline: 17.0625x; 1.0988x over previous
#include <cuda_runtime.h>
#include <cuda_bf16.h>
#include <cuda_fp16.h>
#include <math.h>
#include <stdint.h>

#define S_LEN 4096
#define EMB   512
#define NH    8
#define DH    64
#define BATCH 4
#define M_ROWS (BATCH * S_LEN)          // 16384
#define N_QKV  (3 * EMB)                // 1536
#define KSTR   72
#define TILE_E (64 * KSTR)
#define ATTN_STAGES 3
#define ATTN_SMEM (ATTN_STAGES * 2 * TILE_E * 2)   // 55296

// out-proj GEMM smem (fp16 1-term A + 1-term B), persistent, 3 stages
#define ASTR 40
#define BSTR 136
#define GBUF 9472
#define GSMEM (3 * GBUF * 2)             // 56832
#define OUT_GRID 296

// QKV persistent GEMM smem: mbars @0, 3 stages x 16KB (1-term A + B)
#define QK_STAGES 3
#define QK_SMEM (1024 + QK_STAGES * 16384)   // 50176
#define QK_GRID 296

#define QSCALE 0.18033688f               // 0.125 * log2(e)

// Scratch (allocation-free: __device__ globals)
__device__ __align__(16) __half g_xB[(size_t)M_ROWS * EMB];       // x fp16, blocked
__device__ __align__(16) __half g_WqB[(size_t)EMB * N_QKV];       // Wqkv fp16, blocked
__device__ __align__(16) __half g_Wo16[(size_t)EMB * EMB];
__device__ __align__(16) __half g_Qh[(size_t)BATCH * NH * S_LEN * DH];
__device__ __align__(16) __half g_Kh[(size_t)BATCH * NH * S_LEN * DH];
__device__ __align__(16) __half g_Vh[(size_t)BATCH * NH * S_LEN * DH];
__device__ __align__(16) __half g_atth[(size_t)M_ROWS * EMB];

__device__ __forceinline__ float ex2a(float x)
{
    float y;
    asm("ex2.approx.f32 %0, %1;" : "=f"(y) : "f"(x));
    return y;
}

__device__ __forceinline__ void mma16816h(float c[4], const uint32_t a[4],
                                          const uint32_t* b)
{
    asm volatile(
        "mma.sync.aligned.m16n8k16.row.col.f32.f16.f16.f32 "
        "{%0,%1,%2,%3}, {%4,%5,%6,%7}, {%8,%9}, {%0,%1,%2,%3};\n"
        : "+f"(c[0]), "+f"(c[1]), "+f"(c[2]), "+f"(c[3])
        : "r"(a[0]), "r"(a[1]), "r"(a[2]), "r"(a[3]), "r"(b[0]), "r"(b[1]));
}

__device__ __forceinline__ void ldsm4(uint32_t r[4], uint32_t addr)
{
    asm volatile("ldmatrix.sync.aligned.m8n8.x4.shared.b16 {%0,%1,%2,%3}, [%4];\n"
                 : "=r"(r[0]), "=r"(r[1]), "=r"(r[2]), "=r"(r[3]) : "r"(addr));
}

__device__ __forceinline__ void ldsm4t(uint32_t r[4], uint32_t addr)
{
    asm volatile("ldmatrix.sync.aligned.m8n8.x4.trans.shared.b16 {%0,%1,%2,%3}, [%4];\n"
                 : "=r"(r[0]), "=r"(r[1]), "=r"(r[2]), "=r"(r[3]) : "r"(addr));
}

__device__ __forceinline__ void cpasync16(uint32_t s, const void* g)
{
    asm volatile("cp.async.cg.shared.global [%0], [%1], 16;\n" :: "r"(s), "l"(g));
}

__device__ __forceinline__ void bulk_g2s(uint32_t dst, const void* src,
                                         uint32_t bytes, uint32_t mbar)
{
    asm volatile(
        "cp.async.bulk.shared::cta.global.mbarrier::complete_tx::bytes "
        "[%0], [%1], %2, [%3];\n"
        :: "r"(dst), "l"(src), "r"(bytes), "r"(mbar) : "memory");
}

__device__ __forceinline__ void mbar_init(uint32_t mbar, uint32_t cnt)
{
    asm volatile("mbarrier.init.shared.b64 [%0], %1;" :: "r"(mbar), "r"(cnt) : "memory");
}

__device__ __forceinline__ void mbar_expect_tx(uint32_t mbar, uint32_t bytes)
{
    asm volatile("mbarrier.arrive.expect_tx.shared.b64 _, [%0], %1;"
                 :: "r"(mbar), "r"(bytes) : "memory");
}

__device__ __forceinline__ void mbar_wait(uint32_t mbar, uint32_t parity)
{
    uint32_t done;
    asm volatile(
        "{\n\t.reg .pred p;\n\t"
        "mbarrier.try_wait.parity.acquire.cta.shared::cta.b64 p, [%1], %2;\n\t"
        "selp.b32 %0, 1, 0, p;\n\t}"
        : "=r"(done) : "r"(mbar), "r"(parity) : "memory");
    if (!done) {
        asm volatile(
            "{\n\t.reg .pred P1;\n\t"
            "WL_%=:\n\t"
            "mbarrier.try_wait.parity.acquire.cta.shared::cta.b64 P1, [%0], %1, 0x989680;\n\t"
            "@P1 bra.uni WD_%=;\n\t"
            "bra.uni WL_%=;\n\t"
            "WD_%=:\n\t}"
            :: "r"(mbar), "r"(parity) : "memory");
    }
}

__device__ __forceinline__ uint32_t smem_u32(const void* p)
{
    uint32_t a;
    asm("{ .reg .u64 t; cvta.to.shared.u64 t, %1; cvt.u32.u64 %0, t; }"
        : "=r"(a) : "l"(p));
    return a;
}

// ---------------------------------------------------------------------------
// Merged splits: [0,4096) -> x fp16 blocked; [4096,4480) -> Wqkv; rest -> Wo
// ---------------------------------------------------------------------------
__global__ __launch_bounds__(256) void split_all_kernel(
    const float* __restrict__ x, const float* __restrict__ Wq,
    const float* __restrict__ Wo)
{
    const int bid = blockIdx.x;
    if (bid < 4096) {
        const int idx = bid * 256 + threadIdx.x;
        const int row = idx >> 6;
        const int cu = idx & 63;
        const int kc = cu >> 2;
        const int u = cu & 3;
        const int by = row >> 7;
        const int r = row & 127;
        const int up = (u + (r >> 1)) & 3;
        const size_t off = (size_t)(by * 16 + kc) * 4096 + r * 32 + up * 8;

        const float4 a0 = *(const float4*)(x + (size_t)row * 512 + cu * 8);
        const float4 a1 = *(const float4*)(x + (size_t)row * 512 + cu * 8 + 4);
        uint4 H;
        __half2 h;
        h = __floats2half2_rn(a0.x, a0.y); H.x = *(uint32_t*)&h;
        h = __floats2half2_rn(a0.z, a0.w); H.y = *(uint32_t*)&h;
        h = __floats2half2_rn(a1.x, a1.y); H.z = *(uint32_t*)&h;
        h = __floats2half2_rn(a1.z, a1.w); H.w = *(uint32_t*)&h;
        *(uint4*)(g_xB + off) = H;
    } else if (bid < 4480) {
        const int idx = (bid - 4096) * 256 + threadIdx.x;
        const int k = idx / 192;
        const int cu = idx - k * 192;
        const int bx = cu >> 4;
        const int u = cu & 15;
        const int kc = k >> 5;
        const int r = k & 31;
        const int up = (u & 8) | ((u & 7) ^ (r & 7));
        const size_t off = (size_t)(bx * 16 + kc) * 4096 + r * 128 + up * 8;

        const float4 a0 = *(const float4*)(Wq + (size_t)k * N_QKV + cu * 8);
        const float4 a1 = *(const float4*)(Wq + (size_t)k * N_QKV + cu * 8 + 4);
        uint4 H;
        __half2 h;
        h = __floats2half2_rn(a0.x, a0.y); H.x = *(uint32_t*)&h;
        h = __floats2half2_rn(a0.z, a0.w); H.y = *(uint32_t*)&h;
        h = __floats2half2_rn(a1.x, a1.y); H.z = *(uint32_t*)&h;
        h = __floats2half2_rn(a1.z, a1.w); H.w = *(uint32_t*)&h;
        *(uint4*)(g_WqB + off) = H;
    } else {
        const int idx = (bid - 4480) * 256 + threadIdx.x;
        if (idx >= EMB * EMB / 2) return;
        const float2 v = ((const float2*)Wo)[idx];
        __half2 h = __floats2half2_rn(v.x, v.y);
        ((uint32_t*)g_Wo16)[idx] = *(uint32_t*)&h;
    }
}

// ---------------------------------------------------------------------------
// PERSISTENT QKV GEMM, fp16 1-term, continuous 3-stage bulk pipeline.
// ---------------------------------------------------------------------------
__global__ __launch_bounds__(256, 2) void gemm_qkv_blk_kernel(
    const float* __restrict__ bias)
{
    extern __shared__ __align__(1024) char sq[];
    const uint32_t sb = smem_u32(sq);
    const int tid = threadIdx.x;
    const int bid = blockIdx.x;
    const int lane = tid & 31, warp = tid >> 5;
    const int wm = warp & 3, wn = warp >> 2;
    const int qr = lane >> 2, qc = lane & 3;
    const int g = lane >> 3, rr = lane & 7;

    const int NT = (N_QKV / 128) * (M_ROWS / 128);    // 1536
    const int myTiles = (NT - bid + QK_GRID - 1) / QK_GRID;
    const int totalC = myTiles * 16;

    float acc[2][8][4];
#pragma unroll
    for (int i = 0; i < 2; i++)
#pragma unroll
        for (int j = 0; j < 8; j++)
#pragma unroll
            for (int e = 0; e < 4; e++) acc[i][j][e] = 0.f;

    if (tid == 0) {
        mbar_init(sb, 1); mbar_init(sb + 16, 1); mbar_init(sb + 32, 1);
    }
    __syncthreads();

    auto fillc = [&](int c) {
        const int t = bid + (c >> 4) * QK_GRID;
        const int kc = c & 15;
        const int bx = t % 12;
        const int by = t / 12;
        const int buf = c % 3;
        const uint32_t mb = sb + buf * 16;
        const uint32_t dst = sb + 1024 + buf * 16384;
        mbar_expect_tx(mb, 16384);
        bulk_g2s(dst,        g_xB  + (size_t)(by * 16 + kc) * 4096, 8192, mb);
        bulk_g2s(dst + 8192, g_WqB + (size_t)(bx * 16 + kc) * 4096, 8192, mb);
    };

    if (tid == 0) { fillc(0); if (totalC > 1) fillc(1); }

    for (int c = 0; c < totalC; c++) {
        const int buf = c % 3;
        mbar_wait(sb + buf * 16, (c / 3) & 1);

        const uint32_t base = sb + 1024 + buf * 16384;
        const uint32_t A_s = base;
        const uint32_t B_s = base + 8192;

#pragma unroll
        for (int s = 0; s < 2; s++) {
            uint32_t af[2][4];
#pragma unroll
            for (int i = 0; i < 2; i++) {
                const int ar = wm * 32 + i * 16 + (lane & 15);
                const int au = s * 2 + (lane >> 4);
                const int aup = (au + (ar >> 1)) & 3;
                ldsm4(af[i], A_s + ar * 64 + aup * 16);
            }
#pragma unroll
            for (int jp = 0; jp < 4; jp++) {
                const int br = s * 16 + 8 * (g & 1) + rr;
                const int bu = wn * 8 + jp * 2 + (g >> 1);
                const int bup = (bu & 8) | ((bu & 7) ^ (br & 7));
                uint32_t b4[4];
                ldsm4t(b4, B_s + br * 256 + bup * 16);
#pragma unroll
                for (int i = 0; i < 2; i++) {
                    mma16816h(acc[i][2 * jp],     af[i], &b4[0]);
                    mma16816h(acc[i][2 * jp + 1], af[i], &b4[2]);
                }
            }
        }
        __syncthreads();
        if (tid == 0 && c + 2 < totalC) fillc(c + 2);

        if ((c & 15) == 15) {
            const int t = bid + (c >> 4) * QK_GRID;
            const int bx = t % 12;
            const int by = t / 12;
#pragma unroll
            for (int i = 0; i < 2; i++) {
                const int row0 = by * 128 + wm * 32 + i * 16 + qr;
                const int b = row0 >> 12;
                const int s0 = row0 & 4095;
#pragma unroll
                for (int j = 0; j < 8; j++) {
                    const int col = bx * 128 + wn * 64 + j * 8 + 2 * qc;
                    float v0 = acc[i][j][0] + bias[col];
                    float v1 = acc[i][j][1] + bias[col + 1];
                    float v2 = acc[i][j][2] + bias[col];
                    float v3 = acc[i][j][3] + bias[col + 1];
                    const int which = col >> 9;
                    const int e = col & 511;
                    const int h = e >> 6;
                    const int d = e & 63;
                    const size_t dst0 =
                        (((size_t)(b * NH + h) * S_LEN) + s0) * DH + d;
                    const size_t dst1 = dst0 + (size_t)8 * DH;
                    if (which == 0) { v0 *= QSCALE; v1 *= QSCALE;
                                      v2 *= QSCALE; v3 *= QSCALE; }
                    __half* ph = (which == 0) ? g_Qh : (which == 1) ? g_Kh : g_Vh;
                    __half2 h0 = __floats2half2_rn(v0, v1);
                    __half2 h1 = __floats2half2_rn(v2, v3);
                    *(uint32_t*)&ph[dst0] = *(uint32_t*)&h0;
                    *(uint32_t*)&ph[dst1] = *(uint32_t*)&h1;
                    acc[i][j][0] = 0.f; acc[i][j][1] = 0.f;
                    acc[i][j][2] = 0.f; acc[i][j][3] = 0.f;
                }
            }
        }
    }
}

// ---------------------------------------------------------------------------
// PERSISTENT out-projection GEMM, fp16 1-term, continuous 3-stage pipeline.
// ---------------------------------------------------------------------------
__global__ __launch_bounds__(256, 2) void gemm_out_f16_kernel(
    const float* __restrict__ bias, float* __restrict__ C)
{
    extern __shared__ __align__(16) __half sg[];
    const int tid  = threadIdx.x;
    const int bid = blockIdx.x;
    const int lane = tid & 31, warp = tid >> 5;
    const int wm = warp & 3, wn = warp >> 2;
    const int qr = lane >> 2, qc = lane & 3;
    const int g = lane >> 3, rr = lane & 7;
    const uint32_t sb = (uint32_t)__cvta_generic_to_shared(sg);
    const int N = EMB, K = EMB;

    const int NT = 512;                   // 4 bx x 128 by
    const int myTiles = (NT - bid + OUT_GRID - 1) / OUT_GRID;
    const int totalC = myTiles * 16;

    float acc[2][8][4];
#pragma unroll
    for (int i = 0; i < 2; i++)
#pragma unroll
        for (int j = 0; j < 8; j++)
#pragma unroll
            for (int e = 0; e < 4; e++) acc[i][j][e] = 0.f;

    auto fill = [&](int c) {
        const int t = bid + (c >> 4) * OUT_GRID;
        const int kc = c & 15;
        const int bx = t & 3;
        const int by = t >> 2;
        const int k0 = kc * 32;
        const uint32_t base = sb + (c % 3) * GBUF * 2;
#pragma unroll
        for (int tt = 0; tt < 2; tt++) {
            const int idx = tt * 256 + tid;
            const int row = idx >> 2, cc = idx & 3;
            const __half* src =
                g_atth + (size_t)(by * 128 + row) * K + k0 + cc * 8;
            cpasync16(base + (row * ASTR + cc * 8) * 2, src);
        }
#pragma unroll
        for (int tt = 0; tt < 2; tt++) {
            const int idx = tt * 256 + tid;
            const int row = idx >> 4, cc = idx & 15;
            const __half* src =
                g_Wo16 + (size_t)(k0 + row) * N + bx * 128 + cc * 8;
            cpasync16(base + (5120 + row * BSTR + cc * 8) * 2, src);
        }
        asm volatile("cp.async.commit_group;\n");
    };

    fill(0);
    if (totalC > 1) fill(1);

    for (int c = 0; c < totalC; c++) {
        asm volatile("cp.async.wait_group 1;\n");
        __syncthreads();
        if (c + 2 < totalC) fill(c + 2);

        const uint32_t base = sb + (c % 3) * GBUF * 2;
        const uint32_t A_s = base;
        const uint32_t B_s = base + 5120 * 2;

#pragma unroll
        for (int s = 0; s < 2; s++) {
            uint32_t af[2][4];
#pragma unroll
            for (int i = 0; i < 2; i++) {
                const uint32_t off =
                    ((wm * 32 + i * 16 + (lane & 15)) * ASTR
                     + s * 16 + 8 * (lane >> 4)) * 2;
                ldsm4(af[i], A_s + off);
            }
#pragma unroll
            for (int jp = 0; jp < 4; jp++) {
                const uint32_t off =
                    ((s * 16 + 8 * (g & 1) + rr) * BSTR
                     + wn * 64 + jp * 16 + 8 * (g >> 1)) * 2;
                uint32_t b4[4];
                ldsm4t(b4, B_s + off);
#pragma unroll
                for (int i = 0; i < 2; i++) {
                    mma16816h(acc[i][2 * jp],     af[i], &b4[0]);
                    mma16816h(acc[i][2 * jp + 1], af[i], &b4[2]);
                }
            }
        }

        if ((c & 15) == 15) {
            const int t = bid + (c >> 4) * OUT_GRID;
            const int bx = t & 3;
            const int by = t >> 2;
#pragma unroll
            for (int i = 0; i < 2; i++) {
                const int row0 = by * 128 + wm * 32 + i * 16 + qr;
#pragma unroll
                for (int j = 0; j < 8; j++) {
                    const int col = bx * 128 + wn * 64 + j * 8 + 2 * qc;
                    float2 v0 = make_float2(acc[i][j][0] + bias[col],
                                            acc[i][j][1] + bias[col + 1]);
                    float2 v1 = make_float2(acc[i][j][2] + bias[col],
                                            acc[i][j][3] + bias[col + 1]);
                    *(float2*)(C + (size_t)row0 * N + col) = v0;
                    *(float2*)(C + (size_t)(row0 + 8) * N + col) = v1;
                    acc[i][j][0] = 0.f; acc[i][j][1] = 0.f;
                    acc[i][j][2] = 0.f; acc[i][j][3] = 0.f;
                }
            }
        }
    }
}

// ---------------------------------------------------------------------------
// Flash attention (byte-frozen from R16)
// ---------------------------------------------------------------------------
__global__ __launch_bounds__(256, 2) void attn_mma_kernel()
{
    extern __shared__ __align__(16) __half sm[];

    const int tid  = threadIdx.x;
    const int warp = tid >> 5;
    const int lane = tid & 31;
    const int qt = gridDim.x - 1 - blockIdx.x;
    const int bh = blockIdx.y;
    const int rowbase = qt * 128;
    const int qr = lane >> 2;
    const int qc = lane & 3;
    const int g  = lane >> 3;
    const int rr = lane & 7;

    const uint32_t smem_base = (uint32_t)__cvta_generic_to_shared(sm);

    const __half* srcs[2] = {
        g_Kh + (size_t)bh * S_LEN * DH,
        g_Vh + (size_t)bh * S_LEN * DH };

    uint32_t Qa[4][4];
    {
        const size_t qoff = ((size_t)bh * S_LEN + rowbase + warp * 16) * DH;
#pragma unroll
        for (int s = 0; s < 4; s++)
#pragma unroll
            for (int e = 0; e < 4; e++) {
                const int r = qr + 8 * (e & 1);
                const int c = 16 * s + 2 * qc + 8 * (e >> 1);
                Qa[s][e] = *(const uint32_t*)(g_Qh + qoff + (size_t)r * DH + c);
            }
    }

    float O[8][4];
#pragma unroll
    for (int j = 0; j < 8; j++)
#pragma unroll
        for (int e = 0; e < 4; e++) O[j][e] = 0.f;
    float m0 = -1e30f, m1 = -1e30f, l0 = 0.f, l1 = 0.f;

    const int nT = qt * 2 + 2;

    auto fill = [&](int kt) {
        const int buf = kt % ATTN_STAGES;
#pragma unroll
        for (int i = 0; i < 4; i++) {
            const int arr = i >> 1;
            const int e = ((i & 1) << 8) + tid;
            const int row = e >> 3;
            const int grp = e & 7;
            const __half* src = srcs[arr] + (size_t)kt * 64 * DH
                              + (size_t)row * DH + grp * 8;
            const uint32_t dst = smem_base +
                ((arr * ATTN_STAGES + buf) * TILE_E + row * KSTR + grp * 8) * 2;
            cpasync16(dst, src);
        }
        asm volatile("cp.async.commit_group;\n");
    };

    fill(0);
    if (nT > 1) fill(1);

    for (int kt = 0; kt < nT; kt++) {
        const int buf = kt % ATTN_STAGES;
        asm volatile("cp.async.wait_group 1;\n");
        __syncthreads();
        if (kt + 2 < nT) fill(kt + 2);

        const uint32_t K_t = smem_base + ((0 * ATTN_STAGES + buf) * TILE_E) * 2;
        const uint32_t V_t = smem_base + ((1 * ATTN_STAGES + buf) * TILE_E) * 2;

        float S[8][4];
#pragma unroll
        for (int j = 0; j < 8; j++)
#pragma unroll
            for (int e = 0; e < 4; e++) S[j][e] = 0.f;

#pragma unroll
        for (int s = 0; s < 4; s++) {
#pragma unroll
            for (int jp = 0; jp < 4; jp++) {
                const uint32_t off = ((16 * jp + 8 * (g >> 1) + rr) * KSTR
                                    + 16 * s + 8 * (g & 1)) * 2;
                uint32_t bv[4];
                ldsm4(bv, K_t + off);
                mma16816h(S[2 * jp],     Qa[s], &bv[0]);
                mma16816h(S[2 * jp + 1], Qa[s], &bv[2]);
            }
        }

        const int grow0 = rowbase + warp * 16 + qr;
        if (kt * 64 + 63 > rowbase + warp * 16) {
#pragma unroll
            for (int j = 0; j < 8; j++)
#pragma unroll
                for (int e = 0; e < 4; e++) {
                    const int col = kt * 64 + 8 * j + 2 * qc + (e & 1);
                    const int row = grow0 + 8 * (e >> 1);
                    if (col > row) S[j][e] = -1e30f;
                }
        }

        float mx0 = -1e30f, mx1 = -1e30f;
#pragma unroll
        for (int j = 0; j < 8; j++) {
            mx0 = fmaxf(mx0, fmaxf(S[j][0], S[j][1]));
            mx1 = fmaxf(mx1, fmaxf(S[j][2], S[j][3]));
        }
        mx0 = fmaxf(mx0, __shfl_xor_sync(0xffffffffu, mx0, 1));
        mx0 = fmaxf(mx0, __shfl_xor_sync(0xffffffffu, mx0, 2));
        mx1 = fmaxf(mx1, __shfl_xor_sync(0xffffffffu, mx1, 1));
        mx1 = fmaxf(mx1, __shfl_xor_sync(0xffffffffu, mx1, 2));

        const float nm0 = fmaxf(m0, mx0);
        const float nm1 = fmaxf(m1, mx1);
        const float c0 = ex2a(m0 - nm0);
        const float c1 = ex2a(m1 - nm1);
        m0 = nm0; m1 = nm1;

        float s0 = 0.f, s1 = 0.f;
#pragma unroll
        for (int j = 0; j < 8; j++) {
            S[j][0] = ex2a(S[j][0] - m0); s0 += S[j][0];
            S[j][1] = ex2a(S[j][1] - m0); s0 += S[j][1];
            S[j][2] = ex2a(S[j][2] - m1); s1 += S[j][2];
            S[j][3] = ex2a(S[j][3] - m1); s1 += S[j][3];
        }
        s0 += __shfl_xor_sync(0xffffffffu, s0, 1);
        s0 += __shfl_xor_sync(0xffffffffu, s0, 2);
        s1 += __shfl_xor_sync(0xffffffffu, s1, 1);
        s1 += __shfl_xor_sync(0xffffffffu, s1, 2);
        l0 = l0 * c0 + s0;
        l1 = l1 * c1 + s1;

        if (__any_sync(0xffffffffu, (c0 != 1.f) || (c1 != 1.f))) {
#pragma unroll
            for (int j = 0; j < 8; j++) {
                O[j][0] *= c0; O[j][1] *= c0;
                O[j][2] *= c1; O[j][3] *= c1;
            }
        }

#pragma unroll
        for (int s = 0; s < 4; s++) {
            uint32_t Pa[4];
            {
                __half2 p0 = __floats2half2_rn(S[2 * s][0],     S[2 * s][1]);
                __half2 p1 = __floats2half2_rn(S[2 * s][2],     S[2 * s][3]);
                __half2 p2 = __floats2half2_rn(S[2 * s + 1][0], S[2 * s + 1][1]);
                __half2 p3 = __floats2half2_rn(S[2 * s + 1][2], S[2 * s + 1][3]);
                Pa[0] = *(uint32_t*)&p0;
                Pa[1] = *(uint32_t*)&p1;
                Pa[2] = *(uint32_t*)&p2;
                Pa[3] = *(uint32_t*)&p3;
            }
#pragma unroll
            for (int jp = 0; jp < 4; jp++) {
                const uint32_t off = ((16 * s + 8 * (g & 1) + rr) * KSTR
                                    + 16 * jp + 8 * (g >> 1)) * 2;
                uint32_t bv[4];
                ldsm4t(bv, V_t + off);
                mma16816h(O[2 * jp],     Pa, &bv[0]);
                mma16816h(O[2 * jp + 1], Pa, &bv[2]);
            }
        }
    }

    const float inv0 = 1.f / l0;
    const float inv1 = 1.f / l1;
    const int b = bh >> 3;
    const int h = bh & 7;
    const int row0 = rowbase + warp * 16 + qr;
    const int row1 = row0 + 8;
#pragma unroll
    for (int j = 0; j < 8; j++) {
        const int col = h * DH + 8 * j + 2 * qc;
        const size_t o0 = ((size_t)b * S_LEN + row0) * EMB + col;
        const size_t o1 = ((size_t)b * S_LEN + row1) * EMB + col;
        __half2 h0 = __floats2half2_rn(O[j][0] * inv0, O[j][1] * inv0);
        __half2 h1 = __floats2half2_rn(O[j][2] * inv1, O[j][3] * inv1);
        *(uint32_t*)&g_atth[o0] = *(uint32_t*)&h0;
        *(uint32_t*)&g_atth[o1] = *(uint32_t*)&h1;
    }
}

// ---------------------------------------------------------------------------
extern "C" void kernel_launch(void* const* d_in, const int* in_sizes, int n_in,
                              void* d_out, int out_size)
{
    const float* x    = (const float*)d_in[0];
    const float* Wqkv = (const float*)d_in[1];
    const float* bqkv = (const float*)d_in[2];
    const float* Wo   = (const float*)d_in[3];
    const float* bo   = (const float*)d_in[4];
    for (int i = 0; i < n_in; i++) {
        switch (in_sizes[i]) {
            case 8388608: x    = (const float*)d_in[i]; break;
            case 786432:  Wqkv = (const float*)d_in[i]; break;
            case 1536:    bqkv = (const float*)d_in[i]; break;
            case 262144:  Wo   = (const float*)d_in[i]; break;
            case 512:     bo   = (const float*)d_in[i]; break;
        }
    }
    float* out = (float*)d_out;

    static bool init = false;
    if (!init) {
        cudaFuncSetAttribute(attn_mma_kernel,
                             cudaFuncAttributeMaxDynamicSharedMemorySize,
                             ATTN_SMEM);
        cudaFuncSetAttribute(gemm_out_f16_kernel,
                             cudaFuncAttributeMaxDynamicSharedMemorySize,
                             GSMEM);
        cudaFuncSetAttribute(gemm_qkv_blk_kernel,
                             cudaFuncAttributeMaxDynamicSharedMemorySize,
                             QK_SMEM);
        init = true;
    }

    // 0) merged splits (x single fp16 now)
    split_all_kernel<<<4992, 256>>>(x, Wqkv, Wo);

    // 1) QKV projection (persistent, fp16 1-term)
    gemm_qkv_blk_kernel<<<QK_GRID, 256, QK_SMEM>>>(bqkv);

    // 2) Attention
    attn_mma_kernel<<<dim3(S_LEN / 128, BATCH * NH), 256, ATTN_SMEM>>>();

    // 3) Output projection (persistent)
    gemm_out_f16_kernel<<<OUT_GRID, 256, GSMEM>>>(bo, out);
}